// round 1
// baseline (speedup 1.0000x reference)
#include <cuda_runtime.h>
#include <math.h>

#define NN   8192
#define DIM  128
#define NMOL 256
#define OD   56
#define ODP  64

typedef unsigned long long u64;

// ---------------- f32x2 helpers (Blackwell packed FMA: 2x FFMA throughput) ---
__device__ __forceinline__ u64 pk2(float lo, float hi) {
    u64 r; asm("mov.b64 %0, {%1,%2};" : "=l"(r) : "f"(lo), "f"(hi)); return r;
}
__device__ __forceinline__ void upk2(u64 v, float &lo, float &hi) {
    asm("mov.b64 {%0,%1}, %2;" : "=f"(lo), "=f"(hi) : "l"(v));
}
__device__ __forceinline__ void fma2(u64 &d, u64 a, u64 b) {
    asm("fma.rn.f32x2 %0, %1, %2, %0;" : "+l"(d) : "l"(a), "l"(b));
}
__device__ __forceinline__ void mul2(u64 &d, u64 a) {
    asm("mul.rn.f32x2 %0, %0, %1;" : "+l"(d) : "l"(a));
}

// ---------------- FMA-only exp (avoids MUFU.EX2 throughput wall) ------------
// e^x, accurate ~2e-6 rel. Intended for x <= ~+80; clamps below at -87.
__device__ __forceinline__ float fexp(float x) {
    x = fmaxf(x, -87.0f);
    float y = x * 1.44269504f;
    float r = rintf(y);
    float f = y - r;
    float p = 1.33335581e-3f;
    p = fmaf(p, f, 9.61812911e-3f);
    p = fmaf(p, f, 5.55041087e-2f);
    p = fmaf(p, f, 2.40226507e-1f);
    p = fmaf(p, f, 6.93147181e-1f);
    p = fmaf(p, f, 1.0f);
    int e = (int)r;
    return p * __int_as_float((e + 127) << 23);
}

// ---------------- scratch (no allocations allowed) ---------------------------
__device__ float g_x [NN * DIM];
__device__ float g_h [NN * DIM];
__device__ float g_t [NN * DIM];
__device__ float g_z [NN * DIM];
__device__ float g_s1[NN];
__device__ float g_s2[NN];
__device__ float g_ho [NN * ODP];
__device__ float g_a56[NN * ODP];
__device__ float g_wpad[DIM * ODP];

// ---------------- embedding gather -------------------------------------------
__global__ void k_gather(const int* __restrict__ fp, const float* __restrict__ emb) {
    int idx = blockIdx.x * 256 + threadIdx.x;   // NN*DIM total
    int i = idx >> 7, c = idx & 127;
    g_x[idx] = emb[fp[i] * DIM + c];
}

// ---------------- pad W_oa [128][56] -> [128][64] -----------------------------
__global__ void k_padw(const float* __restrict__ W) {
    int idx = blockIdx.x * 256 + threadIdx.x;   // 128*64
    int k = idx >> 6, c = idx & 63;
    g_wpad[idx] = (c < OD) ? W[k * OD + c] : 0.0f;
}

// ---------------- generic GEMM: C = act(scale*(A@B) + bias + resid) ----------
// A [M x K] (lda), B [K x BN] row-major (ldb == BN), C [M x BN].
// f32x2-packed accumulators along column pairs.
template<int BN>
__global__ void __launch_bounds__(256) k_gemm(
        const float* __restrict__ A, int lda, int K,
        const float* __restrict__ B,
        const float* __restrict__ bias,
        const float* __restrict__ resid,
        float* __restrict__ C, float scale, int relu)
{
    constexpr int BM = 64, BK = 32, TM = 4, TN = BN / 16;
    __shared__ float As[BK][BM + 4];   // transposed A tile, padded
    __shared__ float Bs[BK][BN];
    const int t  = threadIdx.x;
    const int tx = t & 15, ty = t >> 4;
    const int row0 = blockIdx.x * BM;

    u64 acc[TM][TN / 2];
#pragma unroll
    for (int i = 0; i < TM; i++)
#pragma unroll
        for (int j = 0; j < TN / 2; j++) acc[i][j] = 0ULL;

    for (int k0 = 0; k0 < K; k0 += BK) {
#pragma unroll
        for (int l = 0; l < (BM * BK) / 256; l++) {
            int idx = t + l * 256;
            int m = idx >> 5, k = idx & 31;
            As[k][m] = A[(size_t)(row0 + m) * lda + k0 + k];
        }
#pragma unroll
        for (int l = 0; l < (BK * BN) / 256; l++) {
            int idx = t + l * 256;
            int k = idx / BN, c = idx % BN;
            Bs[k][c] = B[(size_t)(k0 + k) * BN + c];
        }
        __syncthreads();
#pragma unroll
        for (int kk = 0; kk < BK; kk++) {
            float4 a4 = *(const float4*)&As[kk][ty * TM];
            u64 ap[4] = { pk2(a4.x, a4.x), pk2(a4.y, a4.y),
                          pk2(a4.z, a4.z), pk2(a4.w, a4.w) };
            const u64* bp = (const u64*)&Bs[kk][tx * TN];
            u64 b[TN / 2];
#pragma unroll
            for (int j = 0; j < TN / 2; j++) b[j] = bp[j];
#pragma unroll
            for (int i = 0; i < TM; i++)
#pragma unroll
                for (int j = 0; j < TN / 2; j++) fma2(acc[i][j], ap[i], b[j]);
        }
        __syncthreads();
    }
#pragma unroll
    for (int i = 0; i < TM; i++) {
        int m = row0 + ty * TM + i;
#pragma unroll
        for (int j = 0; j < TN / 2; j++) {
            int c = tx * TN + 2 * j;
            float lo, hi; upk2(acc[i][j], lo, hi);
            float v0 = scale * lo, v1 = scale * hi;
            if (bias)  { v0 += bias[c]; v1 += bias[c + 1]; }
            if (resid) {
                float2 rr = *(const float2*)&resid[(size_t)m * BN + c];
                v0 += rr.x; v1 += rr.y;
            }
            if (relu) { v0 = fmaxf(v0, 0.f); v1 = fmaxf(v1, 0.f); }
            float2 o; o.x = v0; o.y = v1;
            *(float2*)&C[(size_t)m * BN + c] = o;
        }
    }
}

// ---------------- row L2-normalize (warp per row) -----------------------------
__global__ void k_l2norm(const float* __restrict__ in, float* __restrict__ out) {
    int w = threadIdx.x >> 5, lane = threadIdx.x & 31;
    int row = blockIdx.x * 8 + w;
    const float* r = in + (size_t)row * DIM;
    float v[4], ss = 0.f;
#pragma unroll
    for (int q = 0; q < 4; q++) { v[q] = r[lane + q * 32]; ss += v[q] * v[q]; }
#pragma unroll
    for (int o = 16; o > 0; o >>= 1) ss += __shfl_xor_sync(0xffffffffu, ss, o);
    float inv = 1.0f / fmaxf(sqrtf(ss), 1e-12f);
#pragma unroll
    for (int q = 0; q < 4; q++) out[(size_t)row * DIM + lane + q * 32] = v[q] * inv;
}

// ---------------- s1/s2 projections (warp per row) ----------------------------
__global__ void k_s12(const float* __restrict__ H, int ld, int Dr,
                      const float* __restrict__ a) {
    int w = threadIdx.x >> 5, lane = threadIdx.x & 31;
    int row = blockIdx.x * 8 + w;
    const float* r = H + (size_t)row * ld;
    float p1 = 0.f, p2 = 0.f;
    for (int c = lane; c < Dr; c += 32) {
        float v = r[c];
        p1 = fmaf(v, a[c], p1);
        p2 = fmaf(v, a[Dr + c], p2);
    }
#pragma unroll
    for (int o = 16; o > 0; o >>= 1) {
        p1 += __shfl_xor_sync(0xffffffffu, p1, o);
        p2 += __shfl_xor_sync(0xffffffffu, p2, o);
    }
    if (lane == 0) { g_s1[row] = p1; g_s2[row] = p2; }
}

// ---------------- flash-style masked GAT attention ----------------------------
// score(i,j) = adj(i,j)>0 ? leakyrelu(s1_i + s2_j, 0.25) : -1e30
// out_i = softmax_row(score) @ H ; Z[i] (+)= elu(out_i)
template<int D>
__global__ void __launch_bounds__(256) k_attn(
        const float* __restrict__ adj,
        const float* __restrict__ H,
        float* __restrict__ Z, int accum)
{
    constexpr int JT = 128;
    constexpr int NP = D / 2;       // column pairs
    constexpr int G  = 256 / NP;    // row groups
    constexpr int R  = 32 / G;      // rows per thread
    __shared__ float P[32][JT + 4];
    __shared__ float s1s[32], s2t[JT];
    __shared__ float mrow[32], drow[32], scl[32];

    const int t  = threadIdx.x;
    const int i0 = blockIdx.x * 32;
    const int g  = t / NP, cp = (t % NP) * 2;
    const int si = t >> 3, ssub = t & 7;

    if (t < 32) { s1s[t] = g_s1[i0 + t]; mrow[t] = -1e30f; drow[t] = 0.f; }
    u64 acc[R];
#pragma unroll
    for (int r = 0; r < R; r++) acc[r] = 0ULL;
    __syncthreads();

    for (int jt = 0; jt < NN; jt += JT) {
        if (t < JT) s2t[t] = g_s2[jt + t];
        __syncthreads();                       // also joins prev-iter P reads
        // phase 1: masked leaky-relu scores
#pragma unroll
        for (int l = 0; l < 16; l++) {
            int idx = t + l * 256;
            int i = idx >> 7, j = idx & 127;
            float a = adj[(size_t)(i0 + i) * NN + jt + j];
            float sc;
            if (a > 0.f) { float s = s1s[i] + s2t[j]; sc = (s > 0.f) ? s : 0.25f * s; }
            else sc = -1e30f;
            P[i][j] = sc;
        }
        __syncthreads();
        // phase 2: per-row tile max -> online max update
        {
            float lm = -3e38f;
#pragma unroll
            for (int q = 0; q < 4; q++) {
                float4 v = *(const float4*)&P[si][ssub * 16 + q * 4];
                lm = fmaxf(lm, fmaxf(fmaxf(v.x, v.y), fmaxf(v.z, v.w)));
            }
            lm = fmaxf(lm, __shfl_xor_sync(0xffffffffu, lm, 1));
            lm = fmaxf(lm, __shfl_xor_sync(0xffffffffu, lm, 2));
            lm = fmaxf(lm, __shfl_xor_sync(0xffffffffu, lm, 4));
            if (ssub == 0) {
                float mo = mrow[si];
                float mn = fmaxf(mo, lm);
                mrow[si] = mn;
                scl[si]  = fexp(mo - mn);
            }
        }
        __syncthreads();
        // phase 3: exponentiate + running denominator
        {
            float mn = mrow[si];
            float lsum = 0.f;
#pragma unroll
            for (int q = 0; q < 16; q++) {
                int j = ssub * 16 + q;
                float p = fexp(P[si][j] - mn);
                P[si][j] = p;
                lsum += p;
            }
            lsum += __shfl_xor_sync(0xffffffffu, lsum, 1);
            lsum += __shfl_xor_sync(0xffffffffu, lsum, 2);
            lsum += __shfl_xor_sync(0xffffffffu, lsum, 4);
            if (ssub == 0) drow[si] = drow[si] * scl[si] + lsum;
        }
        __syncthreads();
        // phase 4: rescale accumulators + P @ H (f32x2 packed)
#pragma unroll
        for (int r = 0; r < R; r++) {
            float s = scl[g * R + r];
            mul2(acc[r], pk2(s, s));
        }
        const float* Hb = H + (size_t)jt * D + cp;
#pragma unroll 2
        for (int j = 0; j < JT; j += 4) {
            u64 h0 = *(const u64*)(Hb + (size_t)(j + 0) * D);
            u64 h1 = *(const u64*)(Hb + (size_t)(j + 1) * D);
            u64 h2 = *(const u64*)(Hb + (size_t)(j + 2) * D);
            u64 h3 = *(const u64*)(Hb + (size_t)(j + 3) * D);
#pragma unroll
            for (int r = 0; r < R; r++) {
                float4 pv = *(const float4*)&P[g * R + r][j];
                fma2(acc[r], pk2(pv.x, pv.x), h0);
                fma2(acc[r], pk2(pv.y, pv.y), h1);
                fma2(acc[r], pk2(pv.z, pv.z), h2);
                fma2(acc[r], pk2(pv.w, pv.w), h3);
            }
        }
    }
    // epilogue: normalize, elu, write/accumulate
#pragma unroll
    for (int r = 0; r < R; r++) {
        int row = i0 + g * R + r;
        float inv = 1.0f / drow[g * R + r];
        float lo, hi; upk2(acc[r], lo, hi);
        lo *= inv; hi *= inv;
        lo = (lo > 0.f) ? lo : fexp(lo) - 1.0f;
        hi = (hi > 0.f) ? hi : fexp(hi) - 1.0f;
        float* zp = Z + (size_t)row * D + cp;
        if (accum) { zp[0] += lo; zp[1] += hi; }
        else       { zp[0] = lo;  zp[1] = hi; }
    }
}

// ---------------- row softmax over first 56 of 64 cols ------------------------
__global__ void k_smax56(float* __restrict__ X) {
    int w = threadIdx.x >> 5, lane = threadIdx.x & 31;
    int row = blockIdx.x * 8 + w;
    float* r = X + (size_t)row * ODP;
    float v0 = (lane < OD)      ? r[lane]      : -3e38f;
    float v1 = (lane + 32 < OD) ? r[lane + 32] : -3e38f;
    float m = fmaxf(v0, v1);
#pragma unroll
    for (int o = 16; o > 0; o >>= 1) m = fmaxf(m, __shfl_xor_sync(0xffffffffu, m, o));
    float e0 = (lane < OD)      ? fexp(v0 - m) : 0.f;
    float e1 = (lane + 32 < OD) ? fexp(v1 - m) : 0.f;
    float s = e0 + e1;
#pragma unroll
    for (int o = 16; o > 0; o >>= 1) s += __shfl_xor_sync(0xffffffffu, s, o);
    float inv = 1.0f / s;
    if (lane < OD)      r[lane]      = e0 * inv;
    if (lane + 32 < OD) r[lane + 32] = e1 * inv;
}

// ---------------- deterministic segment-sum readout + MLP head ----------------
__global__ void k_head(const int* __restrict__ seg,
                       const float* __restrict__ Wout, const float* __restrict__ bout,
                       const float* __restrict__ Wprop, const float* __restrict__ bprop,
                       float* __restrict__ out)
{
    __shared__ float v[OD];
    __shared__ float o[OD];
    __shared__ int bnd[2];
    const int m = blockIdx.x, t = threadIdx.x;
    if (t < 2) {  // lower_bound of (m+t) in sorted seg[]
        int target = m + t;
        int lo = 0, hi = NN;
        while (lo < hi) { int mid = (lo + hi) >> 1; if (seg[mid] < target) lo = mid + 1; else hi = mid; }
        bnd[t] = lo;
    }
    __syncthreads();
    int lo = bnd[0], hi = bnd[1];
    if (t < OD) {
        float s = 0.f;
        for (int i = lo; i < hi; i++) s += g_a56[(size_t)i * ODP + t];
        v[t] = s;
    }
    __syncthreads();
    for (int l = 0; l < 2; l++) {
        if (t < OD) {
            float s = bout[l * OD + t];
            const float* W = Wout + l * OD * OD;
            for (int k = 0; k < OD; k++) s = fmaf(v[k], W[k * OD + t], s);
            o[t] = fmaxf(s, 0.f);
        }
        __syncthreads();
        if (t < OD) v[t] = o[t];
        __syncthreads();
    }
    if (t < 2) {
        float s = bprop[t];
        for (int k = 0; k < OD; k++) s = fmaf(v[k], Wprop[k * 2 + t], s);
        float r;
        if (s >= 0.f) r = 1.0f / (1.0f + fexp(-s));
        else { float e = fexp(s); r = e / (1.0f + e); }
        out[m * 2 + t] = r;
    }
}

// ---------------- orchestration ----------------------------------------------
extern "C" void kernel_launch(void* const* d_in, const int* in_sizes, int n_in,
                              void* d_out, int out_size) {
    const int*   fp   = (const int*)  d_in[0];
    const float* adj  = (const float*)d_in[1];
    const int*   seg  = (const int*)  d_in[2];
    const float* emb  = (const float*)d_in[3];
    const float* Wfp  = (const float*)d_in[4];
    const float* bfp  = (const float*)d_in[5];
    const float* Wh   = (const float*)d_in[6];
    const float* ah   = (const float*)d_in[7];
    const float* Woa  = (const float*)d_in[8];
    const float* aoa  = (const float*)d_in[9];
    const float* Wout = (const float*)d_in[10];
    const float* bout = (const float*)d_in[11];
    const float* Wpr  = (const float*)d_in[12];
    const float* bpr  = (const float*)d_in[13];
    float* out = (float*)d_out;

    float *x, *h, *tb, *z, *ho, *a56, *wpad;
    cudaGetSymbolAddress((void**)&x,    g_x);
    cudaGetSymbolAddress((void**)&h,    g_h);
    cudaGetSymbolAddress((void**)&tb,   g_t);
    cudaGetSymbolAddress((void**)&z,    g_z);
    cudaGetSymbolAddress((void**)&ho,   g_ho);
    cudaGetSymbolAddress((void**)&a56,  g_a56);
    cudaGetSymbolAddress((void**)&wpad, g_wpad);

    k_gather<<<NN * DIM / 256, 256>>>(fp, emb);

    // 3 message-passing layers: hs = relu(x@W+b); hs = hs + adj@hs; x = l2norm
    for (int l = 0; l < 3; l++) {
        k_gemm<128><<<NN / 64, 256>>>(x, DIM, DIM, Wfp + l * DIM * DIM,
                                      bfp + l * DIM, nullptr, h, 1.f, 1);
        k_gemm<128><<<NN / 64, 256>>>(adj, NN, NN, h, nullptr, h, tb, 1.f, 0);
        k_l2norm<<<NN / 8, 256>>>(tb, x);
    }

    // 2 GAT heads: z (+)= elu(att @ (x@Wh))
    for (int hd = 0; hd < 2; hd++) {
        k_gemm<128><<<NN / 64, 256>>>(x, DIM, DIM, Wh + hd * DIM * DIM,
                                      nullptr, nullptr, h, 1.f, 0);
        k_s12<<<NN / 8, 256>>>(h, DIM, DIM, ah + hd * 2 * DIM);
        k_attn<128><<<NN / 32, 256>>>(adj, h, z, hd);
    }

    // out-attention at D=56 (padded to 64), input x = z/2 folded into scale
    k_padw<<<DIM * ODP / 256, 256>>>(Woa);
    k_gemm<64><<<NN / 64, 256>>>(z, DIM, DIM, wpad, nullptr, nullptr, ho, 0.5f, 0);
    k_s12<<<NN / 8, 256>>>(ho, ODP, OD, aoa);
    k_attn<64><<<NN / 32, 256>>>(adj, ho, a56, 0);

    k_smax56<<<NN / 8, 256>>>(a56);
    k_head<<<NMOL, 64>>>(seg, Wout, bout, Wpr, bpr, out);
}

// round 3
// speedup vs baseline: 2.2026x; 2.2026x over previous
#include <cuda_runtime.h>
#include <cuda_bf16.h>
#include <math.h>

#define NN   8192
#define DIM  128
#define NMOL 256
#define OD   56
#define ODP  64

typedef unsigned long long u64;
typedef unsigned int u32;

// ---------------- f32x2 helpers (for remaining small GEMMs) ------------------
__device__ __forceinline__ u64 pk2(float lo, float hi) {
    u64 r; asm("mov.b64 %0, {%1,%2};" : "=l"(r) : "f"(lo), "f"(hi)); return r;
}
__device__ __forceinline__ void upk2(u64 v, float &lo, float &hi) {
    asm("mov.b64 {%0,%1}, %2;" : "=f"(lo), "=f"(hi) : "l"(v));
}
__device__ __forceinline__ void fma2(u64 &d, u64 a, u64 b) {
    asm("fma.rn.f32x2 %0, %1, %2, %0;" : "+l"(d) : "l"(a), "l"(b));
}

// ---------------- FMA-only exp ------------------------------------------------
__device__ __forceinline__ float fexp(float x) {
    x = fmaxf(x, -87.0f);
    float y = x * 1.44269504f;
    float r = rintf(y);
    float f = y - r;
    float p = 1.33335581e-3f;
    p = fmaf(p, f, 9.61812911e-3f);
    p = fmaf(p, f, 5.55041087e-2f);
    p = fmaf(p, f, 2.40226507e-1f);
    p = fmaf(p, f, 6.93147181e-1f);
    p = fmaf(p, f, 1.0f);
    int e = (int)r;
    return p * __int_as_float((e + 127) << 23);
}

// ---------------- MMA / ldmatrix helpers --------------------------------------
__device__ __forceinline__ u32 smem_u32(const void* p) {
    return (u32)__cvta_generic_to_shared(p);
}
__device__ __forceinline__ void ldm_x4(u32 a, u32* r) {
    asm volatile("ldmatrix.sync.aligned.m8n8.x4.shared.b16 {%0,%1,%2,%3}, [%4];"
        : "=r"(r[0]), "=r"(r[1]), "=r"(r[2]), "=r"(r[3]) : "r"(a));
}
__device__ __forceinline__ void ldm_x4t(u32 a, u32* r) {
    asm volatile("ldmatrix.sync.aligned.m8n8.x4.trans.shared.b16 {%0,%1,%2,%3}, [%4];"
        : "=r"(r[0]), "=r"(r[1]), "=r"(r[2]), "=r"(r[3]) : "r"(a));
}
__device__ __forceinline__ void mma_bf16(float* c, const u32* a, const u32* b) {
    asm volatile(
        "mma.sync.aligned.m16n8k16.row.col.f32.bf16.bf16.f32 "
        "{%0,%1,%2,%3}, {%4,%5,%6,%7}, {%8,%9}, {%0,%1,%2,%3};"
        : "+f"(c[0]), "+f"(c[1]), "+f"(c[2]), "+f"(c[3])
        : "r"(a[0]), "r"(a[1]), "r"(a[2]), "r"(a[3]), "r"(b[0]), "r"(b[1]));
}

// ---------------- scratch -----------------------------------------------------
__device__ __nv_bfloat16 g_adjb[(size_t)NN * NN];   // 128 MB, exact 0/1
__device__ __nv_bfloat16 g_hh[NN * DIM];
__device__ __nv_bfloat16 g_hl[NN * DIM];
__device__ float g_x [NN * DIM];
__device__ float g_h [NN * DIM];
__device__ float g_t [NN * DIM];
__device__ float g_z [NN * DIM];
__device__ float g_s1[NN];
__device__ float g_s2[NN];
__device__ float g_tmax[NN];
__device__ float g_pa[NN], g_pb[NN], g_pth[NN], g_peg[NN], g_peq[NN];
__device__ float g_ho [NN * ODP];
__device__ float g_a56[NN * ODP];
__device__ float g_wpad[DIM * ODP];
__device__ float g_cm[DIM];
__device__ float g_cmp[64 * DIM];

// ---------------- small utility kernels ---------------------------------------
__global__ void k_gather(const int* __restrict__ fp, const float* __restrict__ emb) {
    int idx = blockIdx.x * 256 + threadIdx.x;
    int i = idx >> 7, c = idx & 127;
    g_x[idx] = emb[fp[i] * DIM + c];
}

__global__ void k_padw(const float* __restrict__ W) {
    int idx = blockIdx.x * 256 + threadIdx.x;
    int k = idx >> 6, c = idx & 63;
    g_wpad[idx] = (c < OD) ? W[k * OD + c] : 0.0f;
}

// adj fp32 -> bf16 (values 0/1: exact)
__global__ void k_adjconv(const float* __restrict__ adj) {
    size_t base = ((size_t)blockIdx.x * 256 + threadIdx.x) * 8;
    float4 a = *(const float4*)(adj + base);
    float4 b = *(const float4*)(adj + base + 4);
    __nv_bfloat16 o[8];
    o[0]=__float2bfloat16(a.x); o[1]=__float2bfloat16(a.y);
    o[2]=__float2bfloat16(a.z); o[3]=__float2bfloat16(a.w);
    o[4]=__float2bfloat16(b.x); o[5]=__float2bfloat16(b.y);
    o[6]=__float2bfloat16(b.z); o[7]=__float2bfloat16(b.w);
    *(uint4*)(g_adjb + base) = *(uint4*)o;
}

// split fp32 -> bf16 hi/lo
__global__ void k_split(const float* __restrict__ in, int n) {
    int i = blockIdx.x * 256 + threadIdx.x;
    if (i >= n) return;
    float v = in[i];
    __nv_bfloat16 h = __float2bfloat16(v);
    g_hh[i] = h;
    g_hl[i] = __float2bfloat16(v - __bfloat162float(h));
}

// ---------------- row L2-normalize --------------------------------------------
__global__ void k_l2norm(const float* __restrict__ in, float* __restrict__ out) {
    int w = threadIdx.x >> 5, lane = threadIdx.x & 31;
    int row = blockIdx.x * 8 + w;
    const float* r = in + (size_t)row * DIM;
    float v[4], ss = 0.f;
#pragma unroll
    for (int q = 0; q < 4; q++) { v[q] = r[lane + q * 32]; ss += v[q] * v[q]; }
#pragma unroll
    for (int o = 16; o > 0; o >>= 1) ss += __shfl_xor_sync(0xffffffffu, ss, o);
    float inv = 1.0f / fmaxf(sqrtf(ss), 1e-12f);
#pragma unroll
    for (int q = 0; q < 4; q++) out[(size_t)row * DIM + lane + q * 32] = v[q] * inv;
}

// ---------------- s1/s2 projections -------------------------------------------
__global__ void k_s12(const float* __restrict__ H, int ld, int Dr,
                      const float* __restrict__ a) {
    int w = threadIdx.x >> 5, lane = threadIdx.x & 31;
    int row = blockIdx.x * 8 + w;
    const float* r = H + (size_t)row * ld;
    float p1 = 0.f, p2 = 0.f;
    for (int c = lane; c < Dr; c += 32) {
        float v = r[c];
        p1 = fmaf(v, a[c], p1);
        p2 = fmaf(v, a[Dr + c], p2);
    }
#pragma unroll
    for (int o = 16; o > 0; o >>= 1) {
        p1 += __shfl_xor_sync(0xffffffffu, p1, o);
        p2 += __shfl_xor_sync(0xffffffffu, p2, o);
    }
    if (lane == 0) { g_s1[row] = p1; g_s2[row] = p2; }
}

// ---------------- masked neighbor max of s2 over adj row ----------------------
__global__ void k_nbrmax() {
    int w = threadIdx.x >> 5, lane = threadIdx.x & 31;
    int row = blockIdx.x * 8 + w;
    const __nv_bfloat16* rp = g_adjb + (size_t)row * NN;
    float m = -1e30f;
    for (int base = lane * 8; base < NN; base += 256) {
        uint4 a = *(const uint4*)(rp + base);
        const unsigned short* ap = (const unsigned short*)&a;
        float4 sa = *(const float4*)(g_s2 + base);
        float4 sb = *(const float4*)(g_s2 + base + 4);
        if (ap[0]) m = fmaxf(m, sa.x);
        if (ap[1]) m = fmaxf(m, sa.y);
        if (ap[2]) m = fmaxf(m, sa.z);
        if (ap[3]) m = fmaxf(m, sa.w);
        if (ap[4]) m = fmaxf(m, sb.x);
        if (ap[5]) m = fmaxf(m, sb.y);
        if (ap[6]) m = fmaxf(m, sb.z);
        if (ap[7]) m = fmaxf(m, sb.w);
    }
#pragma unroll
    for (int o = 16; o > 0; o >>= 1) m = fmaxf(m, __shfl_xor_sync(0xffffffffu, m, o));
    if (lane == 0) g_tmax[row] = m;
}

// ---------------- per-node attention precompute -------------------------------
// m_i = lrelu(s1_i + t_i); a_i = exp(s1_i - m_i); b_i = exp(.25 s1_i - m_i)
// eg_j = exp(s2_j); eq_j = exp(.25 s2_j); th_i = -s1_i
__global__ void k_prep() {
    int i = blockIdx.x * 256 + threadIdx.x;
    float s1 = g_s1[i], s2 = g_s2[i], t = g_tmax[i];
    float a, b;
    if (t < -1e29f) { a = 0.f; b = 0.f; }
    else {
        float u = s1 + t;
        float m = (u > 0.f) ? u : 0.25f * u;
        a = fexp(s1 - m);
        b = fexp(0.25f * s1 - m);
    }
    g_pa[i] = a; g_pb[i] = b; g_pth[i] = -s1;
    g_peg[i] = fexp(s2); g_peq[i] = fexp(0.25f * s2);
}

// ---------------- column mean (deterministic 2-stage) -------------------------
template<int BN>
__global__ void k_colmean1(const float* __restrict__ H) {
    int t = threadIdx.x;       // < BN
    int r0 = blockIdx.x * 128;
    float s = 0.f;
    for (int r = 0; r < 128; r++) s += H[(size_t)(r0 + r) * BN + t];
    g_cmp[blockIdx.x * DIM + t] = s;
}
__global__ void k_colmean2(int BN) {
    int t = threadIdx.x;
    float s = 0.f;
    if (t < BN) for (int b = 0; b < 64; b++) s += g_cmp[b * DIM + t];
    g_cm[t] = s * (1.0f / NN);
}

// ---------------- dynamic shared layout for the MMA kernel --------------------
template<int BN>
struct SmemT {
    static constexpr int BM = 64, BK = 64, HS = BN + 8;
    __nv_bfloat16 Phi[BM][72];
    __nv_bfloat16 Plo[BM][72];
    __nv_bfloat16 Hh[BK][HS];
    __nv_bfloat16 Hl[BK][HS];
    float A[BM], B[BM], Th[BM], D[BM];
};

// ---------------- unified tensor-core kernel ----------------------------------
// MODE 0: Out = resid + adj @ (Hhi+Hlo)                    [adj GEMM + residual]
// MODE 1: P_ij = adj_ij * (s2_j>=th_i ? a_i*eg_j : b_i*eq_j);
//         Out_i = elu(P@H / d_i)  (d_i==0 -> colmean), optional accumulate.
template<int BN, int MODE>
__global__ void __launch_bounds__(256) k_mma(
    const float* __restrict__ resid,
    float* __restrict__ Out, int accum)
{
    constexpr int BM = 64, BK = 64;
    constexpr int NWN = BN / 32, NWM = 8 / NWN;
    constexpr int WM = BM / NWM, FM = WM / 16, FN = 4;

    extern __shared__ char smem_raw[];
    SmemT<BN>& S = *reinterpret_cast<SmemT<BN>*>(smem_raw);

    const int t = threadIdx.x, lane = t & 31, warp = t >> 5;
    const int i0 = blockIdx.x * BM;
    const int wm = warp / NWN, wn = warp % NWN;
    const int pr = warp * 8 + (lane >> 2);   // P-gen row (0..63)
    const int pc = (lane & 3) * 16;          // P-gen col start

    if (MODE && t < BM) {
        S.A[t] = g_pa[i0 + t]; S.B[t] = g_pb[i0 + t]; S.Th[t] = g_pth[i0 + t];
    }
    __syncthreads();
    float ai = 0.f, bi = 0.f, thi = 0.f;
    if (MODE) { ai = S.A[pr]; bi = S.B[pr]; thi = S.Th[pr]; }

    float acc[FM][FN][4];
#pragma unroll
    for (int a = 0; a < FM; a++)
#pragma unroll
        for (int b = 0; b < FN; b++)
#pragma unroll
            for (int c = 0; c < 4; c++) acc[a][b][c] = 0.f;
    float dpart = 0.f;

    for (int kt = 0; kt < NN / BK; kt++) {
        const int k0 = kt * BK;
        __syncthreads();   // previous MMA phase done

        // ---- load H tiles (global bf16 -> smem) ----
        constexpr int HV = BN / 8;
#pragma unroll
        for (int l = 0; l < (BK * HV) / 256; l++) {
            int u = t + l * 256;
            int r = u / HV, c = u % HV;
            *(uint4*)(&S.Hh[r][c * 8]) = *(const uint4*)(g_hh + (size_t)(k0 + r) * BN + c * 8);
            *(uint4*)(&S.Hl[r][c * 8]) = *(const uint4*)(g_hl + (size_t)(k0 + r) * BN + c * 8);
        }

        // ---- A tile ----
        if (MODE) {
            const __nv_bfloat16* arow = g_adjb + (size_t)(i0 + pr) * NN + k0 + pc;
            uint4 av0 = *(const uint4*)arow;
            uint4 av1 = *(const uint4*)(arow + 8);
            unsigned short ab[16];
            *(uint4*)ab = av0; *(uint4*)(ab + 8) = av1;
            __align__(16) __nv_bfloat16 ph[16], pl[16];
            const float* eg = g_peg + k0 + pc;
            const float* eq = g_peq + k0 + pc;
            const float* s2 = g_s2  + k0 + pc;
#pragma unroll
            for (int c = 0; c < 16; c++) {
                float p = 0.f;
                if (ab[c]) p = (s2[c] >= thi) ? ai * eg[c] : bi * eq[c];
                dpart += p;
                __nv_bfloat16 h = __float2bfloat16(p);
                ph[c] = h;
                pl[c] = __float2bfloat16(p - __bfloat162float(h));
            }
            *(uint4*)&S.Phi[pr][pc]     = *(uint4*)ph;
            *(uint4*)&S.Phi[pr][pc + 8] = *(uint4*)(ph + 8);
            *(uint4*)&S.Plo[pr][pc]     = *(uint4*)pl;
            *(uint4*)&S.Plo[pr][pc + 8] = *(uint4*)(pl + 8);
        } else {
#pragma unroll
            for (int l = 0; l < 2; l++) {
                int u = t + l * 256;
                int r = u >> 3, c8 = u & 7;
                *(uint4*)(&S.Phi[r][c8 * 8]) =
                    *(const uint4*)(g_adjb + (size_t)(i0 + r) * NN + k0 + c8 * 8);
            }
        }
        __syncthreads();

        // ---- MMA phase ----
#pragma unroll
        for (int kk = 0; kk < 4; kk++) {
            u32 ah[FM][4], al[FM][4];
#pragma unroll
            for (int fm = 0; fm < FM; fm++) {
                int rr = wm * WM + fm * 16 + (lane & 15);
                int cc = kk * 16 + (lane >> 4) * 8;
                ldm_x4(smem_u32(&S.Phi[rr][cc]), ah[fm]);
                if (MODE) ldm_x4(smem_u32(&S.Plo[rr][cc]), al[fm]);
            }
            u32 bh[4][2], bl[4][2];
#pragma unroll
            for (int fp2 = 0; fp2 < 2; fp2++) {
                int rr = kk * 16 + (lane & 15);
                int cc = wn * 32 + fp2 * 16 + (lane >> 4) * 8;
                u32 r4[4];
                ldm_x4t(smem_u32(&S.Hh[rr][cc]), r4);
                bh[2*fp2][0] = r4[0]; bh[2*fp2][1] = r4[1];
                bh[2*fp2+1][0] = r4[2]; bh[2*fp2+1][1] = r4[3];
                ldm_x4t(smem_u32(&S.Hl[rr][cc]), r4);
                bl[2*fp2][0] = r4[0]; bl[2*fp2][1] = r4[1];
                bl[2*fp2+1][0] = r4[2]; bl[2*fp2+1][1] = r4[3];
            }
#pragma unroll
            for (int fm = 0; fm < FM; fm++)
#pragma unroll
                for (int fn = 0; fn < FN; fn++) {
                    mma_bf16(acc[fm][fn], ah[fm], bh[fn]);
                    mma_bf16(acc[fm][fn], ah[fm], bl[fn]);
                    if (MODE) mma_bf16(acc[fm][fn], al[fm], bh[fn]);
                }
        }
    }

    // ---- d reduce (MODE 1) ----
    if (MODE) {
        dpart += __shfl_xor_sync(0xffffffffu, dpart, 1);
        dpart += __shfl_xor_sync(0xffffffffu, dpart, 2);
        if ((lane & 3) == 0) S.D[pr] = dpart;
    }
    __syncthreads();

    // ---- epilogue ----
#pragma unroll
    for (int fm = 0; fm < FM; fm++) {
#pragma unroll
        for (int h = 0; h < 2; h++) {
            int rl = wm * WM + fm * 16 + (lane >> 2) + h * 8;
            int row = i0 + rl;
#pragma unroll
            for (int fn = 0; fn < FN; fn++) {
                int col = wn * 32 + fn * 8 + (lane & 3) * 2;
                float v0 = acc[fm][fn][2 * h], v1 = acc[fm][fn][2 * h + 1];
                float* op = Out + (size_t)row * BN + col;
                if (MODE == 0) {
                    float2 rr = *(const float2*)(resid + (size_t)row * BN + col);
                    float2 o; o.x = v0 + rr.x; o.y = v1 + rr.y;
                    *(float2*)op = o;
                } else {
                    float dd = S.D[rl];
                    if (dd > 0.f) { float inv = 1.0f / dd; v0 *= inv; v1 *= inv; }
                    else          { v0 = g_cm[col]; v1 = g_cm[col + 1]; }
                    v0 = (v0 > 0.f) ? v0 : fexp(v0) - 1.0f;
                    v1 = (v1 > 0.f) ? v1 : fexp(v1) - 1.0f;
                    if (accum) {
                        float2 zz = *(const float2*)op;
                        v0 += zz.x; v1 += zz.y;
                    }
                    float2 o; o.x = v0; o.y = v1;
                    *(float2*)op = o;
                }
            }
        }
    }
}

// ---------------- small dense GEMM (f32x2 path) -------------------------------
template<int BN>
__global__ void __launch_bounds__(256) k_gemm(
        const float* __restrict__ A, int lda, int K,
        const float* __restrict__ B,
        const float* __restrict__ bias,
        float* __restrict__ C, float scale, int relu)
{
    constexpr int BM = 64, BK = 32, TM = 4, TN = BN / 16;
    __shared__ float As[BK][BM + 4];
    __shared__ float Bs[BK][BN];
    const int t  = threadIdx.x;
    const int tx = t & 15, ty = t >> 4;
    const int row0 = blockIdx.x * BM;

    u64 acc[TM][TN / 2];
#pragma unroll
    for (int i = 0; i < TM; i++)
#pragma unroll
        for (int j = 0; j < TN / 2; j++) acc[i][j] = 0ULL;

    for (int k0 = 0; k0 < K; k0 += BK) {
#pragma unroll
        for (int l = 0; l < (BM * BK) / 256; l++) {
            int idx = t + l * 256;
            int m = idx >> 5, k = idx & 31;
            As[k][m] = A[(size_t)(row0 + m) * lda + k0 + k];
        }
#pragma unroll
        for (int l = 0; l < (BK * BN) / 256; l++) {
            int idx = t + l * 256;
            int k = idx / BN, c = idx % BN;
            Bs[k][c] = B[(size_t)(k0 + k) * BN + c];
        }
        __syncthreads();
#pragma unroll
        for (int kk = 0; kk < BK; kk++) {
            float4 a4 = *(const float4*)&As[kk][ty * TM];
            u64 ap[4] = { pk2(a4.x, a4.x), pk2(a4.y, a4.y),
                          pk2(a4.z, a4.z), pk2(a4.w, a4.w) };
            const u64* bp = (const u64*)&Bs[kk][tx * TN];
            u64 b[TN / 2];
#pragma unroll
            for (int j = 0; j < TN / 2; j++) b[j] = bp[j];
#pragma unroll
            for (int i = 0; i < TM; i++)
#pragma unroll
                for (int j = 0; j < TN / 2; j++) fma2(acc[i][j], ap[i], b[j]);
        }
        __syncthreads();
    }
#pragma unroll
    for (int i = 0; i < TM; i++) {
        int m = row0 + ty * TM + i;
#pragma unroll
        for (int j = 0; j < TN / 2; j++) {
            int c = tx * TN + 2 * j;
            float lo, hi; upk2(acc[i][j], lo, hi);
            float v0 = scale * lo, v1 = scale * hi;
            if (bias)  { v0 += bias[c]; v1 += bias[c + 1]; }
            if (relu) { v0 = fmaxf(v0, 0.f); v1 = fmaxf(v1, 0.f); }
            float2 o; o.x = v0; o.y = v1;
            *(float2*)&C[(size_t)m * BN + c] = o;
        }
    }
}

// ---------------- row softmax over first 56 of 64 cols ------------------------
__global__ void k_smax56(float* __restrict__ X) {
    int w = threadIdx.x >> 5, lane = threadIdx.x & 31;
    int row = blockIdx.x * 8 + w;
    float* r = X + (size_t)row * ODP;
    float v0 = (lane < OD)      ? r[lane]      : -3e38f;
    float v1 = (lane + 32 < OD) ? r[lane + 32] : -3e38f;
    float m = fmaxf(v0, v1);
#pragma unroll
    for (int o = 16; o > 0; o >>= 1) m = fmaxf(m, __shfl_xor_sync(0xffffffffu, m, o));
    float e0 = (lane < OD)      ? fexp(v0 - m) : 0.f;
    float e1 = (lane + 32 < OD) ? fexp(v1 - m) : 0.f;
    float s = e0 + e1;
#pragma unroll
    for (int o = 16; o > 0; o >>= 1) s += __shfl_xor_sync(0xffffffffu, s, o);
    float inv = 1.0f / s;
    if (lane < OD)      r[lane]      = e0 * inv;
    if (lane + 32 < OD) r[lane + 32] = e1 * inv;
}

// ---------------- segment-sum readout + MLP head ------------------------------
__global__ void k_head(const int* __restrict__ seg,
                       const float* __restrict__ Wout, const float* __restrict__ bout,
                       const float* __restrict__ Wprop, const float* __restrict__ bprop,
                       float* __restrict__ out)
{
    __shared__ float v[OD];
    __shared__ float o[OD];
    __shared__ int bnd[2];
    const int m = blockIdx.x, t = threadIdx.x;
    if (t < 2) {
        int target = m + t;
        int lo = 0, hi = NN;
        while (lo < hi) { int mid = (lo + hi) >> 1; if (seg[mid] < target) lo = mid + 1; else hi = mid; }
        bnd[t] = lo;
    }
    __syncthreads();
    int lo = bnd[0], hi = bnd[1];
    if (t < OD) {
        float s = 0.f;
        for (int i = lo; i < hi; i++) s += g_a56[(size_t)i * ODP + t];
        v[t] = s;
    }
    __syncthreads();
    for (int l = 0; l < 2; l++) {
        if (t < OD) {
            float s = bout[l * OD + t];
            const float* W = Wout + l * OD * OD;
            for (int k = 0; k < OD; k++) s = fmaf(v[k], W[k * OD + t], s);
            o[t] = fmaxf(s, 0.f);
        }
        __syncthreads();
        if (t < OD) v[t] = o[t];
        __syncthreads();
    }
    if (t < 2) {
        float s = bprop[t];
        for (int k = 0; k < OD; k++) s = fmaf(v[k], Wprop[k * 2 + t], s);
        float r;
        if (s >= 0.f) r = 1.0f / (1.0f + fexp(-s));
        else { float e = fexp(s); r = e / (1.0f + e); }
        out[m * 2 + t] = r;
    }
}

// ---------------- orchestration ----------------------------------------------
extern "C" void kernel_launch(void* const* d_in, const int* in_sizes, int n_in,
                              void* d_out, int out_size) {
    const int*   fp   = (const int*)  d_in[0];
    const float* adj  = (const float*)d_in[1];
    const int*   seg  = (const int*)  d_in[2];
    const float* emb  = (const float*)d_in[3];
    const float* Wfp  = (const float*)d_in[4];
    const float* bfp  = (const float*)d_in[5];
    const float* Wh   = (const float*)d_in[6];
    const float* ah   = (const float*)d_in[7];
    const float* Woa  = (const float*)d_in[8];
    const float* aoa  = (const float*)d_in[9];
    const float* Wout = (const float*)d_in[10];
    const float* bout = (const float*)d_in[11];
    const float* Wpr  = (const float*)d_in[12];
    const float* bpr  = (const float*)d_in[13];
    float* out = (float*)d_out;

    float *x, *h, *tb, *z, *ho, *a56, *wpad;
    cudaGetSymbolAddress((void**)&x,    g_x);
    cudaGetSymbolAddress((void**)&h,    g_h);
    cudaGetSymbolAddress((void**)&tb,   g_t);
    cudaGetSymbolAddress((void**)&z,    g_z);
    cudaGetSymbolAddress((void**)&ho,   g_ho);
    cudaGetSymbolAddress((void**)&a56,  g_a56);
    cudaGetSymbolAddress((void**)&wpad, g_wpad);

    const int SZ128 = (int)sizeof(SmemT<128>);
    const int SZ64  = (int)sizeof(SmemT<64>);
    cudaFuncSetAttribute(k_mma<128,0>, cudaFuncAttributeMaxDynamicSharedMemorySize, SZ128);
    cudaFuncSetAttribute(k_mma<128,1>, cudaFuncAttributeMaxDynamicSharedMemorySize, SZ128);
    cudaFuncSetAttribute(k_mma<64,1>,  cudaFuncAttributeMaxDynamicSharedMemorySize, SZ64);

    k_gather<<<NN * DIM / 256, 256>>>(fp, emb);
    k_adjconv<<<(size_t)NN * NN / 2048, 256>>>(adj);
    k_padw<<<DIM * ODP / 256, 256>>>(Woa);

    // 3 message-passing layers
    for (int l = 0; l < 3; l++) {
        k_gemm<128><<<NN / 64, 256>>>(x, DIM, DIM, Wfp + l * DIM * DIM,
                                      bfp + l * DIM, h, 1.f, 1);
        k_split<<<NN * DIM / 256, 256>>>(h, NN * DIM);
        k_mma<128, 0><<<NN / 64, 256, SZ128>>>(h, tb, 0);
        k_l2norm<<<NN / 8, 256>>>(tb, x);
    }

    // 2 GAT heads
    for (int hd = 0; hd < 2; hd++) {
        k_gemm<128><<<NN / 64, 256>>>(x, DIM, DIM, Wh + hd * DIM * DIM,
                                      nullptr, h, 1.f, 0);
        k_s12<<<NN / 8, 256>>>(h, DIM, DIM, ah + hd * 2 * DIM);
        k_nbrmax<<<NN / 8, 256>>>();
        k_prep<<<NN / 256, 256>>>();
        k_split<<<NN * DIM / 256, 256>>>(h, NN * DIM);
        k_colmean1<128><<<64, 128>>>(h);
        k_colmean2<<<1, 128>>>(128);
        k_mma<128, 1><<<NN / 64, 256, SZ128>>>(nullptr, z, hd);
    }

    // out-attention at D=56 (padded to 64); x = z/2 folded into scale
    k_gemm<64><<<NN / 64, 256>>>(z, DIM, DIM, wpad, nullptr, ho, 0.5f, 0);
    k_s12<<<NN / 8, 256>>>(ho, ODP, OD, aoa);
    k_nbrmax<<<NN / 8, 256>>>();
    k_prep<<<NN / 256, 256>>>();
    k_split<<<NN * ODP / 256, 256>>>(ho, NN * ODP);
    k_colmean1<64><<<64, 64>>>(ho);
    k_colmean2<<<1, 128>>>(64);
    k_mma<64, 1><<<NN / 64, 256, SZ64>>>(nullptr, a56, 0);

    k_smax56<<<NN / 8, 256>>>(a56);
    k_head<<<NMOL, 64>>>(seg, Wout, bout, Wpr, bpr, out);
}

// round 4
// speedup vs baseline: 2.8607x; 1.2988x over previous
#include <cuda_runtime.h>
#include <cuda_bf16.h>
#include <math.h>

#define NN   8192
#define DIM  128
#define NMOL 256
#define OD   56
#define ODP  64

typedef unsigned long long u64;
typedef unsigned int u32;

// ---------------- f32x2 helpers ----------------------------------------------
__device__ __forceinline__ u64 pk2(float lo, float hi) {
    u64 r; asm("mov.b64 %0, {%1,%2};" : "=l"(r) : "f"(lo), "f"(hi)); return r;
}
__device__ __forceinline__ void upk2(u64 v, float &lo, float &hi) {
    asm("mov.b64 {%0,%1}, %2;" : "=f"(lo), "=f"(hi) : "l"(v));
}
__device__ __forceinline__ void fma2(u64 &d, u64 a, u64 b) {
    asm("fma.rn.f32x2 %0, %1, %2, %0;" : "+l"(d) : "l"(a), "l"(b));
}

// ---------------- FMA-only exp ------------------------------------------------
__device__ __forceinline__ float fexp(float x) {
    x = fmaxf(x, -87.0f);
    float y = x * 1.44269504f;
    float r = rintf(y);
    float f = y - r;
    float p = 1.33335581e-3f;
    p = fmaf(p, f, 9.61812911e-3f);
    p = fmaf(p, f, 5.55041087e-2f);
    p = fmaf(p, f, 2.40226507e-1f);
    p = fmaf(p, f, 6.93147181e-1f);
    p = fmaf(p, f, 1.0f);
    int e = (int)r;
    return p * __int_as_float((e + 127) << 23);
}

// monotone float<->u32 encoding for atomicMax over signed floats
__device__ __forceinline__ u32 encf(float s) {
    u32 b = __float_as_uint(s);
    return (b & 0x80000000u) ? ~b : (b | 0x80000000u);
}
__device__ __forceinline__ float decf(u32 u) {
    return __uint_as_float((u & 0x80000000u) ? (u & 0x7fffffffu) : ~u);
}

// ---------------- MMA / ldmatrix / cp.async helpers ---------------------------
__device__ __forceinline__ u32 smem_u32(const void* p) {
    return (u32)__cvta_generic_to_shared(p);
}
__device__ __forceinline__ void ldm_x4(u32 a, u32* r) {
    asm volatile("ldmatrix.sync.aligned.m8n8.x4.shared.b16 {%0,%1,%2,%3}, [%4];"
        : "=r"(r[0]), "=r"(r[1]), "=r"(r[2]), "=r"(r[3]) : "r"(a));
}
__device__ __forceinline__ void ldm_x4t(u32 a, u32* r) {
    asm volatile("ldmatrix.sync.aligned.m8n8.x4.trans.shared.b16 {%0,%1,%2,%3}, [%4];"
        : "=r"(r[0]), "=r"(r[1]), "=r"(r[2]), "=r"(r[3]) : "r"(a));
}
__device__ __forceinline__ void mma_bf16(float* c, const u32* a, const u32* b) {
    asm volatile(
        "mma.sync.aligned.m16n8k16.row.col.f32.bf16.bf16.f32 "
        "{%0,%1,%2,%3}, {%4,%5,%6,%7}, {%8,%9}, {%0,%1,%2,%3};"
        : "+f"(c[0]), "+f"(c[1]), "+f"(c[2]), "+f"(c[3])
        : "r"(a[0]), "r"(a[1]), "r"(a[2]), "r"(a[3]), "r"(b[0]), "r"(b[1]));
}
__device__ __forceinline__ void cpasync16(u32 dst, const void* src) {
    asm volatile("cp.async.cg.shared.global [%0], [%1], 16;" :: "r"(dst), "l"(src));
}
#define CP_COMMIT() asm volatile("cp.async.commit_group;" ::: "memory")
#define CP_WAIT1()  asm volatile("cp.async.wait_group 1;" ::: "memory")

// ---------------- scratch -----------------------------------------------------
__device__ __nv_bfloat16 g_adjb[(size_t)NN * NN];   // 128 MB, exact 0/1
__device__ __nv_bfloat16 g_hh[NN * DIM];
__device__ __nv_bfloat16 g_hl[NN * DIM];
__device__ float g_x [NN * DIM];
__device__ float g_h [NN * DIM];
__device__ float g_t [NN * DIM];
__device__ float g_z [NN * DIM];
__device__ float g_s1[NN];
__device__ float g_s2[NN];
__device__ u32   g_s2maxu;
__device__ float g_pa[NN], g_pb[NN], g_pth[NN], g_peg[NN], g_peq[NN];
__device__ float g_ho [NN * ODP];
__device__ float g_a56[NN * ODP];
__device__ float g_wpad[DIM * ODP];
__device__ float g_cm[DIM];
__device__ float g_cmp[64 * DIM];

// ---------------- small utility kernels ---------------------------------------
__global__ void k_gather(const int* __restrict__ fp, const float* __restrict__ emb) {
    int idx = blockIdx.x * 256 + threadIdx.x;
    int i = idx >> 7, c = idx & 127;
    g_x[idx] = emb[fp[i] * DIM + c];
}

__global__ void k_padw(const float* __restrict__ W) {
    int idx = blockIdx.x * 256 + threadIdx.x;
    int k = idx >> 6, c = idx & 63;
    g_wpad[idx] = (c < OD) ? W[k * OD + c] : 0.0f;
}

__global__ void k_adjconv(const float* __restrict__ adj) {
    size_t base = ((size_t)blockIdx.x * 256 + threadIdx.x) * 8;
    float4 a = *(const float4*)(adj + base);
    float4 b = *(const float4*)(adj + base + 4);
    __nv_bfloat16 o[8];
    o[0]=__float2bfloat16(a.x); o[1]=__float2bfloat16(a.y);
    o[2]=__float2bfloat16(a.z); o[3]=__float2bfloat16(a.w);
    o[4]=__float2bfloat16(b.x); o[5]=__float2bfloat16(b.y);
    o[6]=__float2bfloat16(b.z); o[7]=__float2bfloat16(b.w);
    *(uint4*)(g_adjb + base) = *(uint4*)o;
}

// ---------------- row L2-normalize --------------------------------------------
__global__ void k_l2norm(const float* __restrict__ in, float* __restrict__ out) {
    int w = threadIdx.x >> 5, lane = threadIdx.x & 31;
    int row = blockIdx.x * 8 + w;
    const float* r = in + (size_t)row * DIM;
    float v[4], ss = 0.f;
#pragma unroll
    for (int q = 0; q < 4; q++) { v[q] = r[lane + q * 32]; ss += v[q] * v[q]; }
#pragma unroll
    for (int o = 16; o > 0; o >>= 1) ss += __shfl_xor_sync(0xffffffffu, ss, o);
    float inv = 1.0f / fmaxf(sqrtf(ss), 1e-12f);
#pragma unroll
    for (int q = 0; q < 4; q++) out[(size_t)row * DIM + lane + q * 32] = v[q] * inv;
}

// ---------------- s1/s2 projections + global s2 max ---------------------------
__global__ void k_s12(const float* __restrict__ H, int ld, int Dr,
                      const float* __restrict__ a) {
    int w = threadIdx.x >> 5, lane = threadIdx.x & 31;
    int row = blockIdx.x * 8 + w;
    const float* r = H + (size_t)row * ld;
    float p1 = 0.f, p2 = 0.f;
    for (int c = lane; c < Dr; c += 32) {
        float v = r[c];
        p1 = fmaf(v, a[c], p1);
        p2 = fmaf(v, a[Dr + c], p2);
    }
#pragma unroll
    for (int o = 16; o > 0; o >>= 1) {
        p1 += __shfl_xor_sync(0xffffffffu, p1, o);
        p2 += __shfl_xor_sync(0xffffffffu, p2, o);
    }
    if (lane == 0) {
        g_s1[row] = p1; g_s2[row] = p2;
        atomicMax(&g_s2maxu, encf(p2));
    }
}

// ---------------- per-node attention precompute -------------------------------
// m_i = lrelu(s1_i + gmax) >= lrelu(s1_i + s2_j) for all j  (lrelu monotone)
__global__ void k_prep() {
    int i = blockIdx.x * 256 + threadIdx.x;
    float gmax = decf(g_s2maxu);
    float s1 = g_s1[i], s2 = g_s2[i];
    float u = s1 + gmax;
    float m = (u > 0.f) ? u : 0.25f * u;
    g_pa[i] = fexp(s1 - m);
    g_pb[i] = fexp(0.25f * s1 - m);
    g_pth[i] = -s1;
    g_peg[i] = fexp(s2);
    g_peq[i] = fexp(0.25f * s2);
}

// ---------------- column mean (deterministic 2-stage) -------------------------
template<int BN>
__global__ void k_colmean1(const float* __restrict__ H) {
    int t = threadIdx.x;       // < BN
    int r0 = blockIdx.x * 128;
    float s = 0.f;
    for (int r = 0; r < 128; r++) s += H[(size_t)(r0 + r) * BN + t];
    g_cmp[blockIdx.x * DIM + t] = s;
}
__global__ void k_colmean2(int BN) {
    int t = threadIdx.x;
    float s = 0.f;
    if (t < BN) for (int b = 0; b < 64; b++) s += g_cmp[b * DIM + t];
    g_cm[t] = s * (1.0f / NN);
}

// ---------------- dynamic shared layout ---------------------------------------
template<int BN, int MODE>
struct SmemP {
    static constexpr int HS = BN + 8;
    __nv_bfloat16 Adj[2][64][72];
    __nv_bfloat16 Hh[2][64][HS];
    __nv_bfloat16 Hl[2][64][HS];
    __nv_bfloat16 Phi[MODE ? 64 : 8][72];
    float A[64], B[64], Th[64], D[64];
};

template<int BN, int MODE>
__device__ __forceinline__ void mm_prefetch(SmemP<BN, MODE>& S, int buf,
                                            int k0, int i0, int t) {
    constexpr int HV = BN / 8;
#pragma unroll
    for (int l = 0; l < (64 * HV) / 256; l++) {
        int u = t + l * 256;
        int r = u / HV, c = (u % HV) * 8;
        cpasync16(smem_u32(&S.Hh[buf][r][c]), g_hh + (size_t)(k0 + r) * BN + c);
        cpasync16(smem_u32(&S.Hl[buf][r][c]), g_hl + (size_t)(k0 + r) * BN + c);
    }
#pragma unroll
    for (int l = 0; l < 2; l++) {
        int u = t + l * 256;
        int r = u >> 3, c = (u & 7) * 8;
        cpasync16(smem_u32(&S.Adj[buf][r][c]), g_adjb + (size_t)(i0 + r) * NN + k0 + c);
    }
}

// ---------------- unified tensor-core kernel (cp.async pipelined) -------------
// MODE 0: Out = resid + adj @ (Hhi+Hlo)
// MODE 1: P_ij = adj_ij * (s2_j>=th_i ? a_i*eg_j : b_i*eq_j) (bf16);
//         Out_i = elu(P@(Hhi+Hlo) / d_i)  (d_i==0 -> colmean), opt accumulate.
template<int BN, int MODE>
__global__ void __launch_bounds__(256) k_mma(
    const float* __restrict__ resid,
    float* __restrict__ Out, int accum)
{
    constexpr int BK = 64, NT = NN / BK;
    constexpr int NWN = BN / 32, NWM = 8 / NWN;
    constexpr int WM = 64 / NWM, FM = WM / 16, FN = 4;

    extern __shared__ char smem_raw[];
    SmemP<BN, MODE>& S = *reinterpret_cast<SmemP<BN, MODE>*>(smem_raw);

    const int t = threadIdx.x, lane = t & 31, warp = t >> 5;
    const int i0 = blockIdx.x * 64;
    const int wm = warp / NWN, wn = warp % NWN;
    const int pr = warp * 8 + (lane >> 2);   // P-gen row
    const int pc = (lane & 3) * 16;          // P-gen col start

    if (MODE && t < 64) {
        S.A[t] = g_pa[i0 + t]; S.B[t] = g_pb[i0 + t]; S.Th[t] = g_pth[i0 + t];
    }
    __syncthreads();
    float ai = 0.f, bi = 0.f, thi = 0.f;
    if (MODE) { ai = S.A[pr]; bi = S.B[pr]; thi = S.Th[pr]; }

    mm_prefetch(S, 0, 0, i0, t);  CP_COMMIT();
    mm_prefetch(S, 1, BK, i0, t); CP_COMMIT();

    float acc[FM][FN][4];
#pragma unroll
    for (int a = 0; a < FM; a++)
#pragma unroll
        for (int b = 0; b < FN; b++)
#pragma unroll
            for (int c = 0; c < 4; c++) acc[a][b][c] = 0.f;
    float dpart = 0.f;

    for (int kt = 0; kt < NT; kt++) {
        const int cur = kt & 1, k0 = kt * BK;
        CP_WAIT1();
        __syncthreads();

        if (MODE) {
            uint4 av0 = *(const uint4*)&S.Adj[cur][pr][pc];
            uint4 av1 = *(const uint4*)&S.Adj[cur][pr][pc + 8];
            unsigned short ab[16];
            *(uint4*)ab = av0; *(uint4*)(ab + 8) = av1;
            __align__(16) __nv_bfloat16 ph[16];
            const float* s2 = g_s2  + k0 + pc;
            const float* eg = g_peg + k0 + pc;
            const float* eq = g_peq + k0 + pc;
#pragma unroll
            for (int c = 0; c < 16; c++) {
                float p = 0.f;
                if (ab[c]) p = (s2[c] >= thi) ? ai * eg[c] : bi * eq[c];
                __nv_bfloat16 hb = __float2bfloat16(p);
                ph[c] = hb;
                dpart += __bfloat162float(hb);
            }
            *(uint4*)&S.Phi[pr][pc]     = *(uint4*)ph;
            *(uint4*)&S.Phi[pr][pc + 8] = *(uint4*)(ph + 8);
            __syncthreads();
        }

        const __nv_bfloat16 (*Am)[72] = MODE
            ? (const __nv_bfloat16 (*)[72])S.Phi
            : (const __nv_bfloat16 (*)[72])S.Adj[cur];

#pragma unroll
        for (int kk = 0; kk < 4; kk++) {
            u32 ah[FM][4];
#pragma unroll
            for (int fm = 0; fm < FM; fm++) {
                int rr = wm * WM + fm * 16 + (lane & 15);
                int cc = kk * 16 + (lane >> 4) * 8;
                ldm_x4(smem_u32(&Am[rr][cc]), ah[fm]);
            }
            u32 bh[4][2], bl[4][2];
#pragma unroll
            for (int fp2 = 0; fp2 < 2; fp2++) {
                int rr = kk * 16 + (lane & 15);
                int cc = wn * 32 + fp2 * 16 + (lane >> 4) * 8;
                u32 r4[4];
                ldm_x4t(smem_u32(&S.Hh[cur][rr][cc]), r4);
                bh[2*fp2][0] = r4[0]; bh[2*fp2][1] = r4[1];
                bh[2*fp2+1][0] = r4[2]; bh[2*fp2+1][1] = r4[3];
                ldm_x4t(smem_u32(&S.Hl[cur][rr][cc]), r4);
                bl[2*fp2][0] = r4[0]; bl[2*fp2][1] = r4[1];
                bl[2*fp2+1][0] = r4[2]; bl[2*fp2+1][1] = r4[3];
            }
#pragma unroll
            for (int fm = 0; fm < FM; fm++)
#pragma unroll
                for (int fn = 0; fn < FN; fn++) {
                    mma_bf16(acc[fm][fn], ah[fm], bh[fn]);
                    mma_bf16(acc[fm][fn], ah[fm], bl[fn]);
                }
        }
        __syncthreads();
        if (kt + 2 < NT) mm_prefetch(S, cur, k0 + 2 * BK, i0, t);
        CP_COMMIT();
    }

    // ---- d reduce (MODE 1) ----
    if (MODE) {
        dpart += __shfl_xor_sync(0xffffffffu, dpart, 1);
        dpart += __shfl_xor_sync(0xffffffffu, dpart, 2);
        if ((lane & 3) == 0) S.D[pr] = dpart;
    }
    __syncthreads();

    // ---- epilogue ----
#pragma unroll
    for (int fm = 0; fm < FM; fm++) {
#pragma unroll
        for (int h = 0; h < 2; h++) {
            int rl = wm * WM + fm * 16 + (lane >> 2) + h * 8;
            int row = i0 + rl;
#pragma unroll
            for (int fn = 0; fn < FN; fn++) {
                int col = wn * 32 + fn * 8 + (lane & 3) * 2;
                float v0 = acc[fm][fn][2 * h], v1 = acc[fm][fn][2 * h + 1];
                float* op = Out + (size_t)row * BN + col;
                if (MODE == 0) {
                    float2 rr = *(const float2*)(resid + (size_t)row * BN + col);
                    float2 o; o.x = v0 + rr.x; o.y = v1 + rr.y;
                    *(float2*)op = o;
                } else {
                    float dd = S.D[rl];
                    if (dd > 0.f) { float inv = 1.0f / dd; v0 *= inv; v1 *= inv; }
                    else          { v0 = g_cm[col]; v1 = g_cm[col + 1]; }
                    v0 = (v0 > 0.f) ? v0 : fexp(v0) - 1.0f;
                    v1 = (v1 > 0.f) ? v1 : fexp(v1) - 1.0f;
                    if (accum) {
                        float2 zz = *(const float2*)op;
                        v0 += zz.x; v1 += zz.y;
                    }
                    float2 o; o.x = v0; o.y = v1;
                    *(float2*)op = o;
                }
            }
        }
    }
}

// ---------------- small dense GEMM (f32x2) + fused hi/lo split ----------------
template<int BN>
__global__ void __launch_bounds__(256) k_gemm(
        const float* __restrict__ A, int lda, int K,
        const float* __restrict__ B,
        const float* __restrict__ bias,
        float* __restrict__ C, float scale, int relu, int split, int rst)
{
    constexpr int BM = 32, BK = 32, TM = 2, TN = BN / 16;
    __shared__ float As[BK][BM + 4];
    __shared__ float Bs[BK][BN];
    const int t  = threadIdx.x;
    const int tx = t & 15, ty = t >> 4;
    const int row0 = blockIdx.x * BM;

    if (rst && blockIdx.x == 0 && t == 0) g_s2maxu = 0u;

    u64 acc[TM][TN / 2];
#pragma unroll
    for (int i = 0; i < TM; i++)
#pragma unroll
        for (int j = 0; j < TN / 2; j++) acc[i][j] = 0ULL;

    for (int k0 = 0; k0 < K; k0 += BK) {
#pragma unroll
        for (int l = 0; l < (BM * BK) / 256; l++) {
            int idx = t + l * 256;
            int m = idx >> 5, k = idx & 31;
            As[k][m] = A[(size_t)(row0 + m) * lda + k0 + k];
        }
#pragma unroll
        for (int l = 0; l < (BK * BN) / 256; l++) {
            int idx = t + l * 256;
            int k = idx / BN, c = idx % BN;
            Bs[k][c] = B[(size_t)(k0 + k) * BN + c];
        }
        __syncthreads();
#pragma unroll
        for (int kk = 0; kk < BK; kk++) {
            float2 a2 = *(const float2*)&As[kk][ty * TM];
            u64 ap[2] = { pk2(a2.x, a2.x), pk2(a2.y, a2.y) };
            const u64* bp = (const u64*)&Bs[kk][tx * TN];
            u64 b[TN / 2];
#pragma unroll
            for (int j = 0; j < TN / 2; j++) b[j] = bp[j];
#pragma unroll
            for (int i = 0; i < TM; i++)
#pragma unroll
                for (int j = 0; j < TN / 2; j++) fma2(acc[i][j], ap[i], b[j]);
        }
        __syncthreads();
    }
#pragma unroll
    for (int i = 0; i < TM; i++) {
        int m = row0 + ty * TM + i;
#pragma unroll
        for (int j = 0; j < TN / 2; j++) {
            int c = tx * TN + 2 * j;
            float lo, hi; upk2(acc[i][j], lo, hi);
            float v0 = scale * lo, v1 = scale * hi;
            if (bias)  { v0 += bias[c]; v1 += bias[c + 1]; }
            if (relu)  { v0 = fmaxf(v0, 0.f); v1 = fmaxf(v1, 0.f); }
            float2 o; o.x = v0; o.y = v1;
            *(float2*)&C[(size_t)m * BN + c] = o;
            if (split) {
                __nv_bfloat16 h0 = __float2bfloat16(v0);
                __nv_bfloat16 h1 = __float2bfloat16(v1);
                __nv_bfloat162 hh; hh.x = h0; hh.y = h1;
                __nv_bfloat162 hl;
                hl.x = __float2bfloat16(v0 - __bfloat162float(h0));
                hl.y = __float2bfloat16(v1 - __bfloat162float(h1));
                *(__nv_bfloat162*)&g_hh[(size_t)m * BN + c] = hh;
                *(__nv_bfloat162*)&g_hl[(size_t)m * BN + c] = hl;
            }
        }
    }
}

// ---------------- row softmax over first 56 of 64 cols ------------------------
__global__ void k_smax56(float* __restrict__ X) {
    int w = threadIdx.x >> 5, lane = threadIdx.x & 31;
    int row = blockIdx.x * 8 + w;
    float* r = X + (size_t)row * ODP;
    float v0 = (lane < OD)      ? r[lane]      : -3e38f;
    float v1 = (lane + 32 < OD) ? r[lane + 32] : -3e38f;
    float m = fmaxf(v0, v1);
#pragma unroll
    for (int o = 16; o > 0; o >>= 1) m = fmaxf(m, __shfl_xor_sync(0xffffffffu, m, o));
    float e0 = (lane < OD)      ? fexp(v0 - m) : 0.f;
    float e1 = (lane + 32 < OD) ? fexp(v1 - m) : 0.f;
    float s = e0 + e1;
#pragma unroll
    for (int o = 16; o > 0; o >>= 1) s += __shfl_xor_sync(0xffffffffu, s, o);
    float inv = 1.0f / s;
    if (lane < OD)      r[lane]      = e0 * inv;
    if (lane + 32 < OD) r[lane + 32] = e1 * inv;
}

// ---------------- segment-sum readout + MLP head ------------------------------
__global__ void k_head(const int* __restrict__ seg,
                       const float* __restrict__ Wout, const float* __restrict__ bout,
                       const float* __restrict__ Wprop, const float* __restrict__ bprop,
                       float* __restrict__ out)
{
    __shared__ float v[OD];
    __shared__ float o[OD];
    __shared__ int bnd[2];
    const int m = blockIdx.x, t = threadIdx.x;
    if (t < 2) {
        int target = m + t;
        int lo = 0, hi = NN;
        while (lo < hi) { int mid = (lo + hi) >> 1; if (seg[mid] < target) lo = mid + 1; else hi = mid; }
        bnd[t] = lo;
    }
    __syncthreads();
    int lo = bnd[0], hi = bnd[1];
    if (t < OD) {
        float s = 0.f;
        for (int i = lo; i < hi; i++) s += g_a56[(size_t)i * ODP + t];
        v[t] = s;
    }
    __syncthreads();
    for (int l = 0; l < 2; l++) {
        if (t < OD) {
            float s = bout[l * OD + t];
            const float* W = Wout + l * OD * OD;
            for (int k = 0; k < OD; k++) s = fmaf(v[k], W[k * OD + t], s);
            o[t] = fmaxf(s, 0.f);
        }
        __syncthreads();
        if (t < OD) v[t] = o[t];
        __syncthreads();
    }
    if (t < 2) {
        float s = bprop[t];
        for (int k = 0; k < OD; k++) s = fmaf(v[k], Wprop[k * 2 + t], s);
        float r;
        if (s >= 0.f) r = 1.0f / (1.0f + fexp(-s));
        else { float e = fexp(s); r = e / (1.0f + e); }
        out[m * 2 + t] = r;
    }
}

// ---------------- orchestration ----------------------------------------------
extern "C" void kernel_launch(void* const* d_in, const int* in_sizes, int n_in,
                              void* d_out, int out_size) {
    const int*   fp   = (const int*)  d_in[0];
    const float* adj  = (const float*)d_in[1];
    const int*   seg  = (const int*)  d_in[2];
    const float* emb  = (const float*)d_in[3];
    const float* Wfp  = (const float*)d_in[4];
    const float* bfp  = (const float*)d_in[5];
    const float* Wh   = (const float*)d_in[6];
    const float* ah   = (const float*)d_in[7];
    const float* Woa  = (const float*)d_in[8];
    const float* aoa  = (const float*)d_in[9];
    const float* Wout = (const float*)d_in[10];
    const float* bout = (const float*)d_in[11];
    const float* Wpr  = (const float*)d_in[12];
    const float* bpr  = (const float*)d_in[13];
    float* out = (float*)d_out;

    float *x, *h, *tb, *z, *ho, *a56, *wpad;
    cudaGetSymbolAddress((void**)&x,    g_x);
    cudaGetSymbolAddress((void**)&h,    g_h);
    cudaGetSymbolAddress((void**)&tb,   g_t);
    cudaGetSymbolAddress((void**)&z,    g_z);
    cudaGetSymbolAddress((void**)&ho,   g_ho);
    cudaGetSymbolAddress((void**)&a56,  g_a56);
    cudaGetSymbolAddress((void**)&wpad, g_wpad);

    const int SZ128_0 = (int)sizeof(SmemP<128, 0>);
    const int SZ128_1 = (int)sizeof(SmemP<128, 1>);
    const int SZ64_1  = (int)sizeof(SmemP<64, 1>);
    cudaFuncSetAttribute(k_mma<128,0>, cudaFuncAttributeMaxDynamicSharedMemorySize, SZ128_0);
    cudaFuncSetAttribute(k_mma<128,1>, cudaFuncAttributeMaxDynamicSharedMemorySize, SZ128_1);
    cudaFuncSetAttribute(k_mma<64,1>,  cudaFuncAttributeMaxDynamicSharedMemorySize, SZ64_1);

    k_gather<<<NN * DIM / 256, 256>>>(fp, emb);
    k_adjconv<<<(size_t)NN * NN / 2048, 256>>>(adj);
    k_padw<<<DIM * ODP / 256, 256>>>(Woa);

    // 3 message-passing layers
    for (int l = 0; l < 3; l++) {
        k_gemm<128><<<NN / 32, 256>>>(x, DIM, DIM, Wfp + l * DIM * DIM,
                                      bfp + l * DIM, h, 1.f, 1, 1, 0);
        k_mma<128, 0><<<NN / 64, 256, SZ128_0>>>(h, tb, 0);
        k_l2norm<<<NN / 8, 256>>>(tb, x);
    }

    // 2 GAT heads
    for (int hd = 0; hd < 2; hd++) {
        k_gemm<128><<<NN / 32, 256>>>(x, DIM, DIM, Wh + hd * DIM * DIM,
                                      nullptr, h, 1.f, 0, 1, 1);
        k_s12<<<NN / 8, 256>>>(h, DIM, DIM, ah + hd * 2 * DIM);
        k_prep<<<NN / 256, 256>>>();
        k_colmean1<128><<<64, 128>>>(h);
        k_colmean2<<<1, 128>>>(128);
        k_mma<128, 1><<<NN / 64, 256, SZ128_1>>>(nullptr, z, hd);
    }

    // out-attention at D=56 (padded to 64); x = z/2 folded into scale
    k_gemm<64><<<NN / 32, 256>>>(z, DIM, DIM, wpad, nullptr, ho, 0.5f, 0, 1, 1);
    k_s12<<<NN / 8, 256>>>(ho, ODP, OD, aoa);
    k_prep<<<NN / 256, 256>>>();
    k_colmean1<64><<<64, 64>>>(ho);
    k_colmean2<<<1, 128>>>(64);
    k_mma<64, 1><<<NN / 64, 256, SZ64_1>>>(nullptr, a56, 0);

    k_smax56<<<NN / 8, 256>>>(a56);
    k_head<<<NMOL, 64>>>(seg, Wout, bout, Wpr, bpr, out);
}

// round 5
// speedup vs baseline: 3.6004x; 1.2586x over previous
#include <cuda_runtime.h>
#include <cuda_bf16.h>
#include <math.h>

#define NN   8192
#define DIM  128
#define NMOL 256
#define OD   56
#define ODP  64

typedef unsigned long long u64;
typedef unsigned int u32;

// ---------------- f32x2 helpers ----------------------------------------------
__device__ __forceinline__ u64 pk2(float lo, float hi) {
    u64 r; asm("mov.b64 %0, {%1,%2};" : "=l"(r) : "f"(lo), "f"(hi)); return r;
}
__device__ __forceinline__ void upk2(u64 v, float &lo, float &hi) {
    asm("mov.b64 {%0,%1}, %2;" : "=f"(lo), "=f"(hi) : "l"(v));
}
__device__ __forceinline__ void fma2(u64 &d, u64 a, u64 b) {
    asm("fma.rn.f32x2 %0, %1, %2, %0;" : "+l"(d) : "l"(a), "l"(b));
}

// ---------------- FMA-only exp ------------------------------------------------
__device__ __forceinline__ float fexp(float x) {
    x = fmaxf(x, -87.0f);
    float y = x * 1.44269504f;
    float r = rintf(y);
    float f = y - r;
    float p = 1.33335581e-3f;
    p = fmaf(p, f, 9.61812911e-3f);
    p = fmaf(p, f, 5.55041087e-2f);
    p = fmaf(p, f, 2.40226507e-1f);
    p = fmaf(p, f, 6.93147181e-1f);
    p = fmaf(p, f, 1.0f);
    int e = (int)r;
    return p * __int_as_float((e + 127) << 23);
}

// monotone float<->u32 encoding for atomicMax over signed floats
__device__ __forceinline__ u32 encf(float s) {
    u32 b = __float_as_uint(s);
    return (b & 0x80000000u) ? ~b : (b | 0x80000000u);
}
__device__ __forceinline__ float decf(u32 u) {
    return __uint_as_float((u & 0x80000000u) ? (u & 0x7fffffffu) : ~u);
}

// ---------------- MMA / ldmatrix / cp.async helpers ---------------------------
__device__ __forceinline__ u32 smem_u32(const void* p) {
    return (u32)__cvta_generic_to_shared(p);
}
__device__ __forceinline__ void ldm_x4(u32 a, u32* r) {
    asm volatile("ldmatrix.sync.aligned.m8n8.x4.shared.b16 {%0,%1,%2,%3}, [%4];"
        : "=r"(r[0]), "=r"(r[1]), "=r"(r[2]), "=r"(r[3]) : "r"(a));
}
__device__ __forceinline__ void ldm_x4t(u32 a, u32* r) {
    asm volatile("ldmatrix.sync.aligned.m8n8.x4.trans.shared.b16 {%0,%1,%2,%3}, [%4];"
        : "=r"(r[0]), "=r"(r[1]), "=r"(r[2]), "=r"(r[3]) : "r"(a));
}
__device__ __forceinline__ void mma_bf16(float* c, const u32* a, const u32* b) {
    asm volatile(
        "mma.sync.aligned.m16n8k16.row.col.f32.bf16.bf16.f32 "
        "{%0,%1,%2,%3}, {%4,%5,%6,%7}, {%8,%9}, {%0,%1,%2,%3};"
        : "+f"(c[0]), "+f"(c[1]), "+f"(c[2]), "+f"(c[3])
        : "r"(a[0]), "r"(a[1]), "r"(a[2]), "r"(a[3]), "r"(b[0]), "r"(b[1]));
}
__device__ __forceinline__ void cpasync16(u32 dst, const void* src) {
    asm volatile("cp.async.cg.shared.global [%0], [%1], 16;" :: "r"(dst), "l"(src));
}
#define CP_COMMIT() asm volatile("cp.async.commit_group;" ::: "memory")
#define CP_WAIT1()  asm volatile("cp.async.wait_group 1;" ::: "memory")

// ---------------- scratch -----------------------------------------------------
__device__ __nv_bfloat16 g_adjb[(size_t)NN * NN];   // 128 MB, exact 0/1
__device__ __nv_bfloat16 g_hh[NN * DIM];
__device__ float g_x [NN * DIM];
__device__ float g_h [NN * DIM];
__device__ float g_t [NN * DIM];
__device__ float g_z [NN * DIM];
__device__ float g_s1[NN];
__device__ float g_s2[NN];
__device__ u32   g_s2maxu;
__device__ float g_pa[NN], g_pb[NN], g_pth[NN], g_peg[NN], g_peq[NN];
__device__ float g_ho [NN * ODP];
__device__ float g_a56[NN * ODP];
__device__ float g_wpad[DIM * ODP];
__device__ float g_cm[DIM];
__device__ float g_cmp[64 * DIM];

// ---------------- small utility kernels ---------------------------------------
__global__ void k_gather(const int* __restrict__ fp, const float* __restrict__ emb) {
    int idx = blockIdx.x * 256 + threadIdx.x;
    int i = idx >> 7, c = idx & 127;
    g_x[idx] = emb[fp[i] * DIM + c];
}

__global__ void k_padw(const float* __restrict__ W) {
    int idx = blockIdx.x * 256 + threadIdx.x;
    int k = idx >> 6, c = idx & 63;
    g_wpad[idx] = (c < OD) ? W[k * OD + c] : 0.0f;
}

__global__ void k_adjconv(const float* __restrict__ adj) {
    size_t base = ((size_t)blockIdx.x * 256 + threadIdx.x) * 8;
    float4 a = *(const float4*)(adj + base);
    float4 b = *(const float4*)(adj + base + 4);
    __nv_bfloat16 o[8];
    o[0]=__float2bfloat16(a.x); o[1]=__float2bfloat16(a.y);
    o[2]=__float2bfloat16(a.z); o[3]=__float2bfloat16(a.w);
    o[4]=__float2bfloat16(b.x); o[5]=__float2bfloat16(b.y);
    o[6]=__float2bfloat16(b.z); o[7]=__float2bfloat16(b.w);
    *(uint4*)(g_adjb + base) = *(uint4*)o;
}

// ---------------- row L2-normalize --------------------------------------------
__global__ void k_l2norm(const float* __restrict__ in, float* __restrict__ out) {
    int w = threadIdx.x >> 5, lane = threadIdx.x & 31;
    int row = blockIdx.x * 8 + w;
    const float* r = in + (size_t)row * DIM;
    float v[4], ss = 0.f;
#pragma unroll
    for (int q = 0; q < 4; q++) { v[q] = r[lane + q * 32]; ss += v[q] * v[q]; }
#pragma unroll
    for (int o = 16; o > 0; o >>= 1) ss += __shfl_xor_sync(0xffffffffu, ss, o);
    float inv = 1.0f / fmaxf(sqrtf(ss), 1e-12f);
#pragma unroll
    for (int q = 0; q < 4; q++) out[(size_t)row * DIM + lane + q * 32] = v[q] * inv;
}

// ---------------- s1/s2 projections + global s2 max ---------------------------
__global__ void k_s12(const float* __restrict__ H, int ld, int Dr,
                      const float* __restrict__ a) {
    int w = threadIdx.x >> 5, lane = threadIdx.x & 31;
    int row = blockIdx.x * 8 + w;
    const float* r = H + (size_t)row * ld;
    float p1 = 0.f, p2 = 0.f;
    for (int c = lane; c < Dr; c += 32) {
        float v = r[c];
        p1 = fmaf(v, a[c], p1);
        p2 = fmaf(v, a[Dr + c], p2);
    }
#pragma unroll
    for (int o = 16; o > 0; o >>= 1) {
        p1 += __shfl_xor_sync(0xffffffffu, p1, o);
        p2 += __shfl_xor_sync(0xffffffffu, p2, o);
    }
    if (lane == 0) {
        g_s1[row] = p1; g_s2[row] = p2;
        atomicMax(&g_s2maxu, encf(p2));
    }
}

// ---------------- per-node attention precompute -------------------------------
__global__ void k_prep() {
    int i = blockIdx.x * 256 + threadIdx.x;
    float gmax = decf(g_s2maxu);
    float s1 = g_s1[i], s2 = g_s2[i];
    float u = s1 + gmax;
    float m = (u > 0.f) ? u : 0.25f * u;
    g_pa[i] = fexp(s1 - m);
    g_pb[i] = fexp(0.25f * s1 - m);
    g_pth[i] = -s1;
    g_peg[i] = fexp(s2);
    g_peq[i] = fexp(0.25f * s2);
}

// ---------------- column mean (deterministic 2-stage) -------------------------
template<int BN>
__global__ void k_colmean1(const float* __restrict__ H) {
    int t = threadIdx.x;       // < BN
    int r0 = blockIdx.x * 128;
    float s = 0.f;
    for (int r = 0; r < 128; r++) s += H[(size_t)(r0 + r) * BN + t];
    g_cmp[blockIdx.x * DIM + t] = s;
}
__global__ void k_colmean2(int BN) {
    int t = threadIdx.x;
    float s = 0.f;
    if (t < BN) for (int b = 0; b < 64; b++) s += g_cmp[b * DIM + t];
    g_cm[t] = s * (1.0f / NN);
}

// ---------------- dynamic shared layout (3-stage pipeline) --------------------
template<int BN, int MODE>
struct SmemP {
    static constexpr int HS = BN + 8;
    __nv_bfloat16 Adj[3][64][72];
    __nv_bfloat16 Hh[3][64][HS];
    __nv_bfloat16 Phi[MODE ? 2 : 1][64][72];
    float A[64], B[64], Th[64], D[64];
};

template<int BN, int MODE>
__device__ __forceinline__ void mm_prefetch(SmemP<BN, MODE>& S, int buf,
                                            int k0, int i0, int t) {
    constexpr int HV = BN / 8;
#pragma unroll
    for (int l = 0; l < (64 * HV) / 256; l++) {
        int u = t + l * 256;
        int r = u / HV, c = (u % HV) * 8;
        cpasync16(smem_u32(&S.Hh[buf][r][c]), g_hh + (size_t)(k0 + r) * BN + c);
    }
#pragma unroll
    for (int l = 0; l < 2; l++) {
        int u = t + l * 256;
        int r = u >> 3, c = (u & 7) * 8;
        cpasync16(smem_u32(&S.Adj[buf][r][c]), g_adjb + (size_t)(i0 + r) * NN + k0 + c);
    }
}

// ---------------- unified tensor-core kernel (3-stage cp.async) ---------------
// MODE 0: Out = resid + adj @ Hh
// MODE 1: P_ij = adj_ij * (s2_j>=th_i ? a_i*eg_j : b_i*eq_j) (bf16);
//         Out_i = elu(P@Hh / d_i)  (d_i==0 -> colmean), opt accumulate.
template<int BN, int MODE>
__global__ void __launch_bounds__(256) k_mma(
    const float* __restrict__ resid,
    float* __restrict__ Out, int accum)
{
    constexpr int BK = 64, NT = NN / BK;
    constexpr int NWN = BN / 32, NWM = 8 / NWN;
    constexpr int WM = 64 / NWM, FM = WM / 16, FN = 4;

    extern __shared__ char smem_raw[];
    SmemP<BN, MODE>& S = *reinterpret_cast<SmemP<BN, MODE>*>(smem_raw);

    const int t = threadIdx.x, lane = t & 31, warp = t >> 5;
    const int i0 = blockIdx.x * 64;
    const int wm = warp / NWN, wn = warp % NWN;
    const int pr = warp * 8 + (lane >> 2);   // P-gen row
    const int pc = (lane & 3) * 16;          // P-gen col start

    if (MODE && t < 64) {
        S.A[t] = g_pa[i0 + t]; S.B[t] = g_pb[i0 + t]; S.Th[t] = g_pth[i0 + t];
    }
    __syncthreads();
    float ai = 0.f, bi = 0.f, thi = 0.f;
    if (MODE) { ai = S.A[pr]; bi = S.B[pr]; thi = S.Th[pr]; }

    mm_prefetch(S, 0, 0, i0, t);  CP_COMMIT();
    mm_prefetch(S, 1, BK, i0, t); CP_COMMIT();

    float acc[FM][FN][4];
#pragma unroll
    for (int a = 0; a < FM; a++)
#pragma unroll
        for (int b = 0; b < FN; b++)
#pragma unroll
            for (int c = 0; c < 4; c++) acc[a][b][c] = 0.f;
    float dpart = 0.f;

    for (int kt = 0; kt < NT; kt++) {
        const int cur = kt % 3, k0 = kt * BK;
        CP_WAIT1();
        __syncthreads();   // stage cur landed; MMA(kt-1) complete chip-wide in CTA

        // prefetch stage kt+2 into buffer (kt+2)%3 == (kt-1)%3 (free after sync)
        if (kt + 2 < NT) mm_prefetch(S, (kt + 2) % 3, k0 + 2 * BK, i0, t);
        CP_COMMIT();

        const __nv_bfloat16 (*Am)[72];
        if (MODE) {
            const int pb = kt & 1;
            uint4 av0 = *(const uint4*)&S.Adj[cur][pr][pc];
            uint4 av1 = *(const uint4*)&S.Adj[cur][pr][pc + 8];
            unsigned short ab[16];
            *(uint4*)ab = av0; *(uint4*)(ab + 8) = av1;
            __align__(16) __nv_bfloat16 ph[16];
            const float* s2 = g_s2  + k0 + pc;
            const float* eg = g_peg + k0 + pc;
            const float* eq = g_peq + k0 + pc;
#pragma unroll
            for (int c = 0; c < 16; c++) {
                float p = 0.f;
                if (ab[c]) p = (s2[c] >= thi) ? ai * eg[c] : bi * eq[c];
                __nv_bfloat16 hb = __float2bfloat16(p);
                ph[c] = hb;
                dpart += __bfloat162float(hb);
            }
            *(uint4*)&S.Phi[pb][pr][pc]     = *(uint4*)ph;
            *(uint4*)&S.Phi[pb][pr][pc + 8] = *(uint4*)(ph + 8);
            __syncthreads();
            Am = (const __nv_bfloat16 (*)[72])S.Phi[pb];
        } else {
            Am = (const __nv_bfloat16 (*)[72])S.Adj[cur];
        }

#pragma unroll
        for (int kk = 0; kk < 4; kk++) {
            u32 ah[FM][4];
#pragma unroll
            for (int fm = 0; fm < FM; fm++) {
                int rr = wm * WM + fm * 16 + (lane & 15);
                int cc = kk * 16 + (lane >> 4) * 8;
                ldm_x4(smem_u32(&Am[rr][cc]), ah[fm]);
            }
            u32 bh[4][2];
#pragma unroll
            for (int fp2 = 0; fp2 < 2; fp2++) {
                int rr = kk * 16 + (lane & 15);
                int cc = wn * 32 + fp2 * 16 + (lane >> 4) * 8;
                u32 r4[4];
                ldm_x4t(smem_u32(&S.Hh[cur][rr][cc]), r4);
                bh[2*fp2][0] = r4[0]; bh[2*fp2][1] = r4[1];
                bh[2*fp2+1][0] = r4[2]; bh[2*fp2+1][1] = r4[3];
            }
#pragma unroll
            for (int fm = 0; fm < FM; fm++)
#pragma unroll
                for (int fn = 0; fn < FN; fn++)
                    mma_bf16(acc[fm][fn], ah[fm], bh[fn]);
        }
    }

    // ---- d reduce (MODE 1) ----
    if (MODE) {
        dpart += __shfl_xor_sync(0xffffffffu, dpart, 1);
        dpart += __shfl_xor_sync(0xffffffffu, dpart, 2);
        if ((lane & 3) == 0) S.D[pr] = dpart;
    }
    __syncthreads();

    // ---- epilogue ----
#pragma unroll
    for (int fm = 0; fm < FM; fm++) {
#pragma unroll
        for (int h = 0; h < 2; h++) {
            int rl = wm * WM + fm * 16 + (lane >> 2) + h * 8;
            int row = i0 + rl;
#pragma unroll
            for (int fn = 0; fn < FN; fn++) {
                int col = wn * 32 + fn * 8 + (lane & 3) * 2;
                float v0 = acc[fm][fn][2 * h], v1 = acc[fm][fn][2 * h + 1];
                float* op = Out + (size_t)row * BN + col;
                if (MODE == 0) {
                    float2 rr = *(const float2*)(resid + (size_t)row * BN + col);
                    float2 o; o.x = v0 + rr.x; o.y = v1 + rr.y;
                    *(float2*)op = o;
                } else {
                    float dd = S.D[rl];
                    if (dd > 0.f) { float inv = 1.0f / dd; v0 *= inv; v1 *= inv; }
                    else          { v0 = g_cm[col]; v1 = g_cm[col + 1]; }
                    v0 = (v0 > 0.f) ? v0 : fexp(v0) - 1.0f;
                    v1 = (v1 > 0.f) ? v1 : fexp(v1) - 1.0f;
                    if (accum) {
                        float2 zz = *(const float2*)op;
                        v0 += zz.x; v1 += zz.y;
                    }
                    float2 o; o.x = v0; o.y = v1;
                    *(float2*)op = o;
                }
            }
        }
    }
}

// ---------------- small dense GEMM (f32x2) + fused bf16 round -----------------
template<int BN>
__global__ void __launch_bounds__(256) k_gemm(
        const float* __restrict__ A, int lda, int K,
        const float* __restrict__ B,
        const float* __restrict__ bias,
        float* __restrict__ C, float scale, int relu, int split, int rst)
{
    constexpr int BM = 64, BK = 32, TM = 4, TN = BN / 16;
    __shared__ float As[BK][BM + 4];
    __shared__ float Bs[BK][BN];
    const int t  = threadIdx.x;
    const int tx = t & 15, ty = t >> 4;
    const int row0 = blockIdx.x * BM;

    if (rst && blockIdx.x == 0 && t == 0) g_s2maxu = 0u;

    u64 acc[TM][TN / 2];
#pragma unroll
    for (int i = 0; i < TM; i++)
#pragma unroll
        for (int j = 0; j < TN / 2; j++) acc[i][j] = 0ULL;

    for (int k0 = 0; k0 < K; k0 += BK) {
#pragma unroll
        for (int l = 0; l < (BM * BK) / 256; l++) {
            int idx = t + l * 256;
            int m = idx >> 5, k = idx & 31;
            As[k][m] = A[(size_t)(row0 + m) * lda + k0 + k];
        }
#pragma unroll
        for (int l = 0; l < (BK * BN) / 256; l++) {
            int idx = t + l * 256;
            int k = idx / BN, c = idx % BN;
            Bs[k][c] = B[(size_t)(k0 + k) * BN + c];
        }
        __syncthreads();
#pragma unroll
        for (int kk = 0; kk < BK; kk++) {
            float4 a4 = *(const float4*)&As[kk][ty * TM];
            u64 ap[4] = { pk2(a4.x, a4.x), pk2(a4.y, a4.y),
                          pk2(a4.z, a4.z), pk2(a4.w, a4.w) };
            const u64* bp = (const u64*)&Bs[kk][tx * TN];
            u64 b[TN / 2];
#pragma unroll
            for (int j = 0; j < TN / 2; j++) b[j] = bp[j];
#pragma unroll
            for (int i = 0; i < TM; i++)
#pragma unroll
                for (int j = 0; j < TN / 2; j++) fma2(acc[i][j], ap[i], b[j]);
        }
        __syncthreads();
    }
#pragma unroll
    for (int i = 0; i < TM; i++) {
        int m = row0 + ty * TM + i;
#pragma unroll
        for (int j = 0; j < TN / 2; j++) {
            int c = tx * TN + 2 * j;
            float lo, hi; upk2(acc[i][j], lo, hi);
            float v0 = scale * lo, v1 = scale * hi;
            if (bias)  { v0 += bias[c]; v1 += bias[c + 1]; }
            if (relu)  { v0 = fmaxf(v0, 0.f); v1 = fmaxf(v1, 0.f); }
            float2 o; o.x = v0; o.y = v1;
            *(float2*)&C[(size_t)m * BN + c] = o;
            if (split) {
                __nv_bfloat162 hh;
                hh.x = __float2bfloat16(v0);
                hh.y = __float2bfloat16(v1);
                *(__nv_bfloat162*)&g_hh[(size_t)m * BN + c] = hh;
            }
        }
    }
}

// ---------------- row softmax over first 56 of 64 cols ------------------------
__global__ void k_smax56(float* __restrict__ X) {
    int w = threadIdx.x >> 5, lane = threadIdx.x & 31;
    int row = blockIdx.x * 8 + w;
    float* r = X + (size_t)row * ODP;
    float v0 = (lane < OD)      ? r[lane]      : -3e38f;
    float v1 = (lane + 32 < OD) ? r[lane + 32] : -3e38f;
    float m = fmaxf(v0, v1);
#pragma unroll
    for (int o = 16; o > 0; o >>= 1) m = fmaxf(m, __shfl_xor_sync(0xffffffffu, m, o));
    float e0 = (lane < OD)      ? fexp(v0 - m) : 0.f;
    float e1 = (lane + 32 < OD) ? fexp(v1 - m) : 0.f;
    float s = e0 + e1;
#pragma unroll
    for (int o = 16; o > 0; o >>= 1) s += __shfl_xor_sync(0xffffffffu, s, o);
    float inv = 1.0f / s;
    if (lane < OD)      r[lane]      = e0 * inv;
    if (lane + 32 < OD) r[lane + 32] = e1 * inv;
}

// ---------------- segment-sum readout + MLP head ------------------------------
__global__ void k_head(const int* __restrict__ seg,
                       const float* __restrict__ Wout, const float* __restrict__ bout,
                       const float* __restrict__ Wprop, const float* __restrict__ bprop,
                       float* __restrict__ out)
{
    __shared__ float v[OD];
    __shared__ float o[OD];
    __shared__ int bnd[2];
    const int m = blockIdx.x, t = threadIdx.x;
    if (t < 2) {
        int target = m + t;
        int lo = 0, hi = NN;
        while (lo < hi) { int mid = (lo + hi) >> 1; if (seg[mid] < target) lo = mid + 1; else hi = mid; }
        bnd[t] = lo;
    }
    __syncthreads();
    int lo = bnd[0], hi = bnd[1];
    if (t < OD) {
        float s = 0.f;
        for (int i = lo; i < hi; i++) s += g_a56[(size_t)i * ODP + t];
        v[t] = s;
    }
    __syncthreads();
    for (int l = 0; l < 2; l++) {
        if (t < OD) {
            float s = bout[l * OD + t];
            const float* W = Wout + l * OD * OD;
            for (int k = 0; k < OD; k++) s = fmaf(v[k], W[k * OD + t], s);
            o[t] = fmaxf(s, 0.f);
        }
        __syncthreads();
        if (t < OD) v[t] = o[t];
        __syncthreads();
    }
    if (t < 2) {
        float s = bprop[t];
        for (int k = 0; k < OD; k++) s = fmaf(v[k], Wprop[k * 2 + t], s);
        float r;
        if (s >= 0.f) r = 1.0f / (1.0f + fexp(-s));
        else { float e = fexp(s); r = e / (1.0f + e); }
        out[m * 2 + t] = r;
    }
}

// ---------------- orchestration ----------------------------------------------
extern "C" void kernel_launch(void* const* d_in, const int* in_sizes, int n_in,
                              void* d_out, int out_size) {
    const int*   fp   = (const int*)  d_in[0];
    const float* adj  = (const float*)d_in[1];
    const int*   seg  = (const int*)  d_in[2];
    const float* emb  = (const float*)d_in[3];
    const float* Wfp  = (const float*)d_in[4];
    const float* bfp  = (const float*)d_in[5];
    const float* Wh   = (const float*)d_in[6];
    const float* ah   = (const float*)d_in[7];
    const float* Woa  = (const float*)d_in[8];
    const float* aoa  = (const float*)d_in[9];
    const float* Wout = (const float*)d_in[10];
    const float* bout = (const float*)d_in[11];
    const float* Wpr  = (const float*)d_in[12];
    const float* bpr  = (const float*)d_in[13];
    float* out = (float*)d_out;

    float *x, *h, *tb, *z, *ho, *a56, *wpad;
    cudaGetSymbolAddress((void**)&x,    g_x);
    cudaGetSymbolAddress((void**)&h,    g_h);
    cudaGetSymbolAddress((void**)&tb,   g_t);
    cudaGetSymbolAddress((void**)&z,    g_z);
    cudaGetSymbolAddress((void**)&ho,   g_ho);
    cudaGetSymbolAddress((void**)&a56,  g_a56);
    cudaGetSymbolAddress((void**)&wpad, g_wpad);

    const int SZ128_0 = (int)sizeof(SmemP<128, 0>);
    const int SZ128_1 = (int)sizeof(SmemP<128, 1>);
    const int SZ64_1  = (int)sizeof(SmemP<64, 1>);
    cudaFuncSetAttribute(k_mma<128,0>, cudaFuncAttributeMaxDynamicSharedMemorySize, SZ128_0);
    cudaFuncSetAttribute(k_mma<128,1>, cudaFuncAttributeMaxDynamicSharedMemorySize, SZ128_1);
    cudaFuncSetAttribute(k_mma<64,1>,  cudaFuncAttributeMaxDynamicSharedMemorySize, SZ64_1);

    k_gather<<<NN * DIM / 256, 256>>>(fp, emb);
    k_adjconv<<<(size_t)NN * NN / 2048, 256>>>(adj);
    k_padw<<<DIM * ODP / 256, 256>>>(Woa);

    // 3 message-passing layers
    for (int l = 0; l < 3; l++) {
        k_gemm<128><<<NN / 64, 256>>>(x, DIM, DIM, Wfp + l * DIM * DIM,
                                      bfp + l * DIM, h, 1.f, 1, 1, 0);
        k_mma<128, 0><<<NN / 64, 256, SZ128_0>>>(h, tb, 0);
        k_l2norm<<<NN / 8, 256>>>(tb, x);
    }

    // 2 GAT heads
    for (int hd = 0; hd < 2; hd++) {
        k_gemm<128><<<NN / 64, 256>>>(x, DIM, DIM, Wh + hd * DIM * DIM,
                                      nullptr, h, 1.f, 0, 1, 1);
        k_s12<<<NN / 8, 256>>>(h, DIM, DIM, ah + hd * 2 * DIM);
        k_prep<<<NN / 256, 256>>>();
        k_colmean1<128><<<64, 128>>>(h);
        k_colmean2<<<1, 128>>>(128);
        k_mma<128, 1><<<NN / 64, 256, SZ128_1>>>(nullptr, z, hd);
    }

    // out-attention at D=56 (padded to 64); x = z/2 folded into scale
    k_gemm<64><<<NN / 64, 256>>>(z, DIM, DIM, wpad, nullptr, ho, 0.5f, 0, 1, 1);
    k_s12<<<NN / 8, 256>>>(ho, ODP, OD, aoa);
    k_prep<<<NN / 256, 256>>>();
    k_colmean1<64><<<64, 64>>>(ho);
    k_colmean2<<<1, 128>>>(64);
    k_mma<64, 1><<<NN / 64, 256, SZ64_1>>>(nullptr, a56, 0);

    k_smax56<<<NN / 8, 256>>>(a56);
    k_head<<<NMOL, 64>>>(seg, Wout, bout, Wpr, bpr, out);
}

// round 7
// speedup vs baseline: 4.0003x; 1.1110x over previous
#include <cuda_runtime.h>
#include <cuda.h>
#include <cuda_bf16.h>
#include <math.h>

#define NN   8192
#define DIM  128
#define NMOL 256
#define OD   56
#define ODP  64

typedef unsigned long long u64;
typedef unsigned int u32;

// ---------------- f32x2 helpers ----------------------------------------------
__device__ __forceinline__ u64 pk2(float lo, float hi) {
    u64 r; asm("mov.b64 %0, {%1,%2};" : "=l"(r) : "f"(lo), "f"(hi)); return r;
}
__device__ __forceinline__ void upk2(u64 v, float &lo, float &hi) {
    asm("mov.b64 {%0,%1}, %2;" : "=f"(lo), "=f"(hi) : "l"(v));
}
__device__ __forceinline__ void fma2(u64 &d, u64 a, u64 b) {
    asm("fma.rn.f32x2 %0, %1, %2, %0;" : "+l"(d) : "l"(a), "l"(b));
}

// ---------------- FMA-only exp ------------------------------------------------
__device__ __forceinline__ float fexp(float x) {
    x = fmaxf(x, -87.0f);
    float y = x * 1.44269504f;
    float r = rintf(y);
    float f = y - r;
    float p = 1.33335581e-3f;
    p = fmaf(p, f, 9.61812911e-3f);
    p = fmaf(p, f, 5.55041087e-2f);
    p = fmaf(p, f, 2.40226507e-1f);
    p = fmaf(p, f, 6.93147181e-1f);
    p = fmaf(p, f, 1.0f);
    int e = (int)r;
    return p * __int_as_float((e + 127) << 23);
}

__device__ __forceinline__ u32 encf(float s) {
    u32 b = __float_as_uint(s);
    return (b & 0x80000000u) ? ~b : (b | 0x80000000u);
}
__device__ __forceinline__ float decf(u32 u) {
    return __uint_as_float((u & 0x80000000u) ? (u & 0x7fffffffu) : ~u);
}

// ---------------- MMA / ldmatrix helpers --------------------------------------
__device__ __forceinline__ u32 smem_u32(const void* p) {
    return (u32)__cvta_generic_to_shared(p);
}
__device__ __forceinline__ void ldm_x4(u32 a, u32* r) {
    asm volatile("ldmatrix.sync.aligned.m8n8.x4.shared.b16 {%0,%1,%2,%3}, [%4];"
        : "=r"(r[0]), "=r"(r[1]), "=r"(r[2]), "=r"(r[3]) : "r"(a));
}
__device__ __forceinline__ void ldm_x4t(u32 a, u32* r) {
    asm volatile("ldmatrix.sync.aligned.m8n8.x4.trans.shared.b16 {%0,%1,%2,%3}, [%4];"
        : "=r"(r[0]), "=r"(r[1]), "=r"(r[2]), "=r"(r[3]) : "r"(a));
}
__device__ __forceinline__ void mma_bf16(float* c, const u32* a, const u32* b) {
    asm volatile(
        "mma.sync.aligned.m16n8k16.row.col.f32.bf16.bf16.f32 "
        "{%0,%1,%2,%3}, {%4,%5,%6,%7}, {%8,%9}, {%0,%1,%2,%3};"
        : "+f"(c[0]), "+f"(c[1]), "+f"(c[2]), "+f"(c[3])
        : "r"(a[0]), "r"(a[1]), "r"(a[2]), "r"(a[3]), "r"(b[0]), "r"(b[1]));
}

// ---------------- TMA / mbarrier (base-target sm_90+ features) ----------------
__device__ __forceinline__ void tma2d(u32 dst, const void* map, int x, int y, u32 mbar) {
    asm volatile(
        "cp.async.bulk.tensor.2d.shared::cta.global.tile.mbarrier::complete_tx::bytes "
        "[%0], [%1, {%2, %3}], [%4];"
        :: "r"(dst), "l"(map), "r"(x), "r"(y), "r"(mbar) : "memory");
}
__device__ __forceinline__ void mbar_init(u32 a, u32 cnt) {
    asm volatile("mbarrier.init.shared.b64 [%0], %1;" :: "r"(a), "r"(cnt) : "memory");
}
__device__ __forceinline__ void mbar_expect(u32 a, u32 bytes) {
    asm volatile("mbarrier.arrive.expect_tx.shared.b64 _, [%0], %1;"
                 :: "r"(a), "r"(bytes) : "memory");
}
__device__ __forceinline__ void mbar_wait(u32 a, u32 parity) {
    asm volatile(
        "{\n\t.reg .pred P;\n\t"
        "W_%=:\n\t"
        "mbarrier.try_wait.parity.acquire.cta.shared::cta.b64 P, [%0], %1, 0x989680;\n\t"
        "@P bra.uni D_%=;\n\t"
        "bra.uni W_%=;\n\t"
        "D_%=:\n\t}"
        :: "r"(a), "r"(parity) : "memory");
}
__device__ __forceinline__ void mbar_inval(u32 a) {
    asm volatile("mbarrier.inval.shared.b64 [%0];" :: "r"(a) : "memory");
}
// standard 128B swizzle: XOR bits [4:7) with bits [7:10)
__device__ __forceinline__ u32 swz(u32 o) { return o ^ ((o >> 3) & 0x70); }

// ---------------- scratch -----------------------------------------------------
__device__ __nv_bfloat16 g_adjb[(size_t)NN * NN];   // 128 MB, exact 0/1
__device__ __nv_bfloat16 g_hh[NN * DIM];
__device__ float g_x [NN * DIM];
__device__ float g_h [NN * DIM];
__device__ float g_t [NN * DIM];
__device__ float g_z [NN * DIM];
__device__ float g_s1[NN];
__device__ float g_s2[NN];
__device__ u32   g_s2maxu;
__device__ float g_pa[NN], g_pb[NN], g_pth[NN], g_peg[NN], g_peq[NN];
__device__ float g_ho [NN * ODP];
__device__ float g_a56[NN * ODP];
__device__ float g_wpad[DIM * ODP];
__device__ float g_cm[DIM];
__device__ float g_cmp[64 * DIM];

// ---------------- small utility kernels ---------------------------------------
__global__ void k_gather(const int* __restrict__ fp, const float* __restrict__ emb) {
    int idx = blockIdx.x * 256 + threadIdx.x;
    int i = idx >> 7, c = idx & 127;
    g_x[idx] = emb[fp[i] * DIM + c];
}

__global__ void k_padw(const float* __restrict__ W) {
    int idx = blockIdx.x * 256 + threadIdx.x;
    int k = idx >> 6, c = idx & 63;
    g_wpad[idx] = (c < OD) ? W[k * OD + c] : 0.0f;
}

__global__ void k_adjconv(const float* __restrict__ adj) {
    size_t base = ((size_t)blockIdx.x * 256 + threadIdx.x) * 8;
    float4 a = *(const float4*)(adj + base);
    float4 b = *(const float4*)(adj + base + 4);
    __nv_bfloat16 o[8];
    o[0]=__float2bfloat16(a.x); o[1]=__float2bfloat16(a.y);
    o[2]=__float2bfloat16(a.z); o[3]=__float2bfloat16(a.w);
    o[4]=__float2bfloat16(b.x); o[5]=__float2bfloat16(b.y);
    o[6]=__float2bfloat16(b.z); o[7]=__float2bfloat16(b.w);
    *(uint4*)(g_adjb + base) = *(uint4*)o;
}

// ---------------- row L2-normalize --------------------------------------------
__global__ void k_l2norm(const float* __restrict__ in, float* __restrict__ out) {
    int w = threadIdx.x >> 5, lane = threadIdx.x & 31;
    int row = blockIdx.x * 8 + w;
    const float* r = in + (size_t)row * DIM;
    float v[4], ss = 0.f;
#pragma unroll
    for (int q = 0; q < 4; q++) { v[q] = r[lane + q * 32]; ss += v[q] * v[q]; }
#pragma unroll
    for (int o = 16; o > 0; o >>= 1) ss += __shfl_xor_sync(0xffffffffu, ss, o);
    float inv = 1.0f / fmaxf(sqrtf(ss), 1e-12f);
#pragma unroll
    for (int q = 0; q < 4; q++) out[(size_t)row * DIM + lane + q * 32] = v[q] * inv;
}

// ---------------- s1/s2 projections + global s2 max ---------------------------
__global__ void k_s12(const float* __restrict__ H, int ld, int Dr,
                      const float* __restrict__ a) {
    int w = threadIdx.x >> 5, lane = threadIdx.x & 31;
    int row = blockIdx.x * 8 + w;
    const float* r = H + (size_t)row * ld;
    float p1 = 0.f, p2 = 0.f;
    for (int c = lane; c < Dr; c += 32) {
        float v = r[c];
        p1 = fmaf(v, a[c], p1);
        p2 = fmaf(v, a[Dr + c], p2);
    }
#pragma unroll
    for (int o = 16; o > 0; o >>= 1) {
        p1 += __shfl_xor_sync(0xffffffffu, p1, o);
        p2 += __shfl_xor_sync(0xffffffffu, p2, o);
    }
    if (lane == 0) {
        g_s1[row] = p1; g_s2[row] = p2;
        atomicMax(&g_s2maxu, encf(p2));
    }
}

// ---------------- per-node attention precompute -------------------------------
__global__ void k_prep() {
    int i = blockIdx.x * 256 + threadIdx.x;
    float gmax = decf(g_s2maxu);
    float s1 = g_s1[i], s2 = g_s2[i];
    float u = s1 + gmax;
    float m = (u > 0.f) ? u : 0.25f * u;
    g_pa[i] = fexp(s1 - m);
    g_pb[i] = fexp(0.25f * s1 - m);
    g_pth[i] = -s1;
    g_peg[i] = fexp(s2);
    g_peq[i] = fexp(0.25f * s2);
}

// ---------------- column mean (deterministic 2-stage) -------------------------
template<int BN>
__global__ void k_colmean1(const float* __restrict__ H) {
    int t = threadIdx.x;
    int r0 = blockIdx.x * 128;
    float s = 0.f;
    for (int r = 0; r < 128; r++) s += H[(size_t)(r0 + r) * BN + t];
    g_cmp[blockIdx.x * DIM + t] = s;
}
__global__ void k_colmean2(int BN) {
    int t = threadIdx.x;
    float s = 0.f;
    if (t < BN) for (int b = 0; b < 64; b++) s += g_cmp[b * DIM + t];
    g_cm[t] = s * (1.0f / NN);
}

// ================== TMA-fed mma.sync kernel ===================================
// NB = BN/64 H-blocks of 64 cols. Tiles: Adj[64r][64k] + H[64k][64n]*NB,
// all SW128 (128-byte rows), 1024-aligned in dynamic smem.
// MODE 0: Out = resid + adj @ H
// MODE 1: P_ij = adj_ij*(s2_j>=th_i ? a_i*eg_j : b_i*eq_j) bf16;
//         Out_i = elu(P@H / d_i) (d_i==0 -> colmean), opt accumulate.
#define TNST 4
struct TAux {
    __nv_bfloat16 Phi[64][72];
    float A[64], B[64], Th[64], D[64];
    u64 bar[TNST];
};

template<int NB, int MODE>
__global__ void __launch_bounds__(256) k_tmma(
    const __grid_constant__ CUtensorMap mAdj,
    const __grid_constant__ CUtensorMap mH,
    const float* __restrict__ resid,
    float* __restrict__ Out, int accum)
{
    constexpr int BN = NB * 64, BK = 64, NT = NN / BK;
    constexpr int NWN = BN / 32, NWM = 8 / NWN;
    constexpr int WM = 64 / NWM, FM = WM / 16, FN = 4;
    constexpr u32 STAGE_B = (1 + NB) * 8192;

    extern __shared__ char raw[];
    TAux& X = *reinterpret_cast<TAux*>(raw);
    const u32 tiles_u = (smem_u32(raw) + (u32)sizeof(TAux) + 1023u) & ~1023u;
    char* tiles_p = raw + (tiles_u - smem_u32(raw));

    const int t = threadIdx.x, lane = t & 31, warp = t >> 5;
    const int i0 = blockIdx.x * 64;
    const int wm = warp / NWN, wn = warp % NWN;
    const int pr = warp * 8 + (lane >> 2);
    const int pc = (lane & 3) * 16;

    if (MODE && t < 64) {
        X.A[t] = g_pa[i0 + t]; X.B[t] = g_pb[i0 + t]; X.Th[t] = g_pth[i0 + t];
    }
    if (t == 0)
        for (int s = 0; s < TNST; s++) mbar_init(smem_u32(&X.bar[s]), 1);
    __syncthreads();
    float ai = 0.f, bi = 0.f, thi = 0.f;
    if (MODE) { ai = X.A[pr]; bi = X.B[pr]; thi = X.Th[pr]; }

    if (t == 0) {
#pragma unroll
        for (int s = 0; s < 3; s++) {
            u32 bar = smem_u32(&X.bar[s]);
            mbar_expect(bar, STAGE_B);
            u32 st = tiles_u + s * STAGE_B;
            tma2d(st, &mAdj, s * 64, i0, bar);
#pragma unroll
            for (int b = 0; b < NB; b++)
                tma2d(st + 8192 + b * 8192, &mH, b * 64, s * 64, bar);
        }
    }

    float acc[FM][FN][4];
#pragma unroll
    for (int a = 0; a < FM; a++)
#pragma unroll
        for (int b = 0; b < FN; b++)
#pragma unroll
            for (int c = 0; c < 4; c++) acc[a][b][c] = 0.f;
    float dpart = 0.f;

    for (int kt = 0; kt < NT; kt++) {
        const int cur = kt & 3, k0 = kt * BK;
        const u32 stg = tiles_u + cur * STAGE_B;
        mbar_wait(smem_u32(&X.bar[cur]), (kt >> 2) & 1);

        const char* adjp = tiles_p + cur * STAGE_B;
        if (MODE) {
            u32 off = (u32)pr * 128 + (u32)pc * 2;
            uint4 av0 = *(const uint4*)(adjp + swz(off));
            uint4 av1 = *(const uint4*)(adjp + swz(off + 16));
            unsigned short ab[16];
            *(uint4*)ab = av0; *(uint4*)(ab + 8) = av1;
            __align__(16) __nv_bfloat16 ph[16];
            const float* s2 = g_s2  + k0 + pc;
            const float* eg = g_peg + k0 + pc;
            const float* eq = g_peq + k0 + pc;
#pragma unroll
            for (int c = 0; c < 16; c++) {
                float p = 0.f;
                if (ab[c]) p = (s2[c] >= thi) ? ai * eg[c] : bi * eq[c];
                __nv_bfloat16 hb = __float2bfloat16(p);
                ph[c] = hb;
                dpart += __bfloat162float(hb);
            }
            *(uint4*)&X.Phi[pr][pc]     = *(uint4*)ph;
            *(uint4*)&X.Phi[pr][pc + 8] = *(uint4*)(ph + 8);
            __syncthreads();
        }

#pragma unroll
        for (int kk = 0; kk < 4; kk++) {
            u32 ah[FM][4];
#pragma unroll
            for (int fm = 0; fm < FM; fm++) {
                int rr = wm * WM + fm * 16 + (lane & 15);
                int cc = kk * 16 + (lane >> 4) * 8;
                u32 a = MODE ? smem_u32(&X.Phi[rr][cc])
                             : stg + swz((u32)rr * 128 + (u32)cc * 2);
                ldm_x4(a, ah[fm]);
            }
            u32 bh[4][2];
#pragma unroll
            for (int fp2 = 0; fp2 < 2; fp2++) {
                int rr = kk * 16 + (lane & 15);
                int cc = wn * 32 + fp2 * 16 + (lane >> 4) * 8;
                u32 a = stg + 8192 + (u32)(cc >> 6) * 8192
                      + swz((u32)rr * 128 + (u32)(cc & 63) * 2);
                u32 r4[4];
                ldm_x4t(a, r4);
                bh[2*fp2][0] = r4[0]; bh[2*fp2][1] = r4[1];
                bh[2*fp2+1][0] = r4[2]; bh[2*fp2+1][1] = r4[3];
            }
#pragma unroll
            for (int fm = 0; fm < FM; fm++)
#pragma unroll
                for (int fn = 0; fn < FN; fn++)
                    mma_bf16(acc[fm][fn], ah[fm], bh[fn]);
        }
        __syncthreads();   // all reads of buffer (kt-1)%4 and cur done

        if (t == 0 && kt + 3 < NT) {
            const int s = (kt + 3) & 3;
            u32 bar = smem_u32(&X.bar[s]);
            mbar_expect(bar, STAGE_B);
            u32 st = tiles_u + s * STAGE_B;
            tma2d(st, &mAdj, (kt + 3) * 64, i0, bar);
#pragma unroll
            for (int b = 0; b < NB; b++)
                tma2d(st + 8192 + b * 8192, &mH, b * 64, (kt + 3) * 64, bar);
        }
    }

    if (MODE) {
        dpart += __shfl_xor_sync(0xffffffffu, dpart, 1);
        dpart += __shfl_xor_sync(0xffffffffu, dpart, 2);
        if ((lane & 3) == 0) X.D[pr] = dpart;
    }
    __syncthreads();

#pragma unroll
    for (int fm = 0; fm < FM; fm++) {
#pragma unroll
        for (int h = 0; h < 2; h++) {
            int rl = wm * WM + fm * 16 + (lane >> 2) + h * 8;
            int row = i0 + rl;
#pragma unroll
            for (int fn = 0; fn < FN; fn++) {
                int col = wn * 32 + fn * 8 + (lane & 3) * 2;
                float v0 = acc[fm][fn][2 * h], v1 = acc[fm][fn][2 * h + 1];
                float* op = Out + (size_t)row * BN + col;
                if (MODE == 0) {
                    float2 rr = *(const float2*)(resid + (size_t)row * BN + col);
                    float2 o; o.x = v0 + rr.x; o.y = v1 + rr.y;
                    *(float2*)op = o;
                } else {
                    float dd = X.D[rl];
                    if (dd > 0.f) { float inv = 1.0f / dd; v0 *= inv; v1 *= inv; }
                    else          { v0 = g_cm[col]; v1 = g_cm[col + 1]; }
                    v0 = (v0 > 0.f) ? v0 : fexp(v0) - 1.0f;
                    v1 = (v1 > 0.f) ? v1 : fexp(v1) - 1.0f;
                    if (accum) {
                        float2 zz = *(const float2*)op;
                        v0 += zz.x; v1 += zz.y;
                    }
                    float2 o; o.x = v0; o.y = v1;
                    *(float2*)op = o;
                }
            }
        }
    }
    __syncthreads();
    if (t == 0)
        for (int s = 0; s < TNST; s++) mbar_inval(smem_u32(&X.bar[s]));
}

// ---------------- small dense GEMM (f32x2) + fused bf16 round -----------------
template<int BN>
__global__ void __launch_bounds__(256) k_gemm(
        const float* __restrict__ A, int lda, int K,
        const float* __restrict__ B,
        const float* __restrict__ bias,
        float* __restrict__ C, float scale, int relu, int split, int rst)
{
    constexpr int BM = 64, BK = 32, TM = 4, TN = BN / 16;
    __shared__ float As[BK][BM + 4];
    __shared__ float Bs[BK][BN];
    const int t  = threadIdx.x;
    const int tx = t & 15, ty = t >> 4;
    const int row0 = blockIdx.x * BM;

    if (rst && blockIdx.x == 0 && t == 0) g_s2maxu = 0u;

    u64 acc[TM][TN / 2];
#pragma unroll
    for (int i = 0; i < TM; i++)
#pragma unroll
        for (int j = 0; j < TN / 2; j++) acc[i][j] = 0ULL;

    for (int k0 = 0; k0 < K; k0 += BK) {
#pragma unroll
        for (int l = 0; l < (BM * BK) / 256; l++) {
            int idx = t + l * 256;
            int m = idx >> 5, k = idx & 31;
            As[k][m] = A[(size_t)(row0 + m) * lda + k0 + k];
        }
#pragma unroll
        for (int l = 0; l < (BK * BN) / 256; l++) {
            int idx = t + l * 256;
            int k = idx / BN, c = idx % BN;
            Bs[k][c] = B[(size_t)(k0 + k) * BN + c];
        }
        __syncthreads();
#pragma unroll
        for (int kk = 0; kk < BK; kk++) {
            float4 a4 = *(const float4*)&As[kk][ty * TM];
            u64 ap[4] = { pk2(a4.x, a4.x), pk2(a4.y, a4.y),
                          pk2(a4.z, a4.z), pk2(a4.w, a4.w) };
            const u64* bp = (const u64*)&Bs[kk][tx * TN];
            u64 b[TN / 2];
#pragma unroll
            for (int j = 0; j < TN / 2; j++) b[j] = bp[j];
#pragma unroll
            for (int i = 0; i < TM; i++)
#pragma unroll
                for (int j = 0; j < TN / 2; j++) fma2(acc[i][j], ap[i], b[j]);
        }
        __syncthreads();
    }
#pragma unroll
    for (int i = 0; i < TM; i++) {
        int m = row0 + ty * TM + i;
#pragma unroll
        for (int j = 0; j < TN / 2; j++) {
            int c = tx * TN + 2 * j;
            float lo, hi; upk2(acc[i][j], lo, hi);
            float v0 = scale * lo, v1 = scale * hi;
            if (bias)  { v0 += bias[c]; v1 += bias[c + 1]; }
            if (relu)  { v0 = fmaxf(v0, 0.f); v1 = fmaxf(v1, 0.f); }
            float2 o; o.x = v0; o.y = v1;
            *(float2*)&C[(size_t)m * BN + c] = o;
            if (split) {
                __nv_bfloat162 hh;
                hh.x = __float2bfloat16(v0);
                hh.y = __float2bfloat16(v1);
                *(__nv_bfloat162*)&g_hh[(size_t)m * BN + c] = hh;
            }
        }
    }
}

// ---------------- row softmax over first 56 of 64 cols ------------------------
__global__ void k_smax56(float* __restrict__ X) {
    int w = threadIdx.x >> 5, lane = threadIdx.x & 31;
    int row = blockIdx.x * 8 + w;
    float* r = X + (size_t)row * ODP;
    float v0 = (lane < OD)      ? r[lane]      : -3e38f;
    float v1 = (lane + 32 < OD) ? r[lane + 32] : -3e38f;
    float m = fmaxf(v0, v1);
#pragma unroll
    for (int o = 16; o > 0; o >>= 1) m = fmaxf(m, __shfl_xor_sync(0xffffffffu, m, o));
    float e0 = (lane < OD)      ? fexp(v0 - m) : 0.f;
    float e1 = (lane + 32 < OD) ? fexp(v1 - m) : 0.f;
    float s = e0 + e1;
#pragma unroll
    for (int o = 16; o > 0; o >>= 1) s += __shfl_xor_sync(0xffffffffu, s, o);
    float inv = 1.0f / s;
    if (lane < OD)      r[lane]      = e0 * inv;
    if (lane + 32 < OD) r[lane + 32] = e1 * inv;
}

// ---------------- segment-sum readout + MLP head ------------------------------
__global__ void k_head(const int* __restrict__ seg,
                       const float* __restrict__ Wout, const float* __restrict__ bout,
                       const float* __restrict__ Wprop, const float* __restrict__ bprop,
                       float* __restrict__ out)
{
    __shared__ float v[OD];
    __shared__ float o[OD];
    __shared__ int bnd[2];
    const int m = blockIdx.x, t = threadIdx.x;
    if (t < 2) {
        int target = m + t;
        int lo = 0, hi = NN;
        while (lo < hi) { int mid = (lo + hi) >> 1; if (seg[mid] < target) lo = mid + 1; else hi = mid; }
        bnd[t] = lo;
    }
    __syncthreads();
    int lo = bnd[0], hi = bnd[1];
    if (t < OD) {
        float s = 0.f;
        for (int i = lo; i < hi; i++) s += g_a56[(size_t)i * ODP + t];
        v[t] = s;
    }
    __syncthreads();
    for (int l = 0; l < 2; l++) {
        if (t < OD) {
            float s = bout[l * OD + t];
            const float* W = Wout + l * OD * OD;
            for (int k = 0; k < OD; k++) s = fmaf(v[k], W[k * OD + t], s);
            o[t] = fmaxf(s, 0.f);
        }
        __syncthreads();
        if (t < OD) v[t] = o[t];
        __syncthreads();
    }
    if (t < 2) {
        float s = bprop[t];
        for (int k = 0; k < OD; k++) s = fmaf(v[k], Wprop[k * 2 + t], s);
        float r;
        if (s >= 0.f) r = 1.0f / (1.0f + fexp(-s));
        else { float e = fexp(s); r = e / (1.0f + e); }
        out[m * 2 + t] = r;
    }
}

// ---------------- orchestration ----------------------------------------------
typedef CUresult (*tmap_fn_t)(CUtensorMap*, CUtensorMapDataType, cuuint32_t, void*,
                              const cuuint64_t*, const cuuint64_t*, const cuuint32_t*,
                              const cuuint32_t*, CUtensorMapInterleave, CUtensorMapSwizzle,
                              CUtensorMapL2promotion, CUtensorMapFloatOOBfill);

static void make_tmap(tmap_fn_t fn, CUtensorMap* m, void* base,
                      unsigned long long d0, unsigned long long d1) {
    cuuint64_t dims[2] = { d0, d1 };
    cuuint64_t strides[1] = { d0 * 2 };       // bf16
    cuuint32_t box[2] = { 64, 64 };
    cuuint32_t es[2] = { 1, 1 };
    fn(m, CU_TENSOR_MAP_DATA_TYPE_BFLOAT16, 2, base, dims, strides, box, es,
       CU_TENSOR_MAP_INTERLEAVE_NONE, CU_TENSOR_MAP_SWIZZLE_128B,
       CU_TENSOR_MAP_L2_PROMOTION_L2_128B, CU_TENSOR_MAP_FLOAT_OOB_FILL_NONE);
}

extern "C" void kernel_launch(void* const* d_in, const int* in_sizes, int n_in,
                              void* d_out, int out_size) {
    const int*   fp   = (const int*)  d_in[0];
    const float* adj  = (const float*)d_in[1];
    const int*   seg  = (const int*)  d_in[2];
    const float* emb  = (const float*)d_in[3];
    const float* Wfp  = (const float*)d_in[4];
    const float* bfp  = (const float*)d_in[5];
    const float* Wh   = (const float*)d_in[6];
    const float* ah   = (const float*)d_in[7];
    const float* Woa  = (const float*)d_in[8];
    const float* aoa  = (const float*)d_in[9];
    const float* Wout = (const float*)d_in[10];
    const float* bout = (const float*)d_in[11];
    const float* Wpr  = (const float*)d_in[12];
    const float* bpr  = (const float*)d_in[13];
    float* out = (float*)d_out;

    float *x, *h, *tb, *z, *ho, *a56, *wpad;
    void *adjb_p, *hh_p;
    cudaGetSymbolAddress((void**)&x,    g_x);
    cudaGetSymbolAddress((void**)&h,    g_h);
    cudaGetSymbolAddress((void**)&tb,   g_t);
    cudaGetSymbolAddress((void**)&z,    g_z);
    cudaGetSymbolAddress((void**)&ho,   g_ho);
    cudaGetSymbolAddress((void**)&a56,  g_a56);
    cudaGetSymbolAddress((void**)&wpad, g_wpad);
    cudaGetSymbolAddress(&adjb_p, g_adjb);
    cudaGetSymbolAddress(&hh_p,   g_hh);

    tmap_fn_t tmap_fn = nullptr;
    cudaDriverEntryPointQueryResult qr;
    cudaGetDriverEntryPointByVersion("cuTensorMapEncodeTiled", (void**)&tmap_fn,
                                     12000, cudaEnableDefault, &qr);
    static CUtensorMap mapAdj, mapH128, mapH64;
    make_tmap(tmap_fn, &mapAdj, adjb_p, NN, NN);
    make_tmap(tmap_fn, &mapH128, hh_p, DIM, NN);
    make_tmap(tmap_fn, &mapH64,  hh_p, 64,  NN);

    const int SZ2 = (int)sizeof(TAux) + 1024 + TNST * 3 * 8192;  // NB=2
    const int SZ1 = (int)sizeof(TAux) + 1024 + TNST * 2 * 8192;  // NB=1
    cudaFuncSetAttribute(k_tmma<2,0>, cudaFuncAttributeMaxDynamicSharedMemorySize, SZ2);
    cudaFuncSetAttribute(k_tmma<2,1>, cudaFuncAttributeMaxDynamicSharedMemorySize, SZ2);
    cudaFuncSetAttribute(k_tmma<1,1>, cudaFuncAttributeMaxDynamicSharedMemorySize, SZ1);

    k_gather<<<NN * DIM / 256, 256>>>(fp, emb);
    k_adjconv<<<(size_t)NN * NN / 2048, 256>>>(adj);
    k_padw<<<DIM * ODP / 256, 256>>>(Woa);

    // 3 message-passing layers
    for (int l = 0; l < 3; l++) {
        k_gemm<128><<<NN / 64, 256>>>(x, DIM, DIM, Wfp + l * DIM * DIM,
                                      bfp + l * DIM, h, 1.f, 1, 1, 0);
        k_tmma<2,0><<<NN / 64, 256, SZ2>>>(mapAdj, mapH128, h, tb, 0);
        k_l2norm<<<NN / 8, 256>>>(tb, x);
    }

    // 2 GAT heads
    for (int hd = 0; hd < 2; hd++) {
        k_gemm<128><<<NN / 64, 256>>>(x, DIM, DIM, Wh + hd * DIM * DIM,
                                      nullptr, h, 1.f, 0, 1, 1);
        k_s12<<<NN / 8, 256>>>(h, DIM, DIM, ah + hd * 2 * DIM);
        k_prep<<<NN / 256, 256>>>();
        k_colmean1<128><<<64, 128>>>(h);
        k_colmean2<<<1, 128>>>(128);
        k_tmma<2,1><<<NN / 64, 256, SZ2>>>(mapAdj, mapH128, nullptr, z, hd);
    }

    // out-attention at D=56 (padded to 64); x = z/2 folded into scale
    k_gemm<64><<<NN / 64, 256>>>(z, DIM, DIM, wpad, nullptr, ho, 0.5f, 0, 1, 1);
    k_s12<<<NN / 8, 256>>>(ho, ODP, OD, aoa);
    k_prep<<<NN / 256, 256>>>();
    k_colmean1<64><<<64, 64>>>(ho);
    k_colmean2<<<1, 128>>>(64);
    k_tmma<1,1><<<NN / 64, 256, SZ1>>>(mapAdj, mapH64, nullptr, a56, 0);

    k_smax56<<<NN / 8, 256>>>(a56);
    k_head<<<NMOL, 64>>>(seg, Wout, bout, Wpr, bpr, out);
}

// round 8
// speedup vs baseline: 4.2223x; 1.0555x over previous
#include <cuda_runtime.h>
#include <cuda.h>
#include <cuda_bf16.h>
#include <cuda_fp16.h>
#include <cuda_fp8.h>
#include <math.h>

#define NN   8192
#define DIM  128
#define NMOL 256
#define OD   56
#define ODP  64

typedef unsigned long long u64;
typedef unsigned int u32;
typedef unsigned short u16;
typedef unsigned char u8;

// ---------------- f32x2 helpers ----------------------------------------------
__device__ __forceinline__ u64 pk2(float lo, float hi) {
    u64 r; asm("mov.b64 %0, {%1,%2};" : "=l"(r) : "f"(lo), "f"(hi)); return r;
}
__device__ __forceinline__ void upk2(u64 v, float &lo, float &hi) {
    asm("mov.b64 {%0,%1}, %2;" : "=f"(lo), "=f"(hi) : "l"(v));
}
__device__ __forceinline__ void fma2(u64 &d, u64 a, u64 b) {
    asm("fma.rn.f32x2 %0, %1, %2, %0;" : "+l"(d) : "l"(a), "l"(b));
}

// ---------------- FMA-only exp ------------------------------------------------
__device__ __forceinline__ float fexp(float x) {
    x = fmaxf(x, -87.0f);
    float y = x * 1.44269504f;
    float r = rintf(y);
    float f = y - r;
    float p = 1.33335581e-3f;
    p = fmaf(p, f, 9.61812911e-3f);
    p = fmaf(p, f, 5.55041087e-2f);
    p = fmaf(p, f, 2.40226507e-1f);
    p = fmaf(p, f, 6.93147181e-1f);
    p = fmaf(p, f, 1.0f);
    int e = (int)r;
    return p * __int_as_float((e + 127) << 23);
}

__device__ __forceinline__ u32 encf(float s) {
    u32 b = __float_as_uint(s);
    return (b & 0x80000000u) ? ~b : (b | 0x80000000u);
}
__device__ __forceinline__ float decf(u32 u) {
    return __uint_as_float((u & 0x80000000u) ? (u & 0x7fffffffu) : ~u);
}

// ---------------- MMA / ldmatrix helpers --------------------------------------
__device__ __forceinline__ u32 smem_u32(const void* p) {
    return (u32)__cvta_generic_to_shared(p);
}
__device__ __forceinline__ void ldm_x4(u32 a, u32* r) {
    asm volatile("ldmatrix.sync.aligned.m8n8.x4.shared.b16 {%0,%1,%2,%3}, [%4];"
        : "=r"(r[0]), "=r"(r[1]), "=r"(r[2]), "=r"(r[3]) : "r"(a));
}
// fp8 e4m3 MMA, K=32 per instruction (sm_89+ base feature)
__device__ __forceinline__ void mma_e4m3(float* c, const u32* a, const u32* b) {
    asm volatile(
        "mma.sync.aligned.m16n8k32.row.col.f32.e4m3.e4m3.f32 "
        "{%0,%1,%2,%3}, {%4,%5,%6,%7}, {%8,%9}, {%0,%1,%2,%3};"
        : "+f"(c[0]), "+f"(c[1]), "+f"(c[2]), "+f"(c[3])
        : "r"(a[0]), "r"(a[1]), "r"(a[2]), "r"(a[3]), "r"(b[0]), "r"(b[1]));
}

// ---------------- TMA / mbarrier (base-target sm_90+ features) ----------------
__device__ __forceinline__ void tma2d(u32 dst, const void* map, int x, int y, u32 mbar) {
    asm volatile(
        "cp.async.bulk.tensor.2d.shared::cta.global.tile.mbarrier::complete_tx::bytes "
        "[%0], [%1, {%2, %3}], [%4];"
        :: "r"(dst), "l"(map), "r"(x), "r"(y), "r"(mbar) : "memory");
}
__device__ __forceinline__ void mbar_init(u32 a, u32 cnt) {
    asm volatile("mbarrier.init.shared.b64 [%0], %1;" :: "r"(a), "r"(cnt) : "memory");
}
__device__ __forceinline__ void mbar_expect(u32 a, u32 bytes) {
    asm volatile("mbarrier.arrive.expect_tx.shared.b64 _, [%0], %1;"
                 :: "r"(a), "r"(bytes) : "memory");
}
__device__ __forceinline__ void mbar_wait(u32 a, u32 parity) {
    asm volatile(
        "{\n\t.reg .pred P;\n\t"
        "W_%=:\n\t"
        "mbarrier.try_wait.parity.acquire.cta.shared::cta.b64 P, [%0], %1, 0x989680;\n\t"
        "@P bra.uni D_%=;\n\t"
        "bra.uni W_%=;\n\t"
        "D_%=:\n\t}"
        :: "r"(a), "r"(parity) : "memory");
}
__device__ __forceinline__ void mbar_inval(u32 a) {
    asm volatile("mbarrier.inval.shared.b64 [%0];" :: "r"(a) : "memory");
}
// standard 128B swizzle: XOR bits [4:7) with bits [7:10)
__device__ __forceinline__ u32 swz(u32 o) { return o ^ ((o >> 3) & 0x70); }

// ---------------- scratch -----------------------------------------------------
__device__ u8 g_adj8[(size_t)NN * NN];    // 64 MB, exact 0/1 in e4m3
__device__ u8 g_h8T[(size_t)DIM * NN];    // H^T fp8, k-major rows per feature
__device__ float g_x [NN * DIM];
__device__ float g_h [NN * DIM];
__device__ float g_t [NN * DIM];
__device__ float g_z [NN * DIM];
__device__ float g_s1[NN];
__device__ float g_s2[NN];
__device__ u32   g_s2maxu;
__device__ float g_pa[NN], g_pb[NN], g_pth[NN], g_peg[NN], g_peq[NN];
__device__ float g_ho [NN * ODP];
__device__ float g_a56[NN * ODP];
__device__ float g_wpad[DIM * ODP];
__device__ float g_cm[DIM];
__device__ float g_cmp[64 * DIM];

// ---------------- small utility kernels ---------------------------------------
__global__ void k_gather(const int* __restrict__ fp, const float* __restrict__ emb) {
    int idx = blockIdx.x * 256 + threadIdx.x;
    int i = idx >> 7, c = idx & 127;
    g_x[idx] = emb[fp[i] * DIM + c];
}

__global__ void k_padw(const float* __restrict__ W) {
    int idx = blockIdx.x * 256 + threadIdx.x;
    int k = idx >> 6, c = idx & 63;
    g_wpad[idx] = (c < OD) ? W[k * OD + c] : 0.0f;
}

// adj fp32 -> e4m3 bytes (1.0 == 0x38), exact
__global__ void k_adjconv(const float* __restrict__ adj) {
    size_t base = ((size_t)blockIdx.x * 256 + threadIdx.x) * 8;
    float4 a = *(const float4*)(adj + base);
    float4 b = *(const float4*)(adj + base + 4);
    u8 o[8];
    o[0] = a.x != 0.f ? 0x38 : 0; o[1] = a.y != 0.f ? 0x38 : 0;
    o[2] = a.z != 0.f ? 0x38 : 0; o[3] = a.w != 0.f ? 0x38 : 0;
    o[4] = b.x != 0.f ? 0x38 : 0; o[5] = b.y != 0.f ? 0x38 : 0;
    o[6] = b.z != 0.f ? 0x38 : 0; o[7] = b.w != 0.f ? 0x38 : 0;
    *(u64*)(g_adj8 + base) = *(u64*)o;
}

// H [NN][ldf] fp32 -> H^T fp8 [feat][NN]; grid (NN/64, feats/64)
__global__ void __launch_bounds__(256) k_transp8(const float* __restrict__ H, int ldf) {
    __shared__ float S[64][65];
    const int n0 = blockIdx.x * 64, f0 = blockIdx.y * 64;
    const int t = threadIdx.x, r = t >> 2, cb = t & 3;
#pragma unroll
    for (int q = 0; q < 4; q++) {
        float4 v = *(const float4*)&H[(size_t)(n0 + r) * ldf + f0 + cb * 16 + q * 4];
        S[r][cb * 16 + q * 4 + 0] = v.x; S[r][cb * 16 + q * 4 + 1] = v.y;
        S[r][cb * 16 + q * 4 + 2] = v.z; S[r][cb * 16 + q * 4 + 3] = v.w;
    }
    __syncthreads();
    const int f = t >> 2, nb = t & 3;
    u8 o[16];
#pragma unroll
    for (int q = 0; q < 8; q++) {
        float2 fv;
        fv.x = S[nb * 16 + 2 * q][f];
        fv.y = S[nb * 16 + 2 * q + 1][f];
        __nv_fp8x2_storage_t qq = __nv_cvt_float2_to_fp8x2(fv, __NV_SATFINITE, __NV_E4M3);
        *(u16*)(o + 2 * q) = qq;
    }
    *(uint4*)(g_h8T + (size_t)(f0 + f) * NN + n0 + nb * 16) = *(uint4*)o;
}

// ---------------- row L2-normalize --------------------------------------------
__global__ void k_l2norm(const float* __restrict__ in, float* __restrict__ out) {
    int w = threadIdx.x >> 5, lane = threadIdx.x & 31;
    int row = blockIdx.x * 8 + w;
    const float* r = in + (size_t)row * DIM;
    float v[4], ss = 0.f;
#pragma unroll
    for (int q = 0; q < 4; q++) { v[q] = r[lane + q * 32]; ss += v[q] * v[q]; }
#pragma unroll
    for (int o = 16; o > 0; o >>= 1) ss += __shfl_xor_sync(0xffffffffu, ss, o);
    float inv = 1.0f / fmaxf(sqrtf(ss), 1e-12f);
#pragma unroll
    for (int q = 0; q < 4; q++) out[(size_t)row * DIM + lane + q * 32] = v[q] * inv;
}

// ---------------- s1/s2 projections + global s2 max ---------------------------
__global__ void k_s12(const float* __restrict__ H, int ld, int Dr,
                      const float* __restrict__ a) {
    int w = threadIdx.x >> 5, lane = threadIdx.x & 31;
    int row = blockIdx.x * 8 + w;
    const float* r = H + (size_t)row * ld;
    float p1 = 0.f, p2 = 0.f;
    for (int c = lane; c < Dr; c += 32) {
        float v = r[c];
        p1 = fmaf(v, a[c], p1);
        p2 = fmaf(v, a[Dr + c], p2);
    }
#pragma unroll
    for (int o = 16; o > 0; o >>= 1) {
        p1 += __shfl_xor_sync(0xffffffffu, p1, o);
        p2 += __shfl_xor_sync(0xffffffffu, p2, o);
    }
    if (lane == 0) {
        g_s1[row] = p1; g_s2[row] = p2;
        atomicMax(&g_s2maxu, encf(p2));
    }
}

// ---------------- per-node attention precompute -------------------------------
__global__ void k_prep() {
    int i = blockIdx.x * 256 + threadIdx.x;
    float gmax = decf(g_s2maxu);
    float s1 = g_s1[i], s2 = g_s2[i];
    float u = s1 + gmax;
    float m = (u > 0.f) ? u : 0.25f * u;
    g_pa[i] = fexp(s1 - m);
    g_pb[i] = fexp(0.25f * s1 - m);
    g_pth[i] = -s1;
    g_peg[i] = fexp(s2);
    g_peq[i] = fexp(0.25f * s2);
}

// ---------------- column mean (deterministic 2-stage) -------------------------
template<int BN>
__global__ void k_colmean1(const float* __restrict__ H) {
    int t = threadIdx.x;
    int r0 = blockIdx.x * 128;
    float s = 0.f;
    for (int r = 0; r < 128; r++) s += H[(size_t)(r0 + r) * BN + t];
    g_cmp[blockIdx.x * DIM + t] = s;
}
__global__ void k_colmean2(int BN) {
    int t = threadIdx.x;
    float s = 0.f;
    if (t < BN) for (int b = 0; b < 64; b++) s += g_cmp[b * DIM + t];
    g_cm[t] = s * (1.0f / NN);
}

// ================== TMA-fed FP8 mma.sync kernel ===============================
// Chunk = 128 K (fp8). Tiles: Adj[64r][128k] + NB x HT[64n][128k], 128B rows SW128.
// MODE 0: Out = resid + adj @ H
// MODE 1: P_ij = adj_ij*(s2_j>=th_i ? a_i*eg_j : b_i*eq_j) quantized e4m3;
//         Out_i = elu(P@H / d_i) (d_i==0 -> colmean), opt accumulate.
#define TNST 4
struct TAux {
    u8 Phi[64][144];            // MODE1 P tile, fp8, 144B row stride
    float A[64], B[64], Th[64], D[64];
    u64 bar[TNST];
};

template<int NB, int MODE>
__global__ void __launch_bounds__(256) k_tmma(
    const __grid_constant__ CUtensorMap mAdj,
    const __grid_constant__ CUtensorMap mH,
    const float* __restrict__ resid,
    float* __restrict__ Out, int accum)
{
    constexpr int BN = NB * 64, BK = 128, NT = NN / BK;   // 64 chunks
    constexpr int NWN = BN / 32, NWM = 8 / NWN;
    constexpr int WM = 64 / NWM, FM = WM / 16, FN = 4;
    constexpr u32 STAGE_B = (1 + NB) * 8192;

    extern __shared__ char raw[];
    TAux& X = *reinterpret_cast<TAux*>(raw);
    const u32 tiles_u = (smem_u32(raw) + (u32)sizeof(TAux) + 1023u) & ~1023u;
    char* tiles_p = raw + (tiles_u - smem_u32(raw));

    const int t = threadIdx.x, lane = t & 31, warp = t >> 5;
    const int i0 = blockIdx.x * 64;
    const int wm = warp / NWN, wn = warp % NWN;
    const int pr = warp * 8 + (lane >> 2);    // P-gen row
    const int pc = (lane & 3) * 32;           // P-gen byte-col start (32 fp8)

    if (MODE && t < 64) {
        X.A[t] = g_pa[i0 + t]; X.B[t] = g_pb[i0 + t]; X.Th[t] = g_pth[i0 + t];
    }
    if (t == 0)
        for (int s = 0; s < TNST; s++) mbar_init(smem_u32(&X.bar[s]), 1);
    __syncthreads();
    float ai = 0.f, bi = 0.f, thi = 0.f;
    if (MODE) { ai = X.A[pr]; bi = X.B[pr]; thi = X.Th[pr]; }

    if (t == 0) {
#pragma unroll
        for (int s = 0; s < 3; s++) {
            u32 bar = smem_u32(&X.bar[s]);
            mbar_expect(bar, STAGE_B);
            u32 st = tiles_u + s * STAGE_B;
            tma2d(st, &mAdj, s * 128, i0, bar);
#pragma unroll
            for (int b = 0; b < NB; b++)
                tma2d(st + 8192 + b * 8192, &mH, s * 128, b * 64, bar);
        }
    }

    float acc[FM][FN][4];
#pragma unroll
    for (int a = 0; a < FM; a++)
#pragma unroll
        for (int b = 0; b < FN; b++)
#pragma unroll
            for (int c = 0; c < 4; c++) acc[a][b][c] = 0.f;
    float dpart = 0.f;

    for (int kt = 0; kt < NT; kt++) {
        const int cur = kt & 3, k0 = kt * BK;
        const u32 stg = tiles_u + cur * STAGE_B;
        mbar_wait(smem_u32(&X.bar[cur]), (kt >> 2) & 1);

        if (MODE) {
            const char* adjp = tiles_p + cur * STAGE_B;
            u32 off = (u32)pr * 128 + (u32)pc;
            uint4 av0 = *(const uint4*)(adjp + swz(off));
            uint4 av1 = *(const uint4*)(adjp + swz(off + 16));
            u8 ab[32];
            *(uint4*)ab = av0; *(uint4*)(ab + 16) = av1;
            u8 pq[32];
            const float* s2 = g_s2  + k0 + pc;
            const float* eg = g_peg + k0 + pc;
            const float* eq = g_peq + k0 + pc;
#pragma unroll
            for (int c = 0; c < 16; c++) {
                int c0 = 2 * c, c1 = 2 * c + 1;
                float2 fv;
                fv.x = ab[c0] ? ((s2[c0] >= thi) ? ai * eg[c0] : bi * eq[c0]) : 0.f;
                fv.y = ab[c1] ? ((s2[c1] >= thi) ? ai * eg[c1] : bi * eq[c1]) : 0.f;
                __nv_fp8x2_storage_t qq = __nv_cvt_float2_to_fp8x2(fv, __NV_SATFINITE, __NV_E4M3);
                *(u16*)(pq + 2 * c) = qq;
                __half2_raw hr = __nv_cvt_fp8x2_to_halfraw2(qq, __NV_E4M3);
                float2 dv = __half22float2(*(__half2*)&hr);
                dpart += dv.x + dv.y;
            }
            *(uint4*)&X.Phi[pr][pc]      = *(uint4*)pq;
            *(uint4*)&X.Phi[pr][pc + 16] = *(uint4*)(pq + 16);
            __syncthreads();
        }

#pragma unroll
        for (int kk = 0; kk < 4; kk++) {    // 4 x k32 = 128 K per chunk
            u32 ah[FM][4];
#pragma unroll
            for (int fm = 0; fm < FM; fm++) {
                int rr = wm * WM + fm * 16 + (lane & 15);
                u32 boff = (u32)kk * 32 + ((u32)(lane >> 4)) * 16;
                u32 a = MODE ? smem_u32(&X.Phi[rr][0]) + boff
                             : stg + swz((u32)rr * 128 + boff);
                ldm_x4(a, ah[fm]);
            }
            u32 bh[4][2];
#pragma unroll
            for (int fp2 = 0; fp2 < 2; fp2++) {
                int nb = wn * 32 + fp2 * 16;
                u32 rowN = (u32)(nb & 63) + (u32)(lane & 7) + (((u32)lane >> 4) << 3);
                u32 a = stg + 8192 + ((u32)(nb >> 6)) * 8192
                      + swz(rowN * 128 + (u32)kk * 32 + (((u32)lane >> 3) & 1) * 16);
                u32 r4[4];
                ldm_x4(a, r4);
                bh[2*fp2][0] = r4[0]; bh[2*fp2][1] = r4[1];
                bh[2*fp2+1][0] = r4[2]; bh[2*fp2+1][1] = r4[3];
            }
#pragma unroll
            for (int fm = 0; fm < FM; fm++)
#pragma unroll
                for (int fn = 0; fn < FN; fn++)
                    mma_e4m3(acc[fm][fn], ah[fm], bh[fn]);
        }
        __syncthreads();   // all reads of stage cur (and Phi) complete

        if (t == 0 && kt + 3 < NT) {
            const int s = (kt + 3) & 3;
            u32 bar = smem_u32(&X.bar[s]);
            mbar_expect(bar, STAGE_B);
            u32 st = tiles_u + s * STAGE_B;
            tma2d(st, &mAdj, (kt + 3) * 128, i0, bar);
#pragma unroll
            for (int b = 0; b < NB; b++)
                tma2d(st + 8192 + b * 8192, &mH, (kt + 3) * 128, b * 64, bar);
        }
    }

    if (MODE) {
        dpart += __shfl_xor_sync(0xffffffffu, dpart, 1);
        dpart += __shfl_xor_sync(0xffffffffu, dpart, 2);
        if ((lane & 3) == 0) X.D[pr] = dpart;
    }
    __syncthreads();

#pragma unroll
    for (int fm = 0; fm < FM; fm++) {
#pragma unroll
        for (int h = 0; h < 2; h++) {
            int rl = wm * WM + fm * 16 + (lane >> 2) + h * 8;
            int row = i0 + rl;
#pragma unroll
            for (int fn = 0; fn < FN; fn++) {
                int col = wn * 32 + fn * 8 + (lane & 3) * 2;
                float v0 = acc[fm][fn][2 * h], v1 = acc[fm][fn][2 * h + 1];
                float* op = Out + (size_t)row * BN + col;
                if (MODE == 0) {
                    float2 rr = *(const float2*)(resid + (size_t)row * BN + col);
                    float2 o; o.x = v0 + rr.x; o.y = v1 + rr.y;
                    *(float2*)op = o;
                } else {
                    float dd = X.D[rl];
                    if (dd > 0.f) { float inv = 1.0f / dd; v0 *= inv; v1 *= inv; }
                    else          { v0 = g_cm[col]; v1 = g_cm[col + 1]; }
                    v0 = (v0 > 0.f) ? v0 : fexp(v0) - 1.0f;
                    v1 = (v1 > 0.f) ? v1 : fexp(v1) - 1.0f;
                    if (accum) {
                        float2 zz = *(const float2*)op;
                        v0 += zz.x; v1 += zz.y;
                    }
                    float2 o; o.x = v0; o.y = v1;
                    *(float2*)op = o;
                }
            }
        }
    }
    __syncthreads();
    if (t == 0)
        for (int s = 0; s < TNST; s++) mbar_inval(smem_u32(&X.bar[s]));
}

// ---------------- small dense GEMM (f32x2) ------------------------------------
template<int BN>
__global__ void __launch_bounds__(256) k_gemm(
        const float* __restrict__ A, int lda, int K,
        const float* __restrict__ B,
        const float* __restrict__ bias,
        float* __restrict__ C, float scale, int relu, int rst)
{
    constexpr int BM = 64, BK = 32, TM = 4, TN = BN / 16;
    __shared__ float As[BK][BM + 4];
    __shared__ float Bs[BK][BN];
    const int t  = threadIdx.x;
    const int tx = t & 15, ty = t >> 4;
    const int row0 = blockIdx.x * BM;

    if (rst && blockIdx.x == 0 && t == 0) g_s2maxu = 0u;

    u64 acc[TM][TN / 2];
#pragma unroll
    for (int i = 0; i < TM; i++)
#pragma unroll
        for (int j = 0; j < TN / 2; j++) acc[i][j] = 0ULL;

    for (int k0 = 0; k0 < K; k0 += BK) {
#pragma unroll
        for (int l = 0; l < (BM * BK) / 256; l++) {
            int idx = t + l * 256;
            int m = idx >> 5, k = idx & 31;
            As[k][m] = A[(size_t)(row0 + m) * lda + k0 + k];
        }
#pragma unroll
        for (int l = 0; l < (BK * BN) / 256; l++) {
            int idx = t + l * 256;
            int k = idx / BN, c = idx % BN;
            Bs[k][c] = B[(size_t)(k0 + k) * BN + c];
        }
        __syncthreads();
#pragma unroll
        for (int kk = 0; kk < BK; kk++) {
            float4 a4 = *(const float4*)&As[kk][ty * TM];
            u64 ap[4] = { pk2(a4.x, a4.x), pk2(a4.y, a4.y),
                          pk2(a4.z, a4.z), pk2(a4.w, a4.w) };
            const u64* bp = (const u64*)&Bs[kk][tx * TN];
            u64 b[TN / 2];
#pragma unroll
            for (int j = 0; j < TN / 2; j++) b[j] = bp[j];
#pragma unroll
            for (int i = 0; i < TM; i++)
#pragma unroll
                for (int j = 0; j < TN / 2; j++) fma2(acc[i][j], ap[i], b[j]);
        }
        __syncthreads();
    }
#pragma unroll
    for (int i = 0; i < TM; i++) {
        int m = row0 + ty * TM + i;
#pragma unroll
        for (int j = 0; j < TN / 2; j++) {
            int c = tx * TN + 2 * j;
            float lo, hi; upk2(acc[i][j], lo, hi);
            float v0 = scale * lo, v1 = scale * hi;
            if (bias)  { v0 += bias[c]; v1 += bias[c + 1]; }
            if (relu)  { v0 = fmaxf(v0, 0.f); v1 = fmaxf(v1, 0.f); }
            float2 o; o.x = v0; o.y = v1;
            *(float2*)&C[(size_t)m * BN + c] = o;
        }
    }
}

// ---------------- row softmax over first 56 of 64 cols ------------------------
__global__ void k_smax56(float* __restrict__ X) {
    int w = threadIdx.x >> 5, lane = threadIdx.x & 31;
    int row = blockIdx.x * 8 + w;
    float* r = X + (size_t)row * ODP;
    float v0 = (lane < OD)      ? r[lane]      : -3e38f;
    float v1 = (lane + 32 < OD) ? r[lane + 32] : -3e38f;
    float m = fmaxf(v0, v1);
#pragma unroll
    for (int o = 16; o > 0; o >>= 1) m = fmaxf(m, __shfl_xor_sync(0xffffffffu, m, o));
    float e0 = (lane < OD)      ? fexp(v0 - m) : 0.f;
    float e1 = (lane + 32 < OD) ? fexp(v1 - m) : 0.f;
    float s = e0 + e1;
#pragma unroll
    for (int o = 16; o > 0; o >>= 1) s += __shfl_xor_sync(0xffffffffu, s, o);
    float inv = 1.0f / s;
    if (lane < OD)      r[lane]      = e0 * inv;
    if (lane + 32 < OD) r[lane + 32] = e1 * inv;
}

// ---------------- segment-sum readout + MLP head ------------------------------
__global__ void k_head(const int* __restrict__ seg,
                       const float* __restrict__ Wout, const float* __restrict__ bout,
                       const float* __restrict__ Wprop, const float* __restrict__ bprop,
                       float* __restrict__ out)
{
    __shared__ float v[OD];
    __shared__ float o[OD];
    __shared__ int bnd[2];
    const int m = blockIdx.x, t = threadIdx.x;
    if (t < 2) {
        int target = m + t;
        int lo = 0, hi = NN;
        while (lo < hi) { int mid = (lo + hi) >> 1; if (seg[mid] < target) lo = mid + 1; else hi = mid; }
        bnd[t] = lo;
    }
    __syncthreads();
    int lo = bnd[0], hi = bnd[1];
    if (t < OD) {
        float s = 0.f;
        for (int i = lo; i < hi; i++) s += g_a56[(size_t)i * ODP + t];
        v[t] = s;
    }
    __syncthreads();
    for (int l = 0; l < 2; l++) {
        if (t < OD) {
            float s = bout[l * OD + t];
            const float* W = Wout + l * OD * OD;
            for (int k = 0; k < OD; k++) s = fmaf(v[k], W[k * OD + t], s);
            o[t] = fmaxf(s, 0.f);
        }
        __syncthreads();
        if (t < OD) v[t] = o[t];
        __syncthreads();
    }
    if (t < 2) {
        float s = bprop[t];
        for (int k = 0; k < OD; k++) s = fmaf(v[k], Wprop[k * 2 + t], s);
        float r;
        if (s >= 0.f) r = 1.0f / (1.0f + fexp(-s));
        else { float e = fexp(s); r = e / (1.0f + e); }
        out[m * 2 + t] = r;
    }
}

// ---------------- orchestration ----------------------------------------------
typedef CUresult (*tmap_fn_t)(CUtensorMap*, CUtensorMapDataType, cuuint32_t, void*,
                              const cuuint64_t*, const cuuint64_t*, const cuuint32_t*,
                              const cuuint32_t*, CUtensorMapInterleave, CUtensorMapSwizzle,
                              CUtensorMapL2promotion, CUtensorMapFloatOOBfill);

static void make_tmap8(tmap_fn_t fn, CUtensorMap* m, void* base,
                       unsigned long long d0, unsigned long long d1) {
    cuuint64_t dims[2] = { d0, d1 };
    cuuint64_t strides[1] = { d0 };           // bytes (uint8)
    cuuint32_t box[2] = { 128, 64 };          // 128B rows = SW128
    cuuint32_t es[2] = { 1, 1 };
    fn(m, CU_TENSOR_MAP_DATA_TYPE_UINT8, 2, base, dims, strides, box, es,
       CU_TENSOR_MAP_INTERLEAVE_NONE, CU_TENSOR_MAP_SWIZZLE_128B,
       CU_TENSOR_MAP_L2_PROMOTION_L2_128B, CU_TENSOR_MAP_FLOAT_OOB_FILL_NONE);
}

extern "C" void kernel_launch(void* const* d_in, const int* in_sizes, int n_in,
                              void* d_out, int out_size) {
    const int*   fp   = (const int*)  d_in[0];
    const float* adj  = (const float*)d_in[1];
    const int*   seg  = (const int*)  d_in[2];
    const float* emb  = (const float*)d_in[3];
    const float* Wfp  = (const float*)d_in[4];
    const float* bfp  = (const float*)d_in[5];
    const float* Wh   = (const float*)d_in[6];
    const float* ah   = (const float*)d_in[7];
    const float* Woa  = (const float*)d_in[8];
    const float* aoa  = (const float*)d_in[9];
    const float* Wout = (const float*)d_in[10];
    const float* bout = (const float*)d_in[11];
    const float* Wpr  = (const float*)d_in[12];
    const float* bpr  = (const float*)d_in[13];
    float* out = (float*)d_out;

    float *x, *h, *tb, *z, *ho, *a56, *wpad;
    void *adj8_p, *h8T_p;
    cudaGetSymbolAddress((void**)&x,    g_x);
    cudaGetSymbolAddress((void**)&h,    g_h);
    cudaGetSymbolAddress((void**)&tb,   g_t);
    cudaGetSymbolAddress((void**)&z,    g_z);
    cudaGetSymbolAddress((void**)&ho,   g_ho);
    cudaGetSymbolAddress((void**)&a56,  g_a56);
    cudaGetSymbolAddress((void**)&wpad, g_wpad);
    cudaGetSymbolAddress(&adj8_p, g_adj8);
    cudaGetSymbolAddress(&h8T_p,  g_h8T);

    tmap_fn_t tmap_fn = nullptr;
    cudaDriverEntryPointQueryResult qr;
    cudaGetDriverEntryPointByVersion("cuTensorMapEncodeTiled", (void**)&tmap_fn,
                                     12000, cudaEnableDefault, &qr);
    static CUtensorMap mapAdj, mapHT, mapHT64;
    make_tmap8(tmap_fn, &mapAdj,  adj8_p, NN, NN);
    make_tmap8(tmap_fn, &mapHT,   h8T_p,  NN, DIM);
    make_tmap8(tmap_fn, &mapHT64, h8T_p,  NN, 64);

    const int SZ2 = (int)sizeof(TAux) + 1024 + TNST * 3 * 8192;  // NB=2
    const int SZ1 = (int)sizeof(TAux) + 1024 + TNST * 2 * 8192;  // NB=1
    cudaFuncSetAttribute(k_tmma<2,0>, cudaFuncAttributeMaxDynamicSharedMemorySize, SZ2);
    cudaFuncSetAttribute(k_tmma<2,1>, cudaFuncAttributeMaxDynamicSharedMemorySize, SZ2);
    cudaFuncSetAttribute(k_tmma<1,1>, cudaFuncAttributeMaxDynamicSharedMemorySize, SZ1);

    k_gather<<<NN * DIM / 256, 256>>>(fp, emb);
    k_adjconv<<<(size_t)NN * NN / 2048, 256>>>(adj);
    k_padw<<<DIM * ODP / 256, 256>>>(Woa);

    // 3 message-passing layers
    for (int l = 0; l < 3; l++) {
        k_gemm<128><<<NN / 64, 256>>>(x, DIM, DIM, Wfp + l * DIM * DIM,
                                      bfp + l * DIM, h, 1.f, 1, 0);
        k_transp8<<<dim3(NN / 64, DIM / 64), 256>>>(h, DIM);
        k_tmma<2,0><<<NN / 64, 256, SZ2>>>(mapAdj, mapHT, h, tb, 0);
        k_l2norm<<<NN / 8, 256>>>(tb, x);
    }

    // 2 GAT heads
    for (int hd = 0; hd < 2; hd++) {
        k_gemm<128><<<NN / 64, 256>>>(x, DIM, DIM, Wh + hd * DIM * DIM,
                                      nullptr, h, 1.f, 0, 1);
        k_s12<<<NN / 8, 256>>>(h, DIM, DIM, ah + hd * 2 * DIM);
        k_prep<<<NN / 256, 256>>>();
        k_transp8<<<dim3(NN / 64, DIM / 64), 256>>>(h, DIM);
        k_colmean1<128><<<64, 128>>>(h);
        k_colmean2<<<1, 128>>>(128);
        k_tmma<2,1><<<NN / 64, 256, SZ2>>>(mapAdj, mapHT, nullptr, z, hd);
    }

    // out-attention at D=56 (padded to 64); x = z/2 folded into scale
    k_gemm<64><<<NN / 64, 256>>>(z, DIM, DIM, wpad, nullptr, ho, 0.5f, 0, 1);
    k_s12<<<NN / 8, 256>>>(ho, ODP, OD, aoa);
    k_prep<<<NN / 256, 256>>>();
    k_transp8<<<dim3(NN / 64, 1), 256>>>(ho, ODP);
    k_colmean1<64><<<64, 64>>>(ho);
    k_colmean2<<<1, 128>>>(64);
    k_tmma<1,1><<<NN / 64, 256, SZ1>>>(mapAdj, mapHT64, nullptr, a56, 0);

    k_smax56<<<NN / 8, 256>>>(a56);
    k_head<<<NMOL, 64>>>(seg, Wout, bout, Wpr, bpr, out);
}

// round 10
// speedup vs baseline: 4.2672x; 1.0106x over previous
#include <cuda_runtime.h>
#include <cuda.h>
#include <cuda_bf16.h>
#include <cuda_fp16.h>
#include <cuda_fp8.h>
#include <math.h>

#define NN   8192
#define DIM  128
#define NMOL 256
#define OD   56
#define ODP  64

typedef unsigned long long u64;
typedef unsigned int u32;
typedef unsigned short u16;
typedef unsigned char u8;

// ---------------- f32x2 helpers ----------------------------------------------
__device__ __forceinline__ u64 pk2(float lo, float hi) {
    u64 r; asm("mov.b64 %0, {%1,%2};" : "=l"(r) : "f"(lo), "f"(hi)); return r;
}
__device__ __forceinline__ void upk2(u64 v, float &lo, float &hi) {
    asm("mov.b64 {%0,%1}, %2;" : "=f"(lo), "=f"(hi) : "l"(v));
}
__device__ __forceinline__ void fma2(u64 &d, u64 a, u64 b) {
    asm("fma.rn.f32x2 %0, %1, %2, %0;" : "+l"(d) : "l"(a), "l"(b));
}

// ---------------- FMA-only exp ------------------------------------------------
__device__ __forceinline__ float fexp(float x) {
    x = fmaxf(x, -87.0f);
    float y = x * 1.44269504f;
    float r = rintf(y);
    float f = y - r;
    float p = 1.33335581e-3f;
    p = fmaf(p, f, 9.61812911e-3f);
    p = fmaf(p, f, 5.55041087e-2f);
    p = fmaf(p, f, 2.40226507e-1f);
    p = fmaf(p, f, 6.93147181e-1f);
    p = fmaf(p, f, 1.0f);
    int e = (int)r;
    return p * __int_as_float((e + 127) << 23);
}

__device__ __forceinline__ u32 encf(float s) {
    u32 b = __float_as_uint(s);
    return (b & 0x80000000u) ? ~b : (b | 0x80000000u);
}
__device__ __forceinline__ float decf(u32 u) {
    return __uint_as_float((u & 0x80000000u) ? (u & 0x7fffffffu) : ~u);
}

// ---------------- MMA / ldmatrix helpers --------------------------------------
__device__ __forceinline__ u32 smem_u32(const void* p) {
    return (u32)__cvta_generic_to_shared(p);
}
__device__ __forceinline__ void ldm_x4(u32 a, u32* r) {
    asm volatile("ldmatrix.sync.aligned.m8n8.x4.shared.b16 {%0,%1,%2,%3}, [%4];"
        : "=r"(r[0]), "=r"(r[1]), "=r"(r[2]), "=r"(r[3]) : "r"(a));
}
// fp8 e4m3 MMA, K=32 per instruction (sm_89+ base feature)
__device__ __forceinline__ void mma_e4m3(float* c, const u32* a, const u32* b) {
    asm volatile(
        "mma.sync.aligned.m16n8k32.row.col.f32.e4m3.e4m3.f32 "
        "{%0,%1,%2,%3}, {%4,%5,%6,%7}, {%8,%9}, {%0,%1,%2,%3};"
        : "+f"(c[0]), "+f"(c[1]), "+f"(c[2]), "+f"(c[3])
        : "r"(a[0]), "r"(a[1]), "r"(a[2]), "r"(a[3]), "r"(b[0]), "r"(b[1]));
}

// ---------------- TMA / mbarrier ----------------------------------------------
__device__ __forceinline__ void tma2d(u32 dst, const void* map, int x, int y, u32 mbar) {
    asm volatile(
        "cp.async.bulk.tensor.2d.shared::cta.global.tile.mbarrier::complete_tx::bytes "
        "[%0], [%1, {%2, %3}], [%4];"
        :: "r"(dst), "l"(map), "r"(x), "r"(y), "r"(mbar) : "memory");
}
__device__ __forceinline__ void mbar_init(u32 a, u32 cnt) {
    asm volatile("mbarrier.init.shared.b64 [%0], %1;" :: "r"(a), "r"(cnt) : "memory");
}
__device__ __forceinline__ void mbar_expect(u32 a, u32 bytes) {
    asm volatile("mbarrier.arrive.expect_tx.shared.b64 _, [%0], %1;"
                 :: "r"(a), "r"(bytes) : "memory");
}
__device__ __forceinline__ void mbar_wait(u32 a, u32 parity) {
    asm volatile(
        "{\n\t.reg .pred P;\n\t"
        "W_%=:\n\t"
        "mbarrier.try_wait.parity.acquire.cta.shared::cta.b64 P, [%0], %1, 0x989680;\n\t"
        "@P bra.uni D_%=;\n\t"
        "bra.uni W_%=;\n\t"
        "D_%=:\n\t}"
        :: "r"(a), "r"(parity) : "memory");
}
__device__ __forceinline__ void mbar_inval(u32 a) {
    asm volatile("mbarrier.inval.shared.b64 [%0];" :: "r"(a) : "memory");
}
// standard 128B swizzle
__device__ __forceinline__ u32 swz(u32 o) { return o ^ ((o >> 3) & 0x70); }

// ---------------- scratch -----------------------------------------------------
__device__ u8 g_adj8[(size_t)NN * NN];    // 64 MB, exact 0/1 in e4m3
__device__ u8 g_h8T[(size_t)DIM * NN];    // H^T fp8, k-major rows per feature
__device__ float g_x [NN * DIM];
__device__ float g_h [NN * DIM];
__device__ float g_t [NN * DIM];
__device__ float g_z [NN * DIM];
__device__ float g_s1[NN];
__device__ float g_s2[NN];
__device__ u32   g_s2maxu;
__device__ float g_pa[NN], g_pb[NN], g_pth[NN], g_peg[NN], g_peq[NN];
__device__ float g_ho [NN * ODP];
__device__ float g_a56[NN * ODP];
__device__ float g_wpad[DIM * ODP];
__device__ float g_cm[DIM];
__device__ float g_cmp[64 * DIM];

// ---------------- small utility kernels ---------------------------------------
__global__ void k_gather(const int* __restrict__ fp, const float* __restrict__ emb) {
    int idx = blockIdx.x * 256 + threadIdx.x;
    int i = idx >> 7, c = idx & 127;
    g_x[idx] = emb[fp[i] * DIM + c];
}

__global__ void k_padw(const float* __restrict__ W) {
    int idx = blockIdx.x * 256 + threadIdx.x;
    int k = idx >> 6, c = idx & 63;
    g_wpad[idx] = (c < OD) ? W[k * OD + c] : 0.0f;
}

// adj fp32 -> e4m3 bytes (1.0 == 0x38), exact
__global__ void k_adjconv(const float* __restrict__ adj) {
    size_t base = ((size_t)blockIdx.x * 256 + threadIdx.x) * 8;
    float4 a = *(const float4*)(adj + base);
    float4 b = *(const float4*)(adj + base + 4);
    u8 o[8];
    o[0] = a.x != 0.f ? 0x38 : 0; o[1] = a.y != 0.f ? 0x38 : 0;
    o[2] = a.z != 0.f ? 0x38 : 0; o[3] = a.w != 0.f ? 0x38 : 0;
    o[4] = b.x != 0.f ? 0x38 : 0; o[5] = b.y != 0.f ? 0x38 : 0;
    o[6] = b.z != 0.f ? 0x38 : 0; o[7] = b.w != 0.f ? 0x38 : 0;
    *(u64*)(g_adj8 + base) = *(u64*)o;
}

// H [NN][ldf] fp32 -> H^T fp8 [feat][NN]; grid (NN/64, feats/64)
__global__ void __launch_bounds__(256) k_transp8(const float* __restrict__ H, int ldf) {
    __shared__ float S[64][65];
    const int n0 = blockIdx.x * 64, f0 = blockIdx.y * 64;
    const int t = threadIdx.x, r = t >> 2, cb = t & 3;
#pragma unroll
    for (int q = 0; q < 4; q++) {
        float4 v = *(const float4*)&H[(size_t)(n0 + r) * ldf + f0 + cb * 16 + q * 4];
        S[r][cb * 16 + q * 4 + 0] = v.x; S[r][cb * 16 + q * 4 + 1] = v.y;
        S[r][cb * 16 + q * 4 + 2] = v.z; S[r][cb * 16 + q * 4 + 3] = v.w;
    }
    __syncthreads();
    const int f = t >> 2, nb = t & 3;
    u8 o[16];
#pragma unroll
    for (int q = 0; q < 8; q++) {
        float2 fv;
        fv.x = S[nb * 16 + 2 * q][f];
        fv.y = S[nb * 16 + 2 * q + 1][f];
        __nv_fp8x2_storage_t qq = __nv_cvt_float2_to_fp8x2(fv, __NV_SATFINITE, __NV_E4M3);
        *(u16*)(o + 2 * q) = qq;
    }
    *(uint4*)(g_h8T + (size_t)(f0 + f) * NN + n0 + nb * 16) = *(uint4*)o;
}

// ---------------- row L2-normalize --------------------------------------------
__global__ void k_l2norm(const float* __restrict__ in, float* __restrict__ out) {
    int w = threadIdx.x >> 5, lane = threadIdx.x & 31;
    int row = blockIdx.x * 8 + w;
    const float* r = in + (size_t)row * DIM;
    float v[4], ss = 0.f;
#pragma unroll
    for (int q = 0; q < 4; q++) { v[q] = r[lane + q * 32]; ss += v[q] * v[q]; }
#pragma unroll
    for (int o = 16; o > 0; o >>= 1) ss += __shfl_xor_sync(0xffffffffu, ss, o);
    float inv = 1.0f / fmaxf(sqrtf(ss), 1e-12f);
#pragma unroll
    for (int q = 0; q < 4; q++) out[(size_t)row * DIM + lane + q * 32] = v[q] * inv;
}

// ---------------- s1/s2 projections + global s2 max ---------------------------
__global__ void k_s12(const float* __restrict__ H, int ld, int Dr,
                      const float* __restrict__ a) {
    int w = threadIdx.x >> 5, lane = threadIdx.x & 31;
    int row = blockIdx.x * 8 + w;
    const float* r = H + (size_t)row * ld;
    float p1 = 0.f, p2 = 0.f;
    for (int c = lane; c < Dr; c += 32) {
        float v = r[c];
        p1 = fmaf(v, a[c], p1);
        p2 = fmaf(v, a[Dr + c], p2);
    }
#pragma unroll
    for (int o = 16; o > 0; o >>= 1) {
        p1 += __shfl_xor_sync(0xffffffffu, p1, o);
        p2 += __shfl_xor_sync(0xffffffffu, p2, o);
    }
    if (lane == 0) {
        g_s1[row] = p1; g_s2[row] = p2;
        atomicMax(&g_s2maxu, encf(p2));
    }
}

// ---------------- per-node attention precompute -------------------------------
__global__ void k_prep() {
    int i = blockIdx.x * 256 + threadIdx.x;
    float gmax = decf(g_s2maxu);
    float s1 = g_s1[i], s2 = g_s2[i];
    float u = s1 + gmax;
    float m = (u > 0.f) ? u : 0.25f * u;
    g_pa[i] = fexp(s1 - m);
    g_pb[i] = fexp(0.25f * s1 - m);
    g_pth[i] = -s1;
    g_peg[i] = fexp(s2);
    g_peq[i] = fexp(0.25f * s2);
}

// ---------------- column mean (deterministic 2-stage) -------------------------
template<int BN>
__global__ void k_colmean1(const float* __restrict__ H) {
    int t = threadIdx.x;
    int r0 = blockIdx.x * 128;
    float s = 0.f;
    for (int r = 0; r < 128; r++) s += H[(size_t)(r0 + r) * BN + t];
    g_cmp[blockIdx.x * DIM + t] = s;
}
__global__ void k_colmean2(int BN) {
    int t = threadIdx.x;
    float s = 0.f;
    if (t < BN) for (int b = 0; b < 64; b++) s += g_cmp[b * DIM + t];
    g_cm[t] = s * (1.0f / NN);
}

// ================== TMA-fed FP8 mma.sync kernel (64x64 per CTA) ===============
// grid (NN/64 row blocks, Ncols/64 col blocks). Chunk = 128 K fp8.
// Tiles: Adj[64r][128k] + HT[64n][128k], 128B rows, SW128.
// MODE 0: Out = resid + adj @ H
// MODE 1: P_ij = adj_ij*(s2_j>=th_i ? a_i*eg_j : b_i*eq_j) e4m3;
//         Out_i = elu(P@H / d_i) (d_i==0 -> colmean), opt accumulate.
#define TNST 4
struct TAux {
    u8 Phi[64][144];
    float A[64], B[64], Th[64], D[64];
    u64 bar[TNST];
};

template<int MODE>
__global__ void __launch_bounds__(256) k_tmma(
    const __grid_constant__ CUtensorMap mAdj,
    const __grid_constant__ CUtensorMap mH,
    const float* __restrict__ resid,
    float* __restrict__ Out, int ldo, int accum)
{
    constexpr int BK = 128, NT = NN / BK;   // 64 chunks
    constexpr u32 STAGE_B = 2 * 8192;       // adj tile + H tile

    extern __shared__ char raw[];
    TAux& X = *reinterpret_cast<TAux*>(raw);
    const u32 tiles_u = (smem_u32(raw) + (u32)sizeof(TAux) + 1023u) & ~1023u;
    char* tiles_p = raw + (tiles_u - smem_u32(raw));

    const int t = threadIdx.x, lane = t & 31, warp = t >> 5;
    const int i0 = blockIdx.x * 64, co = blockIdx.y * 64;
    const int wm = warp >> 1, wn = warp & 1;       // 4x2 warp grid, 16x32 each
    const int pr = warp * 8 + (lane >> 2);         // P-gen row
    const int pc = (lane & 3) * 32;                // P-gen byte-col start

    if (MODE && t < 64) {
        X.A[t] = g_pa[i0 + t]; X.B[t] = g_pb[i0 + t]; X.Th[t] = g_pth[i0 + t];
    }
    if (t == 0)
        for (int s = 0; s < TNST; s++) mbar_init(smem_u32(&X.bar[s]), 1);
    __syncthreads();
    float ai = 0.f, bi = 0.f, thi = 0.f;
    if (MODE) { ai = X.A[pr]; bi = X.B[pr]; thi = X.Th[pr]; }

    if (t == 0) {
#pragma unroll
        for (int s = 0; s < 3; s++) {
            u32 bar = smem_u32(&X.bar[s]);
            mbar_expect(bar, STAGE_B);
            u32 st = tiles_u + s * STAGE_B;
            tma2d(st,        &mAdj, s * 128, i0, bar);
            tma2d(st + 8192, &mH,   s * 128, co, bar);
        }
    }

    float acc[4][4];    // FN=4 blocks of (m16 x n8) frag
#pragma unroll
    for (int b = 0; b < 4; b++)
#pragma unroll
        for (int c = 0; c < 4; c++) acc[b][c] = 0.f;
    float dpart = 0.f;

    for (int kt = 0; kt < NT; kt++) {
        const int cur = kt & 3, k0 = kt * BK;
        const u32 stg = tiles_u + cur * STAGE_B;
        mbar_wait(smem_u32(&X.bar[cur]), (kt >> 2) & 1);

        if (MODE) {
            const char* adjp = tiles_p + cur * STAGE_B;
            u32 off = (u32)pr * 128 + (u32)pc;
            uint4 av0 = *(const uint4*)(adjp + swz(off));
            uint4 av1 = *(const uint4*)(adjp + swz(off + 16));
            u8 ab[32];
            *(uint4*)ab = av0; *(uint4*)(ab + 16) = av1;
            u8 pq[32];
            const float* s2 = g_s2  + k0 + pc;
            const float* eg = g_peg + k0 + pc;
            const float* eq = g_peq + k0 + pc;
#pragma unroll
            for (int c = 0; c < 16; c++) {
                int c0 = 2 * c, c1 = 2 * c + 1;
                float2 fv;
                fv.x = ab[c0] ? ((s2[c0] >= thi) ? ai * eg[c0] : bi * eq[c0]) : 0.f;
                fv.y = ab[c1] ? ((s2[c1] >= thi) ? ai * eg[c1] : bi * eq[c1]) : 0.f;
                __nv_fp8x2_storage_t qq = __nv_cvt_float2_to_fp8x2(fv, __NV_SATFINITE, __NV_E4M3);
                *(u16*)(pq + 2 * c) = qq;
                __half2_raw hr = __nv_cvt_fp8x2_to_halfraw2(qq, __NV_E4M3);
                float2 dv = __half22float2(*(__half2*)&hr);
                dpart += dv.x + dv.y;
            }
            *(uint4*)&X.Phi[pr][pc]      = *(uint4*)pq;
            *(uint4*)&X.Phi[pr][pc + 16] = *(uint4*)(pq + 16);
            __syncthreads();
        }

#pragma unroll
        for (int kk = 0; kk < 4; kk++) {    // 4 x k32 = 128 K per chunk
            u32 ah[4];
            {
                int rr = wm * 16 + (lane & 15);
                u32 boff = (u32)kk * 32 + ((u32)(lane >> 4)) * 16;
                u32 a = MODE ? smem_u32(&X.Phi[rr][0]) + boff
                             : stg + swz((u32)rr * 128 + boff);
                ldm_x4(a, ah);
            }
            u32 bh[4][2];
#pragma unroll
            for (int fp2 = 0; fp2 < 2; fp2++) {
                int nb = wn * 32 + fp2 * 16;
                u32 rowN = (u32)nb + (u32)(lane & 7) + (((u32)lane >> 4) << 3);
                u32 a = stg + 8192
                      + swz(rowN * 128 + (u32)kk * 32 + (((u32)lane >> 3) & 1) * 16);
                u32 r4[4];
                ldm_x4(a, r4);
                bh[2*fp2][0] = r4[0]; bh[2*fp2][1] = r4[1];
                bh[2*fp2+1][0] = r4[2]; bh[2*fp2+1][1] = r4[3];
            }
#pragma unroll
            for (int fn = 0; fn < 4; fn++)
                mma_e4m3(acc[fn], ah, bh[fn]);
        }
        __syncthreads();

        if (t == 0 && kt + 3 < NT) {
            const int s = (kt + 3) & 3;
            u32 bar = smem_u32(&X.bar[s]);
            mbar_expect(bar, STAGE_B);
            u32 st = tiles_u + s * STAGE_B;
            tma2d(st,        &mAdj, (kt + 3) * 128, i0, bar);
            tma2d(st + 8192, &mH,   (kt + 3) * 128, co, bar);
        }
    }

    if (MODE) {
        dpart += __shfl_xor_sync(0xffffffffu, dpart, 1);
        dpart += __shfl_xor_sync(0xffffffffu, dpart, 2);
        if ((lane & 3) == 0) X.D[pr] = dpart;
    }
    __syncthreads();

#pragma unroll
    for (int h = 0; h < 2; h++) {
        int rl = wm * 16 + (lane >> 2) + h * 8;
        int row = i0 + rl;
#pragma unroll
        for (int fn = 0; fn < 4; fn++) {
            int col = co + wn * 32 + fn * 8 + (lane & 3) * 2;
            float v0 = acc[fn][2 * h], v1 = acc[fn][2 * h + 1];
            float* op = Out + (size_t)row * ldo + col;
            if (MODE == 0) {
                float2 rr = *(const float2*)(resid + (size_t)row * ldo + col);
                float2 o; o.x = v0 + rr.x; o.y = v1 + rr.y;
                *(float2*)op = o;
            } else {
                float dd = X.D[rl];
                if (dd > 0.f) { float inv = 1.0f / dd; v0 *= inv; v1 *= inv; }
                else          { v0 = g_cm[col]; v1 = g_cm[col + 1]; }
                v0 = (v0 > 0.f) ? v0 : fexp(v0) - 1.0f;
                v1 = (v1 > 0.f) ? v1 : fexp(v1) - 1.0f;
                if (accum) {
                    float2 zz = *(const float2*)op;
                    v0 += zz.x; v1 += zz.y;
                }
                float2 o; o.x = v0; o.y = v1;
                *(float2*)op = o;
            }
        }
    }
    __syncthreads();
    if (t == 0)
        for (int s = 0; s < TNST; s++) mbar_inval(smem_u32(&X.bar[s]));
}

// ---------------- dense GEMM: 64x64 per CTA, single K=128 shot ----------------
// grid (NN/64, Ncols/64). C = act(scale*(A@B) + bias), fp32.
__global__ void __launch_bounds__(256) k_gemm(
        const float* __restrict__ A,
        const float* __restrict__ B, int ldb,
        const float* __restrict__ bias,
        float* __restrict__ C, int ldc,
        float scale, int relu, int rst)
{
    extern __shared__ float sm[];
    float (*As)[65] = (float(*)[65])sm;                  // [128][65]
    float (*Bs)[64] = (float(*)[64])(sm + 128 * 65);     // [128][64]
    const int t = threadIdx.x;
    const int row0 = blockIdx.x * 64, co = blockIdx.y * 64;

    if (rst && blockIdx.x == 0 && blockIdx.y == 0 && t == 0) g_s2maxu = 0u;

#pragma unroll
    for (int l = 0; l < 32; l++) {
        int idx = t + l * 256;
        int m = idx >> 7, k = idx & 127;
        As[k][m] = A[(size_t)(row0 + m) * DIM + k];
    }
#pragma unroll
    for (int l = 0; l < 32; l++) {
        int idx = t + l * 256;
        int k = idx >> 6, c = idx & 63;
        Bs[k][c] = B[(size_t)k * ldb + co + c];
    }
    __syncthreads();

    const int tx = t & 15, ty = t >> 4;
    u64 acc[4][2];
#pragma unroll
    for (int i = 0; i < 4; i++) { acc[i][0] = 0ULL; acc[i][1] = 0ULL; }

#pragma unroll 4
    for (int k = 0; k < 128; k++) {
        float a0 = As[k][ty * 4 + 0];
        float a1 = As[k][ty * 4 + 1];
        float a2 = As[k][ty * 4 + 2];
        float a3 = As[k][ty * 4 + 3];
        u64 b0 = *(const u64*)&Bs[k][tx * 4];
        u64 b1 = *(const u64*)&Bs[k][tx * 4 + 2];
        fma2(acc[0][0], pk2(a0, a0), b0); fma2(acc[0][1], pk2(a0, a0), b1);
        fma2(acc[1][0], pk2(a1, a1), b0); fma2(acc[1][1], pk2(a1, a1), b1);
        fma2(acc[2][0], pk2(a2, a2), b0); fma2(acc[2][1], pk2(a2, a2), b1);
        fma2(acc[3][0], pk2(a3, a3), b0); fma2(acc[3][1], pk2(a3, a3), b1);
    }
#pragma unroll
    for (int i = 0; i < 4; i++) {
        int m = row0 + ty * 4 + i;
#pragma unroll
        for (int j = 0; j < 2; j++) {
            int c = co + tx * 4 + 2 * j;
            float lo, hi; upk2(acc[i][j], lo, hi);
            float v0 = scale * lo, v1 = scale * hi;
            if (bias)  { v0 += bias[c]; v1 += bias[c + 1]; }
            if (relu)  { v0 = fmaxf(v0, 0.f); v1 = fmaxf(v1, 0.f); }
            float2 o; o.x = v0; o.y = v1;
            *(float2*)&C[(size_t)m * ldc + c] = o;
        }
    }
}

// ---------------- row softmax over first 56 of 64 cols ------------------------
__global__ void k_smax56(float* __restrict__ X) {
    int w = threadIdx.x >> 5, lane = threadIdx.x & 31;
    int row = blockIdx.x * 8 + w;
    float* r = X + (size_t)row * ODP;
    float v0 = (lane < OD)      ? r[lane]      : -3e38f;
    float v1 = (lane + 32 < OD) ? r[lane + 32] : -3e38f;
    float m = fmaxf(v0, v1);
#pragma unroll
    for (int o = 16; o > 0; o >>= 1) m = fmaxf(m, __shfl_xor_sync(0xffffffffu, m, o));
    float e0 = (lane < OD)      ? fexp(v0 - m) : 0.f;
    float e1 = (lane + 32 < OD) ? fexp(v1 - m) : 0.f;
    float s = e0 + e1;
#pragma unroll
    for (int o = 16; o > 0; o >>= 1) s += __shfl_xor_sync(0xffffffffu, s, o);
    float inv = 1.0f / s;
    if (lane < OD)      r[lane]      = e0 * inv;
    if (lane + 32 < OD) r[lane + 32] = e1 * inv;
}

// ---------------- segment-sum readout + MLP head ------------------------------
__global__ void k_head(const int* __restrict__ seg,
                       const float* __restrict__ Wout, const float* __restrict__ bout,
                       const float* __restrict__ Wprop, const float* __restrict__ bprop,
                       float* __restrict__ out)
{
    __shared__ float v[OD];
    __shared__ float o[OD];
    __shared__ int bnd[2];
    const int m = blockIdx.x, t = threadIdx.x;
    if (t < 2) {
        int target = m + t;
        int lo = 0, hi = NN;
        while (lo < hi) { int mid = (lo + hi) >> 1; if (seg[mid] < target) lo = mid + 1; else hi = mid; }
        bnd[t] = lo;
    }
    __syncthreads();
    int lo = bnd[0], hi = bnd[1];
    if (t < OD) {
        float s = 0.f;
        for (int i = lo; i < hi; i++) s += g_a56[(size_t)i * ODP + t];
        v[t] = s;
    }
    __syncthreads();
    for (int l = 0; l < 2; l++) {
        if (t < OD) {
            float s = bout[l * OD + t];
            const float* W = Wout + l * OD * OD;
            for (int k = 0; k < OD; k++) s = fmaf(v[k], W[k * OD + t], s);
            o[t] = fmaxf(s, 0.f);
        }
        __syncthreads();
        if (t < OD) v[t] = o[t];
        __syncthreads();
    }
    if (t < 2) {
        float s = bprop[t];
        for (int k = 0; k < OD; k++) s = fmaf(v[k], Wprop[k * 2 + t], s);
        float r;
        if (s >= 0.f) r = 1.0f / (1.0f + fexp(-s));
        else { float e = fexp(s); r = e / (1.0f + e); }
        out[m * 2 + t] = r;
    }
}

// ---------------- orchestration ----------------------------------------------
typedef CUresult (*tmap_fn_t)(CUtensorMap*, CUtensorMapDataType, cuuint32_t, void*,
                              const cuuint64_t*, const cuuint64_t*, const cuuint32_t*,
                              const cuuint32_t*, CUtensorMapInterleave, CUtensorMapSwizzle,
                              CUtensorMapL2promotion, CUtensorMapFloatOOBfill);

static void make_tmap8(tmap_fn_t fn, CUtensorMap* m, void* base,
                       unsigned long long d0, unsigned long long d1) {
    cuuint64_t dims[2] = { d0, d1 };
    cuuint64_t strides[1] = { d0 };
    cuuint32_t box[2] = { 128, 64 };
    cuuint32_t es[2] = { 1, 1 };
    fn(m, CU_TENSOR_MAP_DATA_TYPE_UINT8, 2, base, dims, strides, box, es,
       CU_TENSOR_MAP_INTERLEAVE_NONE, CU_TENSOR_MAP_SWIZZLE_128B,
       CU_TENSOR_MAP_L2_PROMOTION_L2_128B, CU_TENSOR_MAP_FLOAT_OOB_FILL_NONE);
}

extern "C" void kernel_launch(void* const* d_in, const int* in_sizes, int n_in,
                              void* d_out, int out_size) {
    const int*   fp   = (const int*)  d_in[0];
    const float* adj  = (const float*)d_in[1];
    const int*   seg  = (const int*)  d_in[2];
    const float* emb  = (const float*)d_in[3];
    const float* Wfp  = (const float*)d_in[4];
    const float* bfp  = (const float*)d_in[5];
    const float* Wh   = (const float*)d_in[6];
    const float* ah   = (const float*)d_in[7];
    const float* Woa  = (const float*)d_in[8];
    const float* aoa  = (const float*)d_in[9];
    const float* Wout = (const float*)d_in[10];
    const float* bout = (const float*)d_in[11];
    const float* Wpr  = (const float*)d_in[12];
    const float* bpr  = (const float*)d_in[13];
    float* out = (float*)d_out;

    float *x, *h, *tb, *z, *ho, *a56, *wpad;
    void *adj8_p, *h8T_p;
    cudaGetSymbolAddress((void**)&x,    g_x);
    cudaGetSymbolAddress((void**)&h,    g_h);
    cudaGetSymbolAddress((void**)&tb,   g_t);
    cudaGetSymbolAddress((void**)&z,    g_z);
    cudaGetSymbolAddress((void**)&ho,   g_ho);
    cudaGetSymbolAddress((void**)&a56,  g_a56);
    cudaGetSymbolAddress((void**)&wpad, g_wpad);
    cudaGetSymbolAddress(&adj8_p, g_adj8);
    cudaGetSymbolAddress(&h8T_p,  g_h8T);

    tmap_fn_t tmap_fn = nullptr;
    cudaDriverEntryPointQueryResult qr;
    cudaGetDriverEntryPointByVersion("cuTensorMapEncodeTiled", (void**)&tmap_fn,
                                     12000, cudaEnableDefault, &qr);
    static CUtensorMap mapAdj, mapHT, mapHT64;
    make_tmap8(tmap_fn, &mapAdj,  adj8_p, NN, NN);
    make_tmap8(tmap_fn, &mapHT,   h8T_p,  NN, DIM);
    make_tmap8(tmap_fn, &mapHT64, h8T_p,  NN, 64);

    const int SZT = (int)sizeof(TAux) + 1024 + TNST * 2 * 8192;   // ~76 KB
    const int SZG = (128 * 65 + 128 * 64) * 4;                    // ~66 KB
    cudaFuncSetAttribute(k_tmma<0>, cudaFuncAttributeMaxDynamicSharedMemorySize, SZT);
    cudaFuncSetAttribute(k_tmma<1>, cudaFuncAttributeMaxDynamicSharedMemorySize, SZT);
    cudaFuncSetAttribute(k_gemm,    cudaFuncAttributeMaxDynamicSharedMemorySize, SZG);

    k_gather<<<NN * DIM / 256, 256>>>(fp, emb);
    k_adjconv<<<(size_t)NN * NN / 2048, 256>>>(adj);
    k_padw<<<DIM * ODP / 256, 256>>>(Woa);

    // 3 message-passing layers
    for (int l = 0; l < 3; l++) {
        k_gemm<<<dim3(NN / 64, 2), 256, SZG>>>(x, Wfp + l * DIM * DIM, DIM,
                                               bfp + l * DIM, h, DIM, 1.f, 1, 0);
        k_transp8<<<dim3(NN / 64, DIM / 64), 256>>>(h, DIM);
        k_tmma<0><<<dim3(NN / 64, 2), 256, SZT>>>(mapAdj, mapHT, h, tb, DIM, 0);
        k_l2norm<<<NN / 8, 256>>>(tb, x);
    }

    // 2 GAT heads
    for (int hd = 0; hd < 2; hd++) {
        k_gemm<<<dim3(NN / 64, 2), 256, SZG>>>(x, Wh + hd * DIM * DIM, DIM,
                                               nullptr, h, DIM, 1.f, 0, 1);
        k_s12<<<NN / 8, 256>>>(h, DIM, DIM, ah + hd * 2 * DIM);
        k_prep<<<NN / 256, 256>>>();
        k_transp8<<<dim3(NN / 64, DIM / 64), 256>>>(h, DIM);
        k_colmean1<128><<<64, 128>>>(h);
        k_colmean2<<<1, 128>>>(128);
        k_tmma<1><<<dim3(NN / 64, 2), 256, SZT>>>(mapAdj, mapHT, nullptr, z, DIM, hd);
    }

    // out-attention at D=56 (padded to 64); x = z/2 folded into scale
    k_gemm<<<dim3(NN / 64, 1), 256, SZG>>>(z, wpad, ODP, nullptr, ho, ODP, 0.5f, 0, 1);
    k_s12<<<NN / 8, 256>>>(ho, ODP, OD, aoa);
    k_prep<<<NN / 256, 256>>>();
    k_transp8<<<dim3(NN / 64, 1), 256>>>(ho, ODP);
    k_colmean1<64><<<64, 64>>>(ho);
    k_colmean2<<<1, 128>>>(64);
    k_tmma<1><<<dim3(NN / 64, 1), 256, SZT>>>(mapAdj, mapHT64, nullptr, a56, ODP, 0);

    k_smax56<<<NN / 8, 256>>>(a56);
    k_head<<<NMOL, 64>>>(seg, Wout, bout, Wpr, bpr, out);
}

// round 11
// speedup vs baseline: 4.2867x; 1.0046x over previous
#include <cuda_runtime.h>
#include <cuda.h>
#include <cuda_bf16.h>
#include <cuda_fp16.h>
#include <cuda_fp8.h>
#include <math.h>

#define NN   8192
#define DIM  128
#define NMOL 256
#define OD   56
#define ODP  64

typedef unsigned long long u64;
typedef unsigned int u32;
typedef unsigned short u16;
typedef unsigned char u8;

// ---------------- f32x2 helpers ----------------------------------------------
__device__ __forceinline__ u64 pk2(float lo, float hi) {
    u64 r; asm("mov.b64 %0, {%1,%2};" : "=l"(r) : "f"(lo), "f"(hi)); return r;
}
__device__ __forceinline__ void upk2(u64 v, float &lo, float &hi) {
    asm("mov.b64 {%0,%1}, %2;" : "=f"(lo), "=f"(hi) : "l"(v));
}
__device__ __forceinline__ void fma2(u64 &d, u64 a, u64 b) {
    asm("fma.rn.f32x2 %0, %1, %2, %0;" : "+l"(d) : "l"(a), "l"(b));
}

// ---------------- FMA-only exp ------------------------------------------------
__device__ __forceinline__ float fexp(float x) {
    x = fmaxf(x, -87.0f);
    float y = x * 1.44269504f;
    float r = rintf(y);
    float f = y - r;
    float p = 1.33335581e-3f;
    p = fmaf(p, f, 9.61812911e-3f);
    p = fmaf(p, f, 5.55041087e-2f);
    p = fmaf(p, f, 2.40226507e-1f);
    p = fmaf(p, f, 6.93147181e-1f);
    p = fmaf(p, f, 1.0f);
    int e = (int)r;
    return p * __int_as_float((e + 127) << 23);
}

__device__ __forceinline__ u32 encf(float s) {
    u32 b = __float_as_uint(s);
    return (b & 0x80000000u) ? ~b : (b | 0x80000000u);
}
__device__ __forceinline__ float decf(u32 u) {
    return __uint_as_float((u & 0x80000000u) ? (u & 0x7fffffffu) : ~u);
}

// ---------------- MMA / ldmatrix helpers --------------------------------------
__device__ __forceinline__ u32 smem_u32(const void* p) {
    return (u32)__cvta_generic_to_shared(p);
}
__device__ __forceinline__ void ldm_x4(u32 a, u32* r) {
    asm volatile("ldmatrix.sync.aligned.m8n8.x4.shared.b16 {%0,%1,%2,%3}, [%4];"
        : "=r"(r[0]), "=r"(r[1]), "=r"(r[2]), "=r"(r[3]) : "r"(a));
}
// fp8 e4m3 MMA with f16 accumulator (potential 2x rate vs f32 accum)
__device__ __forceinline__ void mma_e4m3_h(u32* c, const u32* a, const u32* b) {
    asm volatile(
        "mma.sync.aligned.m16n8k32.row.col.f16.e4m3.e4m3.f16 "
        "{%0,%1}, {%2,%3,%4,%5}, {%6,%7}, {%0,%1};"
        : "+r"(c[0]), "+r"(c[1])
        : "r"(a[0]), "r"(a[1]), "r"(a[2]), "r"(a[3]), "r"(b[0]), "r"(b[1]));
}

// ---------------- TMA / mbarrier ----------------------------------------------
__device__ __forceinline__ void tma2d(u32 dst, const void* map, int x, int y, u32 mbar) {
    asm volatile(
        "cp.async.bulk.tensor.2d.shared::cta.global.tile.mbarrier::complete_tx::bytes "
        "[%0], [%1, {%2, %3}], [%4];"
        :: "r"(dst), "l"(map), "r"(x), "r"(y), "r"(mbar) : "memory");
}
__device__ __forceinline__ void mbar_init(u32 a, u32 cnt) {
    asm volatile("mbarrier.init.shared.b64 [%0], %1;" :: "r"(a), "r"(cnt) : "memory");
}
__device__ __forceinline__ void mbar_expect(u32 a, u32 bytes) {
    asm volatile("mbarrier.arrive.expect_tx.shared.b64 _, [%0], %1;"
                 :: "r"(a), "r"(bytes) : "memory");
}
__device__ __forceinline__ void mbar_wait(u32 a, u32 parity) {
    asm volatile(
        "{\n\t.reg .pred P;\n\t"
        "W_%=:\n\t"
        "mbarrier.try_wait.parity.acquire.cta.shared::cta.b64 P, [%0], %1, 0x989680;\n\t"
        "@P bra.uni D_%=;\n\t"
        "bra.uni W_%=;\n\t"
        "D_%=:\n\t}"
        :: "r"(a), "r"(parity) : "memory");
}
__device__ __forceinline__ void mbar_inval(u32 a) {
    asm volatile("mbarrier.inval.shared.b64 [%0];" :: "r"(a) : "memory");
}
// standard 128B swizzle
__device__ __forceinline__ u32 swz(u32 o) { return o ^ ((o >> 3) & 0x70); }

// ---------------- scratch -----------------------------------------------------
__device__ u8 g_adj8[(size_t)NN * NN];    // 64 MB, exact 0/1 in e4m3
__device__ u8 g_h8T[(size_t)DIM * NN];    // H^T fp8, k-major rows per feature
__device__ float g_x [NN * DIM];
__device__ float g_h [NN * DIM];
__device__ float g_t [NN * DIM];
__device__ float g_z [NN * DIM];
__device__ float g_s1[NN];
__device__ float g_s2[NN];
__device__ u32   g_s2maxu;
__device__ float g_pa[NN], g_pb[NN], g_pth[NN], g_peg[NN], g_peq[NN];
__device__ float g_ho [NN * ODP];
__device__ float g_a56[NN * ODP];
__device__ float g_wpad[DIM * ODP];
__device__ float g_cm[DIM];
__device__ float g_cmp[64 * DIM];

// ---------------- small utility kernels ---------------------------------------
__global__ void k_gather(const int* __restrict__ fp, const float* __restrict__ emb) {
    int idx = blockIdx.x * 256 + threadIdx.x;
    int i = idx >> 7, c = idx & 127;
    g_x[idx] = emb[fp[i] * DIM + c];
}

__global__ void k_padw(const float* __restrict__ W) {
    int idx = blockIdx.x * 256 + threadIdx.x;
    int k = idx >> 6, c = idx & 63;
    g_wpad[idx] = (c < OD) ? W[k * OD + c] : 0.0f;
}

// adj fp32 -> e4m3 bytes (1.0 == 0x38), exact
__global__ void k_adjconv(const float* __restrict__ adj) {
    size_t base = ((size_t)blockIdx.x * 256 + threadIdx.x) * 8;
    float4 a = *(const float4*)(adj + base);
    float4 b = *(const float4*)(adj + base + 4);
    u8 o[8];
    o[0] = a.x != 0.f ? 0x38 : 0; o[1] = a.y != 0.f ? 0x38 : 0;
    o[2] = a.z != 0.f ? 0x38 : 0; o[3] = a.w != 0.f ? 0x38 : 0;
    o[4] = b.x != 0.f ? 0x38 : 0; o[5] = b.y != 0.f ? 0x38 : 0;
    o[6] = b.z != 0.f ? 0x38 : 0; o[7] = b.w != 0.f ? 0x38 : 0;
    *(u64*)(g_adj8 + base) = *(u64*)o;
}

// H [NN][ldf] fp32 -> H^T fp8 [feat][NN]; grid (NN/64, feats/64)
__global__ void __launch_bounds__(256) k_transp8(const float* __restrict__ H, int ldf) {
    __shared__ float S[64][65];
    const int n0 = blockIdx.x * 64, f0 = blockIdx.y * 64;
    const int t = threadIdx.x, r = t >> 2, cb = t & 3;
#pragma unroll
    for (int q = 0; q < 4; q++) {
        float4 v = *(const float4*)&H[(size_t)(n0 + r) * ldf + f0 + cb * 16 + q * 4];
        S[r][cb * 16 + q * 4 + 0] = v.x; S[r][cb * 16 + q * 4 + 1] = v.y;
        S[r][cb * 16 + q * 4 + 2] = v.z; S[r][cb * 16 + q * 4 + 3] = v.w;
    }
    __syncthreads();
    const int f = t >> 2, nb = t & 3;
    u8 o[16];
#pragma unroll
    for (int q = 0; q < 8; q++) {
        float2 fv;
        fv.x = S[nb * 16 + 2 * q][f];
        fv.y = S[nb * 16 + 2 * q + 1][f];
        __nv_fp8x2_storage_t qq = __nv_cvt_float2_to_fp8x2(fv, __NV_SATFINITE, __NV_E4M3);
        *(u16*)(o + 2 * q) = qq;
    }
    *(uint4*)(g_h8T + (size_t)(f0 + f) * NN + n0 + nb * 16) = *(uint4*)o;
}

// ---------------- row L2-normalize --------------------------------------------
__global__ void k_l2norm(const float* __restrict__ in, float* __restrict__ out) {
    int w = threadIdx.x >> 5, lane = threadIdx.x & 31;
    int row = blockIdx.x * 8 + w;
    const float* r = in + (size_t)row * DIM;
    float v[4], ss = 0.f;
#pragma unroll
    for (int q = 0; q < 4; q++) { v[q] = r[lane + q * 32]; ss += v[q] * v[q]; }
#pragma unroll
    for (int o = 16; o > 0; o >>= 1) ss += __shfl_xor_sync(0xffffffffu, ss, o);
    float inv = 1.0f / fmaxf(sqrtf(ss), 1e-12f);
#pragma unroll
    for (int q = 0; q < 4; q++) out[(size_t)row * DIM + lane + q * 32] = v[q] * inv;
}

// ---------------- s1/s2 projections + global s2 max ---------------------------
__global__ void k_s12(const float* __restrict__ H, int ld, int Dr,
                      const float* __restrict__ a) {
    int w = threadIdx.x >> 5, lane = threadIdx.x & 31;
    int row = blockIdx.x * 8 + w;
    const float* r = H + (size_t)row * ld;
    float p1 = 0.f, p2 = 0.f;
    for (int c = lane; c < Dr; c += 32) {
        float v = r[c];
        p1 = fmaf(v, a[c], p1);
        p2 = fmaf(v, a[Dr + c], p2);
    }
#pragma unroll
    for (int o = 16; o > 0; o >>= 1) {
        p1 += __shfl_xor_sync(0xffffffffu, p1, o);
        p2 += __shfl_xor_sync(0xffffffffu, p2, o);
    }
    if (lane == 0) {
        g_s1[row] = p1; g_s2[row] = p2;
        atomicMax(&g_s2maxu, encf(p2));
    }
}

// ---------------- per-node attention precompute -------------------------------
__global__ void k_prep() {
    int i = blockIdx.x * 256 + threadIdx.x;
    float gmax = decf(g_s2maxu);
    float s1 = g_s1[i], s2 = g_s2[i];
    float u = s1 + gmax;
    float m = (u > 0.f) ? u : 0.25f * u;
    g_pa[i] = fexp(s1 - m);
    g_pb[i] = fexp(0.25f * s1 - m);
    g_pth[i] = -s1;
    g_peg[i] = fexp(s2);
    g_peq[i] = fexp(0.25f * s2);
}

// ---------------- column mean (deterministic 2-stage) -------------------------
template<int BN>
__global__ void k_colmean1(const float* __restrict__ H) {
    int t = threadIdx.x;
    int r0 = blockIdx.x * 128;
    float s = 0.f;
    for (int r = 0; r < 128; r++) s += H[(size_t)(r0 + r) * BN + t];
    g_cmp[blockIdx.x * DIM + t] = s;
}
__global__ void k_colmean2(int BN) {
    int t = threadIdx.x;
    float s = 0.f;
    if (t < BN) for (int b = 0; b < 64; b++) s += g_cmp[b * DIM + t];
    g_cm[t] = s * (1.0f / NN);
}

// ================== TMA-fed FP8 mma.sync kernel (64x64 per CTA) ===============
// f16 accumulators drained to f32 every 8 chunks (1024 K) for accuracy.
// grid (NN/64 row blocks, Ncols/64 col blocks). Chunk = 128 K fp8.
// MODE 0: Out = resid + adj @ H
// MODE 1: P_ij = adj_ij*(s2_j>=th_i ? a_i*eg_j : b_i*eq_j) e4m3;
//         Out_i = elu(P@H / d_i) (d_i==0 -> colmean), opt accumulate.
#define TNST 4
struct TAux {
    u8 Phi[64][144];
    float A[64], B[64], Th[64], D[64];
    u64 bar[TNST];
};

template<int MODE>
__global__ void __launch_bounds__(256) k_tmma(
    const __grid_constant__ CUtensorMap mAdj,
    const __grid_constant__ CUtensorMap mH,
    const float* __restrict__ resid,
    float* __restrict__ Out, int ldo, int accum)
{
    constexpr int BK = 128, NT = NN / BK;   // 64 chunks
    constexpr u32 STAGE_B = 2 * 8192;       // adj tile + H tile

    extern __shared__ char raw[];
    TAux& X = *reinterpret_cast<TAux*>(raw);
    const u32 tiles_u = (smem_u32(raw) + (u32)sizeof(TAux) + 1023u) & ~1023u;
    char* tiles_p = raw + (tiles_u - smem_u32(raw));

    const int t = threadIdx.x, lane = t & 31, warp = t >> 5;
    const int i0 = blockIdx.x * 64, co = blockIdx.y * 64;
    const int wm = warp >> 1, wn = warp & 1;       // 4x2 warp grid, 16x32 each
    const int pr = warp * 8 + (lane >> 2);         // P-gen row
    const int pc = (lane & 3) * 32;                // P-gen byte-col start

    if (MODE && t < 64) {
        X.A[t] = g_pa[i0 + t]; X.B[t] = g_pb[i0 + t]; X.Th[t] = g_pth[i0 + t];
    }
    if (t == 0)
        for (int s = 0; s < TNST; s++) mbar_init(smem_u32(&X.bar[s]), 1);
    __syncthreads();
    float ai = 0.f, bi = 0.f, thi = 0.f;
    if (MODE) { ai = X.A[pr]; bi = X.B[pr]; thi = X.Th[pr]; }

    if (t == 0) {
#pragma unroll
        for (int s = 0; s < 3; s++) {
            u32 bar = smem_u32(&X.bar[s]);
            mbar_expect(bar, STAGE_B);
            u32 st = tiles_u + s * STAGE_B;
            tma2d(st,        &mAdj, s * 128, i0, bar);
            tma2d(st + 8192, &mH,   s * 128, co, bar);
        }
    }

    u32   hacc[4][2];     // f16x2 MMA accumulators
    float facc[4][4];     // f32 drain accumulators
#pragma unroll
    for (int b = 0; b < 4; b++) {
        hacc[b][0] = 0u; hacc[b][1] = 0u;
#pragma unroll
        for (int c = 0; c < 4; c++) facc[b][c] = 0.f;
    }
    float dpart = 0.f;

    for (int kt = 0; kt < NT; kt++) {
        const int cur = kt & 3, k0 = kt * BK;
        const u32 stg = tiles_u + cur * STAGE_B;
        mbar_wait(smem_u32(&X.bar[cur]), (kt >> 2) & 1);

        if (MODE) {
            const char* adjp = tiles_p + cur * STAGE_B;
            u32 off = (u32)pr * 128 + (u32)pc;
            uint4 av0 = *(const uint4*)(adjp + swz(off));
            uint4 av1 = *(const uint4*)(adjp + swz(off + 16));
            u8 ab[32];
            *(uint4*)ab = av0; *(uint4*)(ab + 16) = av1;
            u8 pq[32];
            const float* s2 = g_s2  + k0 + pc;
            const float* eg = g_peg + k0 + pc;
            const float* eq = g_peq + k0 + pc;
#pragma unroll
            for (int c = 0; c < 16; c++) {
                int c0 = 2 * c, c1 = 2 * c + 1;
                float2 fv;
                fv.x = ab[c0] ? ((s2[c0] >= thi) ? ai * eg[c0] : bi * eq[c0]) : 0.f;
                fv.y = ab[c1] ? ((s2[c1] >= thi) ? ai * eg[c1] : bi * eq[c1]) : 0.f;
                __nv_fp8x2_storage_t qq = __nv_cvt_float2_to_fp8x2(fv, __NV_SATFINITE, __NV_E4M3);
                *(u16*)(pq + 2 * c) = qq;
                __half2_raw hr = __nv_cvt_fp8x2_to_halfraw2(qq, __NV_E4M3);
                float2 dv = __half22float2(*(__half2*)&hr);
                dpart += dv.x + dv.y;
            }
            *(uint4*)&X.Phi[pr][pc]      = *(uint4*)pq;
            *(uint4*)&X.Phi[pr][pc + 16] = *(uint4*)(pq + 16);
            __syncthreads();
        }

#pragma unroll
        for (int kk = 0; kk < 4; kk++) {    // 4 x k32 = 128 K per chunk
            u32 ah[4];
            {
                int rr = wm * 16 + (lane & 15);
                u32 boff = (u32)kk * 32 + ((u32)(lane >> 4)) * 16;
                u32 a = MODE ? smem_u32(&X.Phi[rr][0]) + boff
                             : stg + swz((u32)rr * 128 + boff);
                ldm_x4(a, ah);
            }
            u32 bh[4][2];
#pragma unroll
            for (int fp2 = 0; fp2 < 2; fp2++) {
                int nb = wn * 32 + fp2 * 16;
                u32 rowN = (u32)nb + (u32)(lane & 7) + (((u32)lane >> 4) << 3);
                u32 a = stg + 8192
                      + swz(rowN * 128 + (u32)kk * 32 + (((u32)lane >> 3) & 1) * 16);
                u32 r4[4];
                ldm_x4(a, r4);
                bh[2*fp2][0] = r4[0]; bh[2*fp2][1] = r4[1];
                bh[2*fp2+1][0] = r4[2]; bh[2*fp2+1][1] = r4[3];
            }
#pragma unroll
            for (int fn = 0; fn < 4; fn++)
                mma_e4m3_h(hacc[fn], ah, bh[fn]);
        }

        // drain f16 accumulators to f32 every 8 chunks (keeps rounding noise ~ulp)
        if ((kt & 7) == 7) {
#pragma unroll
            for (int fn = 0; fn < 4; fn++) {
                float2 lo = __half22float2(*(__half2*)&hacc[fn][0]);
                float2 hi = __half22float2(*(__half2*)&hacc[fn][1]);
                facc[fn][0] += lo.x; facc[fn][1] += lo.y;
                facc[fn][2] += hi.x; facc[fn][3] += hi.y;
                hacc[fn][0] = 0u; hacc[fn][1] = 0u;
            }
        }
        __syncthreads();

        if (t == 0 && kt + 3 < NT) {
            const int s = (kt + 3) & 3;
            u32 bar = smem_u32(&X.bar[s]);
            mbar_expect(bar, STAGE_B);
            u32 st = tiles_u + s * STAGE_B;
            tma2d(st,        &mAdj, (kt + 3) * 128, i0, bar);
            tma2d(st + 8192, &mH,   (kt + 3) * 128, co, bar);
        }
    }

    if (MODE) {
        dpart += __shfl_xor_sync(0xffffffffu, dpart, 1);
        dpart += __shfl_xor_sync(0xffffffffu, dpart, 2);
        if ((lane & 3) == 0) X.D[pr] = dpart;
    }
    __syncthreads();

#pragma unroll
    for (int h = 0; h < 2; h++) {
        int rl = wm * 16 + (lane >> 2) + h * 8;
        int row = i0 + rl;
#pragma unroll
        for (int fn = 0; fn < 4; fn++) {
            int col = co + wn * 32 + fn * 8 + (lane & 3) * 2;
            float v0 = facc[fn][2 * h], v1 = facc[fn][2 * h + 1];
            float* op = Out + (size_t)row * ldo + col;
            if (MODE == 0) {
                float2 rr = *(const float2*)(resid + (size_t)row * ldo + col);
                float2 o; o.x = v0 + rr.x; o.y = v1 + rr.y;
                *(float2*)op = o;
            } else {
                float dd = X.D[rl];
                if (dd > 0.f) { float inv = 1.0f / dd; v0 *= inv; v1 *= inv; }
                else          { v0 = g_cm[col]; v1 = g_cm[col + 1]; }
                v0 = (v0 > 0.f) ? v0 : fexp(v0) - 1.0f;
                v1 = (v1 > 0.f) ? v1 : fexp(v1) - 1.0f;
                if (accum) {
                    float2 zz = *(const float2*)op;
                    v0 += zz.x; v1 += zz.y;
                }
                float2 o; o.x = v0; o.y = v1;
                *(float2*)op = o;
            }
        }
    }
    __syncthreads();
    if (t == 0)
        for (int s = 0; s < TNST; s++) mbar_inval(smem_u32(&X.bar[s]));
}

// ---------------- dense GEMM: 64x64 per CTA, single K=128 shot ----------------
// grid (NN/64, Ncols/64). C = act(scale*(A@B) + bias), fp32.
__global__ void __launch_bounds__(256) k_gemm(
        const float* __restrict__ A,
        const float* __restrict__ B, int ldb,
        const float* __restrict__ bias,
        float* __restrict__ C, int ldc,
        float scale, int relu, int rst)
{
    extern __shared__ float sm[];
    float (*As)[65] = (float(*)[65])sm;                  // [128][65]
    float (*Bs)[64] = (float(*)[64])(sm + 128 * 65);     // [128][64]
    const int t = threadIdx.x;
    const int row0 = blockIdx.x * 64, co = blockIdx.y * 64;

    if (rst && blockIdx.x == 0 && blockIdx.y == 0 && t == 0) g_s2maxu = 0u;

#pragma unroll
    for (int l = 0; l < 32; l++) {
        int idx = t + l * 256;
        int m = idx >> 7, k = idx & 127;
        As[k][m] = A[(size_t)(row0 + m) * DIM + k];
    }
#pragma unroll
    for (int l = 0; l < 32; l++) {
        int idx = t + l * 256;
        int k = idx >> 6, c = idx & 63;
        Bs[k][c] = B[(size_t)k * ldb + co + c];
    }
    __syncthreads();

    const int tx = t & 15, ty = t >> 4;
    u64 acc[4][2];
#pragma unroll
    for (int i = 0; i < 4; i++) { acc[i][0] = 0ULL; acc[i][1] = 0ULL; }

#pragma unroll 4
    for (int k = 0; k < 128; k++) {
        float a0 = As[k][ty * 4 + 0];
        float a1 = As[k][ty * 4 + 1];
        float a2 = As[k][ty * 4 + 2];
        float a3 = As[k][ty * 4 + 3];
        u64 b0 = *(const u64*)&Bs[k][tx * 4];
        u64 b1 = *(const u64*)&Bs[k][tx * 4 + 2];
        fma2(acc[0][0], pk2(a0, a0), b0); fma2(acc[0][1], pk2(a0, a0), b1);
        fma2(acc[1][0], pk2(a1, a1), b0); fma2(acc[1][1], pk2(a1, a1), b1);
        fma2(acc[2][0], pk2(a2, a2), b0); fma2(acc[2][1], pk2(a2, a2), b1);
        fma2(acc[3][0], pk2(a3, a3), b0); fma2(acc[3][1], pk2(a3, a3), b1);
    }
#pragma unroll
    for (int i = 0; i < 4; i++) {
        int m = row0 + ty * 4 + i;
#pragma unroll
        for (int j = 0; j < 2; j++) {
            int c = co + tx * 4 + 2 * j;
            float lo, hi; upk2(acc[i][j], lo, hi);
            float v0 = scale * lo, v1 = scale * hi;
            if (bias)  { v0 += bias[c]; v1 += bias[c + 1]; }
            if (relu)  { v0 = fmaxf(v0, 0.f); v1 = fmaxf(v1, 0.f); }
            float2 o; o.x = v0; o.y = v1;
            *(float2*)&C[(size_t)m * ldc + c] = o;
        }
    }
}

// ---------------- row softmax over first 56 of 64 cols ------------------------
__global__ void k_smax56(float* __restrict__ X) {
    int w = threadIdx.x >> 5, lane = threadIdx.x & 31;
    int row = blockIdx.x * 8 + w;
    float* r = X + (size_t)row * ODP;
    float v0 = (lane < OD)      ? r[lane]      : -3e38f;
    float v1 = (lane + 32 < OD) ? r[lane + 32] : -3e38f;
    float m = fmaxf(v0, v1);
#pragma unroll
    for (int o = 16; o > 0; o >>= 1) m = fmaxf(m, __shfl_xor_sync(0xffffffffu, m, o));
    float e0 = (lane < OD)      ? fexp(v0 - m) : 0.f;
    float e1 = (lane + 32 < OD) ? fexp(v1 - m) : 0.f;
    float s = e0 + e1;
#pragma unroll
    for (int o = 16; o > 0; o >>= 1) s += __shfl_xor_sync(0xffffffffu, s, o);
    float inv = 1.0f / s;
    if (lane < OD)      r[lane]      = e0 * inv;
    if (lane + 32 < OD) r[lane + 32] = e1 * inv;
}

// ---------------- segment-sum readout + MLP head ------------------------------
__global__ void k_head(const int* __restrict__ seg,
                       const float* __restrict__ Wout, const float* __restrict__ bout,
                       const float* __restrict__ Wprop, const float* __restrict__ bprop,
                       float* __restrict__ out)
{
    __shared__ float v[OD];
    __shared__ float o[OD];
    __shared__ int bnd[2];
    const int m = blockIdx.x, t = threadIdx.x;
    if (t < 2) {
        int target = m + t;
        int lo = 0, hi = NN;
        while (lo < hi) { int mid = (lo + hi) >> 1; if (seg[mid] < target) lo = mid + 1; else hi = mid; }
        bnd[t] = lo;
    }
    __syncthreads();
    int lo = bnd[0], hi = bnd[1];
    if (t < OD) {
        float s = 0.f;
        for (int i = lo; i < hi; i++) s += g_a56[(size_t)i * ODP + t];
        v[t] = s;
    }
    __syncthreads();
    for (int l = 0; l < 2; l++) {
        if (t < OD) {
            float s = bout[l * OD + t];
            const float* W = Wout + l * OD * OD;
            for (int k = 0; k < OD; k++) s = fmaf(v[k], W[k * OD + t], s);
            o[t] = fmaxf(s, 0.f);
        }
        __syncthreads();
        if (t < OD) v[t] = o[t];
        __syncthreads();
    }
    if (t < 2) {
        float s = bprop[t];
        for (int k = 0; k < OD; k++) s = fmaf(v[k], Wprop[k * 2 + t], s);
        float r;
        if (s >= 0.f) r = 1.0f / (1.0f + fexp(-s));
        else { float e = fexp(s); r = e / (1.0f + e); }
        out[m * 2 + t] = r;
    }
}

// ---------------- orchestration ----------------------------------------------
typedef CUresult (*tmap_fn_t)(CUtensorMap*, CUtensorMapDataType, cuuint32_t, void*,
                              const cuuint64_t*, const cuuint64_t*, const cuuint32_t*,
                              const cuuint32_t*, CUtensorMapInterleave, CUtensorMapSwizzle,
                              CUtensorMapL2promotion, CUtensorMapFloatOOBfill);

static void make_tmap8(tmap_fn_t fn, CUtensorMap* m, void* base,
                       unsigned long long d0, unsigned long long d1) {
    cuuint64_t dims[2] = { d0, d1 };
    cuuint64_t strides[1] = { d0 };
    cuuint32_t box[2] = { 128, 64 };
    cuuint32_t es[2] = { 1, 1 };
    fn(m, CU_TENSOR_MAP_DATA_TYPE_UINT8, 2, base, dims, strides, box, es,
       CU_TENSOR_MAP_INTERLEAVE_NONE, CU_TENSOR_MAP_SWIZZLE_128B,
       CU_TENSOR_MAP_L2_PROMOTION_L2_128B, CU_TENSOR_MAP_FLOAT_OOB_FILL_NONE);
}

extern "C" void kernel_launch(void* const* d_in, const int* in_sizes, int n_in,
                              void* d_out, int out_size) {
    const int*   fp   = (const int*)  d_in[0];
    const float* adj  = (const float*)d_in[1];
    const int*   seg  = (const int*)  d_in[2];
    const float* emb  = (const float*)d_in[3];
    const float* Wfp  = (const float*)d_in[4];
    const float* bfp  = (const float*)d_in[5];
    const float* Wh   = (const float*)d_in[6];
    const float* ah   = (const float*)d_in[7];
    const float* Woa  = (const float*)d_in[8];
    const float* aoa  = (const float*)d_in[9];
    const float* Wout = (const float*)d_in[10];
    const float* bout = (const float*)d_in[11];
    const float* Wpr  = (const float*)d_in[12];
    const float* bpr  = (const float*)d_in[13];
    float* out = (float*)d_out;

    float *x, *h, *tb, *z, *ho, *a56, *wpad;
    void *adj8_p, *h8T_p;
    cudaGetSymbolAddress((void**)&x,    g_x);
    cudaGetSymbolAddress((void**)&h,    g_h);
    cudaGetSymbolAddress((void**)&tb,   g_t);
    cudaGetSymbolAddress((void**)&z,    g_z);
    cudaGetSymbolAddress((void**)&ho,   g_ho);
    cudaGetSymbolAddress((void**)&a56,  g_a56);
    cudaGetSymbolAddress((void**)&wpad, g_wpad);
    cudaGetSymbolAddress(&adj8_p, g_adj8);
    cudaGetSymbolAddress(&h8T_p,  g_h8T);

    tmap_fn_t tmap_fn = nullptr;
    cudaDriverEntryPointQueryResult qr;
    cudaGetDriverEntryPointByVersion("cuTensorMapEncodeTiled", (void**)&tmap_fn,
                                     12000, cudaEnableDefault, &qr);
    static CUtensorMap mapAdj, mapHT, mapHT64;
    make_tmap8(tmap_fn, &mapAdj,  adj8_p, NN, NN);
    make_tmap8(tmap_fn, &mapHT,   h8T_p,  NN, DIM);
    make_tmap8(tmap_fn, &mapHT64, h8T_p,  NN, 64);

    const int SZT = (int)sizeof(TAux) + 1024 + TNST * 2 * 8192;   // ~76 KB
    const int SZG = (128 * 65 + 128 * 64) * 4;                    // ~66 KB
    cudaFuncSetAttribute(k_tmma<0>, cudaFuncAttributeMaxDynamicSharedMemorySize, SZT);
    cudaFuncSetAttribute(k_tmma<1>, cudaFuncAttributeMaxDynamicSharedMemorySize, SZT);
    cudaFuncSetAttribute(k_gemm,    cudaFuncAttributeMaxDynamicSharedMemorySize, SZG);

    k_gather<<<NN * DIM / 256, 256>>>(fp, emb);
    k_adjconv<<<(size_t)NN * NN / 2048, 256>>>(adj);
    k_padw<<<DIM * ODP / 256, 256>>>(Woa);

    // 3 message-passing layers
    for (int l = 0; l < 3; l++) {
        k_gemm<<<dim3(NN / 64, 2), 256, SZG>>>(x, Wfp + l * DIM * DIM, DIM,
                                               bfp + l * DIM, h, DIM, 1.f, 1, 0);
        k_transp8<<<dim3(NN / 64, DIM / 64), 256>>>(h, DIM);
        k_tmma<0><<<dim3(NN / 64, 2), 256, SZT>>>(mapAdj, mapHT, h, tb, DIM, 0);
        k_l2norm<<<NN / 8, 256>>>(tb, x);
    }

    // 2 GAT heads
    for (int hd = 0; hd < 2; hd++) {
        k_gemm<<<dim3(NN / 64, 2), 256, SZG>>>(x, Wh + hd * DIM * DIM, DIM,
                                               nullptr, h, DIM, 1.f, 0, 1);
        k_s12<<<NN / 8, 256>>>(h, DIM, DIM, ah + hd * 2 * DIM);
        k_prep<<<NN / 256, 256>>>();
        k_transp8<<<dim3(NN / 64, DIM / 64), 256>>>(h, DIM);
        k_colmean1<128><<<64, 128>>>(h);
        k_colmean2<<<1, 128>>>(128);
        k_tmma<1><<<dim3(NN / 64, 2), 256, SZT>>>(mapAdj, mapHT, nullptr, z, DIM, hd);
    }

    // out-attention at D=56 (padded to 64); x = z/2 folded into scale
    k_gemm<<<dim3(NN / 64, 1), 256, SZG>>>(z, wpad, ODP, nullptr, ho, ODP, 0.5f, 0, 1);
    k_s12<<<NN / 8, 256>>>(ho, ODP, OD, aoa);
    k_prep<<<NN / 256, 256>>>();
    k_transp8<<<dim3(NN / 64, 1), 256>>>(ho, ODP);
    k_colmean1<64><<<64, 64>>>(ho);
    k_colmean2<<<1, 128>>>(64);
    k_tmma<1><<<dim3(NN / 64, 1), 256, SZT>>>(mapAdj, mapHT64, nullptr, a56, ODP, 0);

    k_smax56<<<NN / 8, 256>>>(a56);
    k_head<<<NMOL, 64>>>(seg, Wout, bout, Wpr, bpr, out);
}

// round 12
// speedup vs baseline: 4.4535x; 1.0389x over previous
#include <cuda_runtime.h>
#include <cuda.h>
#include <cuda_bf16.h>
#include <cuda_fp16.h>
#include <cuda_fp8.h>
#include <math.h>

#define NN   8192
#define DIM  128
#define NMOL 256
#define OD   56
#define ODP  64

typedef unsigned long long u64;
typedef unsigned int u32;
typedef unsigned short u16;
typedef unsigned char u8;

// ---------------- f32x2 helpers ----------------------------------------------
__device__ __forceinline__ u64 pk2(float lo, float hi) {
    u64 r; asm("mov.b64 %0, {%1,%2};" : "=l"(r) : "f"(lo), "f"(hi)); return r;
}
__device__ __forceinline__ void upk2(u64 v, float &lo, float &hi) {
    asm("mov.b64 {%0,%1}, %2;" : "=f"(lo), "=f"(hi) : "l"(v));
}
__device__ __forceinline__ void fma2(u64 &d, u64 a, u64 b) {
    asm("fma.rn.f32x2 %0, %1, %2, %0;" : "+l"(d) : "l"(a), "l"(b));
}

// ---------------- FMA-only exp ------------------------------------------------
__device__ __forceinline__ float fexp(float x) {
    x = fmaxf(x, -87.0f);
    float y = x * 1.44269504f;
    float r = rintf(y);
    float f = y - r;
    float p = 1.33335581e-3f;
    p = fmaf(p, f, 9.61812911e-3f);
    p = fmaf(p, f, 5.55041087e-2f);
    p = fmaf(p, f, 2.40226507e-1f);
    p = fmaf(p, f, 6.93147181e-1f);
    p = fmaf(p, f, 1.0f);
    int e = (int)r;
    return p * __int_as_float((e + 127) << 23);
}

__device__ __forceinline__ u32 encf(float s) {
    u32 b = __float_as_uint(s);
    return (b & 0x80000000u) ? ~b : (b | 0x80000000u);
}
__device__ __forceinline__ float decf(u32 u) {
    return __uint_as_float((u & 0x80000000u) ? (u & 0x7fffffffu) : ~u);
}

// ---------------- MMA / ldmatrix helpers --------------------------------------
__device__ __forceinline__ u32 smem_u32(const void* p) {
    return (u32)__cvta_generic_to_shared(p);
}
__device__ __forceinline__ void ldm_x4(u32 a, u32* r) {
    asm volatile("ldmatrix.sync.aligned.m8n8.x4.shared.b16 {%0,%1,%2,%3}, [%4];"
        : "=r"(r[0]), "=r"(r[1]), "=r"(r[2]), "=r"(r[3]) : "r"(a));
}
// fp8 e4m3 MMA, f32 accum (proven R10 path)
__device__ __forceinline__ void mma_e4m3(float* c, const u32* a, const u32* b) {
    asm volatile(
        "mma.sync.aligned.m16n8k32.row.col.f32.e4m3.e4m3.f32 "
        "{%0,%1,%2,%3}, {%4,%5,%6,%7}, {%8,%9}, {%0,%1,%2,%3};"
        : "+f"(c[0]), "+f"(c[1]), "+f"(c[2]), "+f"(c[3])
        : "r"(a[0]), "r"(a[1]), "r"(a[2]), "r"(a[3]), "r"(b[0]), "r"(b[1]));
}
// int8 MMA, s32 accum (sm_80+ base; possibly 2x rate vs fp datapath)
__device__ __forceinline__ void mma_s8(int* c, const u32* a, const u32* b) {
    asm volatile(
        "mma.sync.aligned.m16n8k32.row.col.s32.s8.s8.s32 "
        "{%0,%1,%2,%3}, {%4,%5,%6,%7}, {%8,%9}, {%0,%1,%2,%3};"
        : "+r"(c[0]), "+r"(c[1]), "+r"(c[2]), "+r"(c[3])
        : "r"(a[0]), "r"(a[1]), "r"(a[2]), "r"(a[3]), "r"(b[0]), "r"(b[1]));
}

// ---------------- TMA / mbarrier ----------------------------------------------
__device__ __forceinline__ void tma2d(u32 dst, const void* map, int x, int y, u32 mbar) {
    asm volatile(
        "cp.async.bulk.tensor.2d.shared::cta.global.tile.mbarrier::complete_tx::bytes "
        "[%0], [%1, {%2, %3}], [%4];"
        :: "r"(dst), "l"(map), "r"(x), "r"(y), "r"(mbar) : "memory");
}
__device__ __forceinline__ void mbar_init(u32 a, u32 cnt) {
    asm volatile("mbarrier.init.shared.b64 [%0], %1;" :: "r"(a), "r"(cnt) : "memory");
}
__device__ __forceinline__ void mbar_expect(u32 a, u32 bytes) {
    asm volatile("mbarrier.arrive.expect_tx.shared.b64 _, [%0], %1;"
                 :: "r"(a), "r"(bytes) : "memory");
}
__device__ __forceinline__ void mbar_wait(u32 a, u32 parity) {
    asm volatile(
        "{\n\t.reg .pred P;\n\t"
        "W_%=:\n\t"
        "mbarrier.try_wait.parity.acquire.cta.shared::cta.b64 P, [%0], %1, 0x989680;\n\t"
        "@P bra.uni D_%=;\n\t"
        "bra.uni W_%=;\n\t"
        "D_%=:\n\t}"
        :: "r"(a), "r"(parity) : "memory");
}
__device__ __forceinline__ void mbar_inval(u32 a) {
    asm volatile("mbarrier.inval.shared.b64 [%0];" :: "r"(a) : "memory");
}
// standard 128B swizzle
__device__ __forceinline__ u32 swz(u32 o) { return o ^ ((o >> 3) & 0x70); }

// ---------------- scratch -----------------------------------------------------
__device__ u8 g_adj8[(size_t)NN * NN];    // 64 MB, exact 0/1 (byte 0x01)
__device__ u8 g_h8T[(size_t)DIM * NN];    // H^T, fp8 (MODE1) or s8 (MODE0)
__device__ float g_x [NN * DIM];
__device__ float g_h [NN * DIM];
__device__ float g_t [NN * DIM];
__device__ float g_z [NN * DIM];
__device__ float g_s1[NN];
__device__ float g_s2[NN];
__device__ u32   g_s2maxu;
__device__ float g_pa[NN], g_pb[NN], g_pth[NN], g_peg[NN], g_peq[NN];
__device__ float g_ho [NN * ODP];
__device__ float g_a56[NN * ODP];
__device__ float g_wpad[DIM * ODP];
__device__ float g_cm[DIM];
__device__ float g_cmp[64 * DIM];
__device__ float g_cmx[64 * DIM];     // column-max partials
__device__ float g_hsc[DIM];          // per-column dequant scale (cmax/127)
__device__ float g_hsi[DIM];          // per-column quant scale (127/cmax)

// ---------------- small utility kernels ---------------------------------------
__global__ void k_gather(const int* __restrict__ fp, const float* __restrict__ emb) {
    int idx = blockIdx.x * 256 + threadIdx.x;
    int i = idx >> 7, c = idx & 127;
    g_x[idx] = emb[fp[i] * DIM + c];
}

__global__ void k_padw(const float* __restrict__ W) {
    int idx = blockIdx.x * 256 + threadIdx.x;
    int k = idx >> 6, c = idx & 63;
    g_wpad[idx] = (c < OD) ? W[k * OD + c] : 0.0f;
}

// adj fp32 -> byte 0x01 (int8 value 1; also nonzero flag for MODE1 P-gen)
__global__ void k_adjconv(const float* __restrict__ adj) {
    size_t base = ((size_t)blockIdx.x * 256 + threadIdx.x) * 8;
    float4 a = *(const float4*)(adj + base);
    float4 b = *(const float4*)(adj + base + 4);
    u8 o[8];
    o[0] = a.x != 0.f ? 1 : 0; o[1] = a.y != 0.f ? 1 : 0;
    o[2] = a.z != 0.f ? 1 : 0; o[3] = a.w != 0.f ? 1 : 0;
    o[4] = b.x != 0.f ? 1 : 0; o[5] = b.y != 0.f ? 1 : 0;
    o[6] = b.z != 0.f ? 1 : 0; o[7] = b.w != 0.f ? 1 : 0;
    *(u64*)(g_adj8 + base) = *(u64*)o;
}

// per-feature-column abs-max, 2-stage deterministic
__global__ void k_cmax1(const float* __restrict__ H) {
    int t = threadIdx.x;          // feature (< DIM)
    int r0 = blockIdx.x * 128;
    float m = 0.f;
    for (int r = 0; r < 128; r++) m = fmaxf(m, fabsf(H[(size_t)(r0 + r) * DIM + t]));
    g_cmx[blockIdx.x * DIM + t] = m;
}
__global__ void k_cmax2() {
    int t = threadIdx.x;
    float m = 0.f;
    for (int b = 0; b < 64; b++) m = fmaxf(m, g_cmx[b * DIM + t]);
    g_hsc[t] = m * (1.0f / 127.0f);
    g_hsi[t] = (m > 0.f) ? 127.0f / m : 0.f;
}

// H [NN][DIM] fp32 -> H^T s8 per-column quantized; grid (NN/64, DIM/64)
__global__ void __launch_bounds__(256) k_transp8i(const float* __restrict__ H) {
    __shared__ float S[64][65];
    const int n0 = blockIdx.x * 64, f0 = blockIdx.y * 64;
    const int t = threadIdx.x, r = t >> 2, cb = t & 3;
#pragma unroll
    for (int q = 0; q < 4; q++) {
        float4 v = *(const float4*)&H[(size_t)(n0 + r) * DIM + f0 + cb * 16 + q * 4];
        S[r][cb * 16 + q * 4 + 0] = v.x; S[r][cb * 16 + q * 4 + 1] = v.y;
        S[r][cb * 16 + q * 4 + 2] = v.z; S[r][cb * 16 + q * 4 + 3] = v.w;
    }
    __syncthreads();
    const int f = t >> 2, nb = t & 3;
    const float si = g_hsi[f0 + f];
    char o[16];
#pragma unroll
    for (int q = 0; q < 16; q++) {
        float v = S[nb * 16 + q][f] * si;
        v = fminf(fmaxf(v, -127.f), 127.f);
        o[q] = (char)__float2int_rn(v);
    }
    *(uint4*)(g_h8T + (size_t)(f0 + f) * NN + n0 + nb * 16) = *(uint4*)o;
}

// H [NN][ldf] fp32 -> H^T fp8 e4m3; grid (NN/64, feats/64)
__global__ void __launch_bounds__(256) k_transp8(const float* __restrict__ H, int ldf) {
    __shared__ float S[64][65];
    const int n0 = blockIdx.x * 64, f0 = blockIdx.y * 64;
    const int t = threadIdx.x, r = t >> 2, cb = t & 3;
#pragma unroll
    for (int q = 0; q < 4; q++) {
        float4 v = *(const float4*)&H[(size_t)(n0 + r) * ldf + f0 + cb * 16 + q * 4];
        S[r][cb * 16 + q * 4 + 0] = v.x; S[r][cb * 16 + q * 4 + 1] = v.y;
        S[r][cb * 16 + q * 4 + 2] = v.z; S[r][cb * 16 + q * 4 + 3] = v.w;
    }
    __syncthreads();
    const int f = t >> 2, nb = t & 3;
    u8 o[16];
#pragma unroll
    for (int q = 0; q < 8; q++) {
        float2 fv;
        fv.x = S[nb * 16 + 2 * q][f];
        fv.y = S[nb * 16 + 2 * q + 1][f];
        __nv_fp8x2_storage_t qq = __nv_cvt_float2_to_fp8x2(fv, __NV_SATFINITE, __NV_E4M3);
        *(u16*)(o + 2 * q) = qq;
    }
    *(uint4*)(g_h8T + (size_t)(f0 + f) * NN + n0 + nb * 16) = *(uint4*)o;
}

// ---------------- row L2-normalize --------------------------------------------
__global__ void k_l2norm(const float* __restrict__ in, float* __restrict__ out) {
    int w = threadIdx.x >> 5, lane = threadIdx.x & 31;
    int row = blockIdx.x * 8 + w;
    const float* r = in + (size_t)row * DIM;
    float v[4], ss = 0.f;
#pragma unroll
    for (int q = 0; q < 4; q++) { v[q] = r[lane + q * 32]; ss += v[q] * v[q]; }
#pragma unroll
    for (int o = 16; o > 0; o >>= 1) ss += __shfl_xor_sync(0xffffffffu, ss, o);
    float inv = 1.0f / fmaxf(sqrtf(ss), 1e-12f);
#pragma unroll
    for (int q = 0; q < 4; q++) out[(size_t)row * DIM + lane + q * 32] = v[q] * inv;
}

// ---------------- s1/s2 projections + global s2 max ---------------------------
__global__ void k_s12(const float* __restrict__ H, int ld, int Dr,
                      const float* __restrict__ a) {
    int w = threadIdx.x >> 5, lane = threadIdx.x & 31;
    int row = blockIdx.x * 8 + w;
    const float* r = H + (size_t)row * ld;
    float p1 = 0.f, p2 = 0.f;
    for (int c = lane; c < Dr; c += 32) {
        float v = r[c];
        p1 = fmaf(v, a[c], p1);
        p2 = fmaf(v, a[Dr + c], p2);
    }
#pragma unroll
    for (int o = 16; o > 0; o >>= 1) {
        p1 += __shfl_xor_sync(0xffffffffu, p1, o);
        p2 += __shfl_xor_sync(0xffffffffu, p2, o);
    }
    if (lane == 0) {
        g_s1[row] = p1; g_s2[row] = p2;
        atomicMax(&g_s2maxu, encf(p2));
    }
}

// ---------------- per-node attention precompute -------------------------------
__global__ void k_prep() {
    int i = blockIdx.x * 256 + threadIdx.x;
    float gmax = decf(g_s2maxu);
    float s1 = g_s1[i], s2 = g_s2[i];
    float u = s1 + gmax;
    float m = (u > 0.f) ? u : 0.25f * u;
    g_pa[i] = fexp(s1 - m);
    g_pb[i] = fexp(0.25f * s1 - m);
    g_pth[i] = -s1;
    g_peg[i] = fexp(s2);
    g_peq[i] = fexp(0.25f * s2);
}

// ---------------- column mean (deterministic 2-stage) -------------------------
template<int BN>
__global__ void k_colmean1(const float* __restrict__ H) {
    int t = threadIdx.x;
    int r0 = blockIdx.x * 128;
    float s = 0.f;
    for (int r = 0; r < 128; r++) s += H[(size_t)(r0 + r) * BN + t];
    g_cmp[blockIdx.x * DIM + t] = s;
}
__global__ void k_colmean2(int BN) {
    int t = threadIdx.x;
    float s = 0.f;
    if (t < BN) for (int b = 0; b < 64; b++) s += g_cmp[b * DIM + t];
    g_cm[t] = s * (1.0f / NN);
}

// ================== TMA-fed 8-bit mma.sync kernel (64x64 per CTA) =============
// grid (NN/64 row blocks, Ncols/64 col blocks). Chunk = 128 K.
// MODE 0: s8 x s8 -> s32 exact; Out = resid + (adj @ Hq) * colscale
// MODE 1: e4m3 f32-acc; P_ij = adj_ij*(s2_j>=th_i ? a_i*eg_j : b_i*eq_j) e4m3;
//         Out_i = elu(P@H / d_i) (d_i==0 -> colmean), opt accumulate.
#define TNST 4
struct TAux {
    u8 Phi[64][144];
    float A[64], B[64], Th[64], D[64];
    u64 bar[TNST];
};

template<int MODE>
__global__ void __launch_bounds__(256) k_tmma(
    const __grid_constant__ CUtensorMap mAdj,
    const __grid_constant__ CUtensorMap mH,
    const float* __restrict__ resid,
    float* __restrict__ Out, int ldo, int accum)
{
    constexpr int BK = 128, NT = NN / BK;   // 64 chunks
    constexpr u32 STAGE_B = 2 * 8192;       // adj tile + H tile

    extern __shared__ char raw[];
    TAux& X = *reinterpret_cast<TAux*>(raw);
    const u32 tiles_u = (smem_u32(raw) + (u32)sizeof(TAux) + 1023u) & ~1023u;
    char* tiles_p = raw + (tiles_u - smem_u32(raw));

    const int t = threadIdx.x, lane = t & 31, warp = t >> 5;
    const int i0 = blockIdx.x * 64, co = blockIdx.y * 64;
    const int wm = warp >> 1, wn = warp & 1;       // 4x2 warp grid, 16x32 each
    const int pr = warp * 8 + (lane >> 2);         // P-gen row
    const int pc = (lane & 3) * 32;                // P-gen byte-col start

    if (MODE && t < 64) {
        X.A[t] = g_pa[i0 + t]; X.B[t] = g_pb[i0 + t]; X.Th[t] = g_pth[i0 + t];
    }
    if (t == 0)
        for (int s = 0; s < TNST; s++) mbar_init(smem_u32(&X.bar[s]), 1);
    __syncthreads();
    float ai = 0.f, bi = 0.f, thi = 0.f;
    if (MODE) { ai = X.A[pr]; bi = X.B[pr]; thi = X.Th[pr]; }

    if (t == 0) {
#pragma unroll
        for (int s = 0; s < 3; s++) {
            u32 bar = smem_u32(&X.bar[s]);
            mbar_expect(bar, STAGE_B);
            u32 st = tiles_u + s * STAGE_B;
            tma2d(st,        &mAdj, s * 128, i0, bar);
            tma2d(st + 8192, &mH,   s * 128, co, bar);
        }
    }

    float facc[4][4];
    int   iacc[4][4];
#pragma unroll
    for (int b = 0; b < 4; b++)
#pragma unroll
        for (int c = 0; c < 4; c++) { facc[b][c] = 0.f; iacc[b][c] = 0; }
    float dpart = 0.f;

    for (int kt = 0; kt < NT; kt++) {
        const int cur = kt & 3, k0 = kt * BK;
        const u32 stg = tiles_u + cur * STAGE_B;
        mbar_wait(smem_u32(&X.bar[cur]), (kt >> 2) & 1);

        if (MODE) {
            const char* adjp = tiles_p + cur * STAGE_B;
            u32 off = (u32)pr * 128 + (u32)pc;
            uint4 av0 = *(const uint4*)(adjp + swz(off));
            uint4 av1 = *(const uint4*)(adjp + swz(off + 16));
            u8 ab[32];
            *(uint4*)ab = av0; *(uint4*)(ab + 16) = av1;
            u8 pq[32];
            const float* s2 = g_s2  + k0 + pc;
            const float* eg = g_peg + k0 + pc;
            const float* eq = g_peq + k0 + pc;
#pragma unroll
            for (int c = 0; c < 16; c++) {
                int c0 = 2 * c, c1 = 2 * c + 1;
                float2 fv;
                fv.x = ab[c0] ? ((s2[c0] >= thi) ? ai * eg[c0] : bi * eq[c0]) : 0.f;
                fv.y = ab[c1] ? ((s2[c1] >= thi) ? ai * eg[c1] : bi * eq[c1]) : 0.f;
                __nv_fp8x2_storage_t qq = __nv_cvt_float2_to_fp8x2(fv, __NV_SATFINITE, __NV_E4M3);
                *(u16*)(pq + 2 * c) = qq;
                __half2_raw hr = __nv_cvt_fp8x2_to_halfraw2(qq, __NV_E4M3);
                float2 dv = __half22float2(*(__half2*)&hr);
                dpart += dv.x + dv.y;
            }
            *(uint4*)&X.Phi[pr][pc]      = *(uint4*)pq;
            *(uint4*)&X.Phi[pr][pc + 16] = *(uint4*)(pq + 16);
            __syncthreads();
        }

#pragma unroll
        for (int kk = 0; kk < 4; kk++) {    // 4 x k32 = 128 K per chunk
            u32 ah[4];
            {
                int rr = wm * 16 + (lane & 15);
                u32 boff = (u32)kk * 32 + ((u32)(lane >> 4)) * 16;
                u32 a = MODE ? smem_u32(&X.Phi[rr][0]) + boff
                             : stg + swz((u32)rr * 128 + boff);
                ldm_x4(a, ah);
            }
            u32 bh[4][2];
#pragma unroll
            for (int fp2 = 0; fp2 < 2; fp2++) {
                int nb = wn * 32 + fp2 * 16;
                u32 rowN = (u32)nb + (u32)(lane & 7) + (((u32)lane >> 4) << 3);
                u32 a = stg + 8192
                      + swz(rowN * 128 + (u32)kk * 32 + (((u32)lane >> 3) & 1) * 16);
                u32 r4[4];
                ldm_x4(a, r4);
                bh[2*fp2][0] = r4[0]; bh[2*fp2][1] = r4[1];
                bh[2*fp2+1][0] = r4[2]; bh[2*fp2+1][1] = r4[3];
            }
#pragma unroll
            for (int fn = 0; fn < 4; fn++) {
                if (MODE) mma_e4m3(facc[fn], ah, bh[fn]);
                else      mma_s8  (iacc[fn], ah, bh[fn]);
            }
        }
        __syncthreads();

        if (t == 0 && kt + 3 < NT) {
            const int s = (kt + 3) & 3;
            u32 bar = smem_u32(&X.bar[s]);
            mbar_expect(bar, STAGE_B);
            u32 st = tiles_u + s * STAGE_B;
            tma2d(st,        &mAdj, (kt + 3) * 128, i0, bar);
            tma2d(st + 8192, &mH,   (kt + 3) * 128, co, bar);
        }
    }

    if (MODE) {
        dpart += __shfl_xor_sync(0xffffffffu, dpart, 1);
        dpart += __shfl_xor_sync(0xffffffffu, dpart, 2);
        if ((lane & 3) == 0) X.D[pr] = dpart;
    }
    __syncthreads();

#pragma unroll
    for (int h = 0; h < 2; h++) {
        int rl = wm * 16 + (lane >> 2) + h * 8;
        int row = i0 + rl;
#pragma unroll
        for (int fn = 0; fn < 4; fn++) {
            int col = co + wn * 32 + fn * 8 + (lane & 3) * 2;
            float* op = Out + (size_t)row * ldo + col;
            if (MODE == 0) {
                float v0 = (float)iacc[fn][2 * h]     * g_hsc[col];
                float v1 = (float)iacc[fn][2 * h + 1] * g_hsc[col + 1];
                float2 rr = *(const float2*)(resid + (size_t)row * ldo + col);
                float2 o; o.x = v0 + rr.x; o.y = v1 + rr.y;
                *(float2*)op = o;
            } else {
                float v0 = facc[fn][2 * h], v1 = facc[fn][2 * h + 1];
                float dd = X.D[rl];
                if (dd > 0.f) { float inv = 1.0f / dd; v0 *= inv; v1 *= inv; }
                else          { v0 = g_cm[col]; v1 = g_cm[col + 1]; }
                v0 = (v0 > 0.f) ? v0 : fexp(v0) - 1.0f;
                v1 = (v1 > 0.f) ? v1 : fexp(v1) - 1.0f;
                if (accum) {
                    float2 zz = *(const float2*)op;
                    v0 += zz.x; v1 += zz.y;
                }
                float2 o; o.x = v0; o.y = v1;
                *(float2*)op = o;
            }
        }
    }
    __syncthreads();
    if (t == 0)
        for (int s = 0; s < TNST; s++) mbar_inval(smem_u32(&X.bar[s]));
}

// ---------------- dense GEMM: 64x64 per CTA, single K=128 shot ----------------
__global__ void __launch_bounds__(256) k_gemm(
        const float* __restrict__ A,
        const float* __restrict__ B, int ldb,
        const float* __restrict__ bias,
        float* __restrict__ C, int ldc,
        float scale, int relu, int rst)
{
    extern __shared__ float sm[];
    float (*As)[65] = (float(*)[65])sm;                  // [128][65]
    float (*Bs)[64] = (float(*)[64])(sm + 128 * 65);     // [128][64]
    const int t = threadIdx.x;
    const int row0 = blockIdx.x * 64, co = blockIdx.y * 64;

    if (rst && blockIdx.x == 0 && blockIdx.y == 0 && t == 0) g_s2maxu = 0u;

#pragma unroll
    for (int l = 0; l < 32; l++) {
        int idx = t + l * 256;
        int m = idx >> 7, k = idx & 127;
        As[k][m] = A[(size_t)(row0 + m) * DIM + k];
    }
#pragma unroll
    for (int l = 0; l < 32; l++) {
        int idx = t + l * 256;
        int k = idx >> 6, c = idx & 63;
        Bs[k][c] = B[(size_t)k * ldb + co + c];
    }
    __syncthreads();

    const int tx = t & 15, ty = t >> 4;
    u64 acc[4][2];
#pragma unroll
    for (int i = 0; i < 4; i++) { acc[i][0] = 0ULL; acc[i][1] = 0ULL; }

#pragma unroll 4
    for (int k = 0; k < 128; k++) {
        float a0 = As[k][ty * 4 + 0];
        float a1 = As[k][ty * 4 + 1];
        float a2 = As[k][ty * 4 + 2];
        float a3 = As[k][ty * 4 + 3];
        u64 b0 = *(const u64*)&Bs[k][tx * 4];
        u64 b1 = *(const u64*)&Bs[k][tx * 4 + 2];
        fma2(acc[0][0], pk2(a0, a0), b0); fma2(acc[0][1], pk2(a0, a0), b1);
        fma2(acc[1][0], pk2(a1, a1), b0); fma2(acc[1][1], pk2(a1, a1), b1);
        fma2(acc[2][0], pk2(a2, a2), b0); fma2(acc[2][1], pk2(a2, a2), b1);
        fma2(acc[3][0], pk2(a3, a3), b0); fma2(acc[3][1], pk2(a3, a3), b1);
    }
#pragma unroll
    for (int i = 0; i < 4; i++) {
        int m = row0 + ty * 4 + i;
#pragma unroll
        for (int j = 0; j < 2; j++) {
            int c = co + tx * 4 + 2 * j;
            float lo, hi; upk2(acc[i][j], lo, hi);
            float v0 = scale * lo, v1 = scale * hi;
            if (bias)  { v0 += bias[c]; v1 += bias[c + 1]; }
            if (relu)  { v0 = fmaxf(v0, 0.f); v1 = fmaxf(v1, 0.f); }
            float2 o; o.x = v0; o.y = v1;
            *(float2*)&C[(size_t)m * ldc + c] = o;
        }
    }
}

// ---------------- row softmax over first 56 of 64 cols ------------------------
__global__ void k_smax56(float* __restrict__ X) {
    int w = threadIdx.x >> 5, lane = threadIdx.x & 31;
    int row = blockIdx.x * 8 + w;
    float* r = X + (size_t)row * ODP;
    float v0 = (lane < OD)      ? r[lane]      : -3e38f;
    float v1 = (lane + 32 < OD) ? r[lane + 32] : -3e38f;
    float m = fmaxf(v0, v1);
#pragma unroll
    for (int o = 16; o > 0; o >>= 1) m = fmaxf(m, __shfl_xor_sync(0xffffffffu, m, o));
    float e0 = (lane < OD)      ? fexp(v0 - m) : 0.f;
    float e1 = (lane + 32 < OD) ? fexp(v1 - m) : 0.f;
    float s = e0 + e1;
#pragma unroll
    for (int o = 16; o > 0; o >>= 1) s += __shfl_xor_sync(0xffffffffu, s, o);
    float inv = 1.0f / s;
    if (lane < OD)      r[lane]      = e0 * inv;
    if (lane + 32 < OD) r[lane + 32] = e1 * inv;
}

// ---------------- segment-sum readout + MLP head ------------------------------
__global__ void k_head(const int* __restrict__ seg,
                       const float* __restrict__ Wout, const float* __restrict__ bout,
                       const float* __restrict__ Wprop, const float* __restrict__ bprop,
                       float* __restrict__ out)
{
    __shared__ float v[OD];
    __shared__ float o[OD];
    __shared__ int bnd[2];
    const int m = blockIdx.x, t = threadIdx.x;
    if (t < 2) {
        int target = m + t;
        int lo = 0, hi = NN;
        while (lo < hi) { int mid = (lo + hi) >> 1; if (seg[mid] < target) lo = mid + 1; else hi = mid; }
        bnd[t] = lo;
    }
    __syncthreads();
    int lo = bnd[0], hi = bnd[1];
    if (t < OD) {
        float s = 0.f;
        for (int i = lo; i < hi; i++) s += g_a56[(size_t)i * ODP + t];
        v[t] = s;
    }
    __syncthreads();
    for (int l = 0; l < 2; l++) {
        if (t < OD) {
            float s = bout[l * OD + t];
            const float* W = Wout + l * OD * OD;
            for (int k = 0; k < OD; k++) s = fmaf(v[k], W[k * OD + t], s);
            o[t] = fmaxf(s, 0.f);
        }
        __syncthreads();
        if (t < OD) v[t] = o[t];
        __syncthreads();
    }
    if (t < 2) {
        float s = bprop[t];
        for (int k = 0; k < OD; k++) s = fmaf(v[k], Wprop[k * 2 + t], s);
        float r;
        if (s >= 0.f) r = 1.0f / (1.0f + fexp(-s));
        else { float e = fexp(s); r = e / (1.0f + e); }
        out[m * 2 + t] = r;
    }
}

// ---------------- orchestration ----------------------------------------------
typedef CUresult (*tmap_fn_t)(CUtensorMap*, CUtensorMapDataType, cuuint32_t, void*,
                              const cuuint64_t*, const cuuint64_t*, const cuuint32_t*,
                              const cuuint32_t*, CUtensorMapInterleave, CUtensorMapSwizzle,
                              CUtensorMapL2promotion, CUtensorMapFloatOOBfill);

static void make_tmap8(tmap_fn_t fn, CUtensorMap* m, void* base,
                       unsigned long long d0, unsigned long long d1) {
    cuuint64_t dims[2] = { d0, d1 };
    cuuint64_t strides[1] = { d0 };
    cuuint32_t box[2] = { 128, 64 };
    cuuint32_t es[2] = { 1, 1 };
    fn(m, CU_TENSOR_MAP_DATA_TYPE_UINT8, 2, base, dims, strides, box, es,
       CU_TENSOR_MAP_INTERLEAVE_NONE, CU_TENSOR_MAP_SWIZZLE_128B,
       CU_TENSOR_MAP_L2_PROMOTION_L2_128B, CU_TENSOR_MAP_FLOAT_OOB_FILL_NONE);
}

extern "C" void kernel_launch(void* const* d_in, const int* in_sizes, int n_in,
                              void* d_out, int out_size) {
    const int*   fp   = (const int*)  d_in[0];
    const float* adj  = (const float*)d_in[1];
    const int*   seg  = (const int*)  d_in[2];
    const float* emb  = (const float*)d_in[3];
    const float* Wfp  = (const float*)d_in[4];
    const float* bfp  = (const float*)d_in[5];
    const float* Wh   = (const float*)d_in[6];
    const float* ah   = (const float*)d_in[7];
    const float* Woa  = (const float*)d_in[8];
    const float* aoa  = (const float*)d_in[9];
    const float* Wout = (const float*)d_in[10];
    const float* bout = (const float*)d_in[11];
    const float* Wpr  = (const float*)d_in[12];
    const float* bpr  = (const float*)d_in[13];
    float* out = (float*)d_out;

    float *x, *h, *tb, *z, *ho, *a56, *wpad;
    void *adj8_p, *h8T_p;
    cudaGetSymbolAddress((void**)&x,    g_x);
    cudaGetSymbolAddress((void**)&h,    g_h);
    cudaGetSymbolAddress((void**)&tb,   g_t);
    cudaGetSymbolAddress((void**)&z,    g_z);
    cudaGetSymbolAddress((void**)&ho,   g_ho);
    cudaGetSymbolAddress((void**)&a56,  g_a56);
    cudaGetSymbolAddress((void**)&wpad, g_wpad);
    cudaGetSymbolAddress(&adj8_p, g_adj8);
    cudaGetSymbolAddress(&h8T_p,  g_h8T);

    tmap_fn_t tmap_fn = nullptr;
    cudaDriverEntryPointQueryResult qr;
    cudaGetDriverEntryPointByVersion("cuTensorMapEncodeTiled", (void**)&tmap_fn,
                                     12000, cudaEnableDefault, &qr);
    static CUtensorMap mapAdj, mapHT, mapHT64;
    make_tmap8(tmap_fn, &mapAdj,  adj8_p, NN, NN);
    make_tmap8(tmap_fn, &mapHT,   h8T_p,  NN, DIM);
    make_tmap8(tmap_fn, &mapHT64, h8T_p,  NN, 64);

    const int SZT = (int)sizeof(TAux) + 1024 + TNST * 2 * 8192;   // ~76 KB
    const int SZG = (128 * 65 + 128 * 64) * 4;                    // ~66 KB
    cudaFuncSetAttribute(k_tmma<0>, cudaFuncAttributeMaxDynamicSharedMemorySize, SZT);
    cudaFuncSetAttribute(k_tmma<1>, cudaFuncAttributeMaxDynamicSharedMemorySize, SZT);
    cudaFuncSetAttribute(k_gemm,    cudaFuncAttributeMaxDynamicSharedMemorySize, SZG);

    k_gather<<<NN * DIM / 256, 256>>>(fp, emb);
    k_adjconv<<<(size_t)NN * NN / 2048, 256>>>(adj);
    k_padw<<<DIM * ODP / 256, 256>>>(Woa);

    // 3 message-passing layers (int8 exact-adj path)
    for (int l = 0; l < 3; l++) {
        k_gemm<<<dim3(NN / 64, 2), 256, SZG>>>(x, Wfp + l * DIM * DIM, DIM,
                                               bfp + l * DIM, h, DIM, 1.f, 1, 0);
        k_cmax1<<<64, 128>>>(h);
        k_cmax2<<<1, 128>>>();
        k_transp8i<<<dim3(NN / 64, DIM / 64), 256>>>(h);
        k_tmma<0><<<dim3(NN / 64, 2), 256, SZT>>>(mapAdj, mapHT, h, tb, DIM, 0);
        k_l2norm<<<NN / 8, 256>>>(tb, x);
    }

    // 2 GAT heads (fp8 attention path)
    for (int hd = 0; hd < 2; hd++) {
        k_gemm<<<dim3(NN / 64, 2), 256, SZG>>>(x, Wh + hd * DIM * DIM, DIM,
                                               nullptr, h, DIM, 1.f, 0, 1);
        k_s12<<<NN / 8, 256>>>(h, DIM, DIM, ah + hd * 2 * DIM);
        k_prep<<<NN / 256, 256>>>();
        k_transp8<<<dim3(NN / 64, DIM / 64), 256>>>(h, DIM);
        k_colmean1<128><<<64, 128>>>(h);
        k_colmean2<<<1, 128>>>(128);
        k_tmma<1><<<dim3(NN / 64, 2), 256, SZT>>>(mapAdj, mapHT, nullptr, z, DIM, hd);
    }

    // out-attention at D=56 (padded to 64); x = z/2 folded into scale
    k_gemm<<<dim3(NN / 64, 1), 256, SZG>>>(z, wpad, ODP, nullptr, ho, ODP, 0.5f, 0, 1);
    k_s12<<<NN / 8, 256>>>(ho, ODP, OD, aoa);
    k_prep<<<NN / 256, 256>>>();
    k_transp8<<<dim3(NN / 64, 1), 256>>>(ho, ODP);
    k_colmean1<64><<<64, 64>>>(ho);
    k_colmean2<<<1, 128>>>(64);
    k_tmma<1><<<dim3(NN / 64, 1), 256, SZT>>>(mapAdj, mapHT64, nullptr, a56, ODP, 0);

    k_smax56<<<NN / 8, 256>>>(a56);
    k_head<<<NMOL, 64>>>(seg, Wout, bout, Wpr, bpr, out);
}

// round 13
// speedup vs baseline: 6.5854x; 1.4787x over previous
#include <cuda_runtime.h>
#include <cuda.h>
#include <cuda_bf16.h>
#include <cuda_fp16.h>
#include <math.h>

#define NN   8192
#define DIM  128
#define NMOL 256
#define OD   56
#define ODP  64

typedef unsigned long long u64;
typedef unsigned int u32;
typedef unsigned short u16;
typedef unsigned char u8;

// ---------------- f32x2 helpers ----------------------------------------------
__device__ __forceinline__ u64 pk2(float lo, float hi) {
    u64 r; asm("mov.b64 %0, {%1,%2};" : "=l"(r) : "f"(lo), "f"(hi)); return r;
}
__device__ __forceinline__ void upk2(u64 v, float &lo, float &hi) {
    asm("mov.b64 {%0,%1}, %2;" : "=f"(lo), "=f"(hi) : "l"(v));
}
__device__ __forceinline__ void fma2(u64 &d, u64 a, u64 b) {
    asm("fma.rn.f32x2 %0, %1, %2, %0;" : "+l"(d) : "l"(a), "l"(b));
}

// ---------------- FMA-only exp ------------------------------------------------
__device__ __forceinline__ float fexp(float x) {
    x = fmaxf(x, -87.0f);
    float y = x * 1.44269504f;
    float r = rintf(y);
    float f = y - r;
    float p = 1.33335581e-3f;
    p = fmaf(p, f, 9.61812911e-3f);
    p = fmaf(p, f, 5.55041087e-2f);
    p = fmaf(p, f, 2.40226507e-1f);
    p = fmaf(p, f, 6.93147181e-1f);
    p = fmaf(p, f, 1.0f);
    int e = (int)r;
    return p * __int_as_float((e + 127) << 23);
}

__device__ __forceinline__ u32 encf(float s) {
    u32 b = __float_as_uint(s);
    return (b & 0x80000000u) ? ~b : (b | 0x80000000u);
}
__device__ __forceinline__ float decf(u32 u) {
    return __uint_as_float((u & 0x80000000u) ? (u & 0x7fffffffu) : ~u);
}

// ---------------- MMA / ldmatrix helpers --------------------------------------
__device__ __forceinline__ u32 smem_u32(const void* p) {
    return (u32)__cvta_generic_to_shared(p);
}
__device__ __forceinline__ void ldm_x4(u32 a, u32* r) {
    asm volatile("ldmatrix.sync.aligned.m8n8.x4.shared.b16 {%0,%1,%2,%3}, [%4];"
        : "=r"(r[0]), "=r"(r[1]), "=r"(r[2]), "=r"(r[3]) : "r"(a));
}
// int8 MMA, s32 accum (fastest measured format on this part)
__device__ __forceinline__ void mma_s8(int* c, const u32* a, const u32* b) {
    asm volatile(
        "mma.sync.aligned.m16n8k32.row.col.s32.s8.s8.s32 "
        "{%0,%1,%2,%3}, {%4,%5,%6,%7}, {%8,%9}, {%0,%1,%2,%3};"
        : "+r"(c[0]), "+r"(c[1]), "+r"(c[2]), "+r"(c[3])
        : "r"(a[0]), "r"(a[1]), "r"(a[2]), "r"(a[3]), "r"(b[0]), "r"(b[1]));
}

// ---------------- TMA / mbarrier ----------------------------------------------
__device__ __forceinline__ void tma2d(u32 dst, const void* map, int x, int y, u32 mbar) {
    asm volatile(
        "cp.async.bulk.tensor.2d.shared::cta.global.tile.mbarrier::complete_tx::bytes "
        "[%0], [%1, {%2, %3}], [%4];"
        :: "r"(dst), "l"(map), "r"(x), "r"(y), "r"(mbar) : "memory");
}
__device__ __forceinline__ void mbar_init(u32 a, u32 cnt) {
    asm volatile("mbarrier.init.shared.b64 [%0], %1;" :: "r"(a), "r"(cnt) : "memory");
}
__device__ __forceinline__ void mbar_expect(u32 a, u32 bytes) {
    asm volatile("mbarrier.arrive.expect_tx.shared.b64 _, [%0], %1;"
                 :: "r"(a), "r"(bytes) : "memory");
}
__device__ __forceinline__ void mbar_wait(u32 a, u32 parity) {
    asm volatile(
        "{\n\t.reg .pred P;\n\t"
        "W_%=:\n\t"
        "mbarrier.try_wait.parity.acquire.cta.shared::cta.b64 P, [%0], %1, 0x989680;\n\t"
        "@P bra.uni D_%=;\n\t"
        "bra.uni W_%=;\n\t"
        "D_%=:\n\t}"
        :: "r"(a), "r"(parity) : "memory");
}
__device__ __forceinline__ void mbar_inval(u32 a) {
    asm volatile("mbarrier.inval.shared.b64 [%0];" :: "r"(a) : "memory");
}
// standard 128B swizzle
__device__ __forceinline__ u32 swz(u32 o) { return o ^ ((o >> 3) & 0x70); }

// ---------------- scratch -----------------------------------------------------
__device__ u8 g_adj8[(size_t)NN * NN];    // 64 MB, exact 0/1 (byte 0x01)
__device__ u8 g_h8T[(size_t)DIM * NN];    // H^T s8, per-column quantized
__device__ float g_x [NN * DIM];
__device__ float g_h [NN * DIM];
__device__ float g_t [NN * DIM];
__device__ float g_z [NN * DIM];
__device__ float g_s1[NN];
__device__ float g_s2[NN];
__device__ u32   g_s2maxu;
__device__ float g_pa[NN], g_pb[NN];
__device__ float2 g_egq[NN];
__device__ float g_ho [NN * ODP];
__device__ float g_a56[NN * ODP];
__device__ float g_wpad[DIM * ODP];
__device__ float g_cm[DIM];
__device__ float g_cmp[64 * DIM];
__device__ u32   g_cmxu[DIM];         // column abs-max (raw non-neg float bits)
__device__ float g_hsc[DIM];          // dequant scale (cmax/127)
__device__ float g_hsi[DIM];          // quant scale (127/cmax)

// ---------------- small utility kernels ---------------------------------------
__global__ void k_gather(const int* __restrict__ fp, const float* __restrict__ emb) {
    int idx = blockIdx.x * 256 + threadIdx.x;
    if (blockIdx.x == 0 && threadIdx.x < DIM) g_cmxu[threadIdx.x] = 0u;
    int i = idx >> 7, c = idx & 127;
    g_x[idx] = emb[fp[i] * DIM + c];
}

__global__ void k_padw(const float* __restrict__ W) {
    int idx = blockIdx.x * 256 + threadIdx.x;
    int k = idx >> 6, c = idx & 63;
    g_wpad[idx] = (c < OD) ? W[k * OD + c] : 0.0f;
}

// adj fp32 -> byte 0x01 (s8 value 1; nonzero flag)
__global__ void k_adjconv(const float* __restrict__ adj) {
    size_t base = ((size_t)blockIdx.x * 256 + threadIdx.x) * 8;
    float4 a = *(const float4*)(adj + base);
    float4 b = *(const float4*)(adj + base + 4);
    u8 o[8];
    o[0] = a.x != 0.f ? 1 : 0; o[1] = a.y != 0.f ? 1 : 0;
    o[2] = a.z != 0.f ? 1 : 0; o[3] = a.w != 0.f ? 1 : 0;
    o[4] = b.x != 0.f ? 1 : 0; o[5] = b.y != 0.f ? 1 : 0;
    o[6] = b.z != 0.f ? 1 : 0; o[7] = b.w != 0.f ? 1 : 0;
    *(u64*)(g_adj8 + base) = *(u64*)o;
}

// finalize quant scales from fused column-max atomics
__global__ void k_qscale() {
    int t = threadIdx.x;
    float m = __uint_as_float(g_cmxu[t]);
    g_hsc[t] = m * (1.0f / 127.0f);
    g_hsi[t] = (m > 0.f) ? 127.0f / m : 0.f;
}

// H [NN][ldf] fp32 -> H^T s8 per-column quantized; grid (NN/64, feats/64)
// also clears g_cmxu for the NEXT pass (block (0,0)).
__global__ void __launch_bounds__(256) k_transp8i(const float* __restrict__ H, int ldf) {
    __shared__ float S[64][65];
    if (blockIdx.x == 0 && blockIdx.y == 0 && threadIdx.x < DIM) g_cmxu[threadIdx.x] = 0u;
    const int n0 = blockIdx.x * 64, f0 = blockIdx.y * 64;
    const int t = threadIdx.x, r = t >> 2, cb = t & 3;
#pragma unroll
    for (int q = 0; q < 4; q++) {
        float4 v = *(const float4*)&H[(size_t)(n0 + r) * ldf + f0 + cb * 16 + q * 4];
        S[r][cb * 16 + q * 4 + 0] = v.x; S[r][cb * 16 + q * 4 + 1] = v.y;
        S[r][cb * 16 + q * 4 + 2] = v.z; S[r][cb * 16 + q * 4 + 3] = v.w;
    }
    __syncthreads();
    const int f = t >> 2, nb = t & 3;
    const float si = g_hsi[f0 + f];
    char o[16];
#pragma unroll
    for (int q = 0; q < 16; q++) {
        float v = S[nb * 16 + q][f] * si;
        v = fminf(fmaxf(v, -127.f), 127.f);
        o[q] = (char)__float2int_rn(v);
    }
    *(uint4*)(g_h8T + (size_t)(f0 + f) * NN + n0 + nb * 16) = *(uint4*)o;
}

// ---------------- row L2-normalize --------------------------------------------
__global__ void k_l2norm(const float* __restrict__ in, float* __restrict__ out) {
    int w = threadIdx.x >> 5, lane = threadIdx.x & 31;
    int row = blockIdx.x * 8 + w;
    const float* r = in + (size_t)row * DIM;
    float v[4], ss = 0.f;
#pragma unroll
    for (int q = 0; q < 4; q++) { v[q] = r[lane + q * 32]; ss += v[q] * v[q]; }
#pragma unroll
    for (int o = 16; o > 0; o >>= 1) ss += __shfl_xor_sync(0xffffffffu, ss, o);
    float inv = 1.0f / fmaxf(sqrtf(ss), 1e-12f);
#pragma unroll
    for (int q = 0; q < 4; q++) out[(size_t)row * DIM + lane + q * 32] = v[q] * inv;
}

// ---------------- s1/s2 projections + global s2 max ---------------------------
__global__ void k_s12(const float* __restrict__ H, int ld, int Dr,
                      const float* __restrict__ a) {
    int w = threadIdx.x >> 5, lane = threadIdx.x & 31;
    int row = blockIdx.x * 8 + w;
    const float* r = H + (size_t)row * ld;
    float p1 = 0.f, p2 = 0.f;
    for (int c = lane; c < Dr; c += 32) {
        float v = r[c];
        p1 = fmaf(v, a[c], p1);
        p2 = fmaf(v, a[Dr + c], p2);
    }
#pragma unroll
    for (int o = 16; o > 0; o >>= 1) {
        p1 += __shfl_xor_sync(0xffffffffu, p1, o);
        p2 += __shfl_xor_sync(0xffffffffu, p2, o);
    }
    if (lane == 0) {
        g_s1[row] = p1; g_s2[row] = p2;
        atomicMax(&g_s2maxu, encf(p2));
    }
}

// ---------------- per-node attention precompute -------------------------------
// e^{lrelu(s)-m} = max(a_i*eg_j, b_i*eq_j); fold 127 into a,b for s8 quant.
__global__ void k_prep() {
    int i = blockIdx.x * 256 + threadIdx.x;
    float gmax = decf(g_s2maxu);
    float s1 = g_s1[i], s2 = g_s2[i];
    float u = s1 + gmax;
    float m = (u > 0.f) ? u : 0.25f * u;
    g_pa[i] = 127.0f * fexp(s1 - m);
    g_pb[i] = 127.0f * fexp(0.25f * s1 - m);
    float2 e; e.x = fexp(s2); e.y = fexp(0.25f * s2);
    g_egq[i] = e;
}

// ---------------- column mean (deterministic 2-stage) -------------------------
template<int BN>
__global__ void k_colmean1(const float* __restrict__ H) {
    int t = threadIdx.x;
    int r0 = blockIdx.x * 128;
    float s = 0.f;
    for (int r = 0; r < 128; r++) s += H[(size_t)(r0 + r) * BN + t];
    g_cmp[blockIdx.x * DIM + t] = s;
}
__global__ void k_colmean2(int BN) {
    int t = threadIdx.x;
    float s = 0.f;
    if (t < BN) for (int b = 0; b < 64; b++) s += g_cmp[b * DIM + t];
    g_cm[t] = s * (1.0f / NN);
}

// ================== TMA-fed s8 mma.sync kernel (64x64 per CTA) ================
// grid (NN/64 row blocks, Ncols/64 col blocks). Chunk = 128 K.
// MODE 0: Out = resid + (adj @ Hq) * colscale                 (s32 exact)
// MODE 1: q_ij = rint(adj_ij * max(a_i*eg_j, b_i*eq_j)) s8 in [0,127];
//         d_i = sum_j q_ij via ones-column MMA (exact);
//         Out_i = elu((q@Hq)*colscale / d_i)  (d==0 -> colmean), opt accum.
#define TNST 4
struct TAux {
    u8 Phi[64][144];
    float A[64], B[64], D[64];
    u64 bar[TNST];
};

template<int MODE>
__global__ void __launch_bounds__(256) k_tmma(
    const __grid_constant__ CUtensorMap mAdj,
    const __grid_constant__ CUtensorMap mH,
    const float* __restrict__ resid,
    float* __restrict__ Out, int ldo, int accum)
{
    constexpr int BK = 128, NT = NN / BK;   // 64 chunks
    constexpr u32 STAGE_B = 2 * 8192;       // adj tile + H tile

    extern __shared__ char raw[];
    TAux& X = *reinterpret_cast<TAux*>(raw);
    const u32 tiles_u = (smem_u32(raw) + (u32)sizeof(TAux) + 1023u) & ~1023u;
    char* tiles_p = raw + (tiles_u - smem_u32(raw));

    const int t = threadIdx.x, lane = t & 31, warp = t >> 5;
    const int i0 = blockIdx.x * 64, co = blockIdx.y * 64;
    const int wm = warp >> 1, wn = warp & 1;       // 4x2 warp grid, 16x32 each
    const int pr = warp * 8 + (lane >> 2);         // P-gen row
    const int pc = (lane & 3) * 32;                // P-gen byte-col start

    if (MODE && t < 64) { X.A[t] = g_pa[i0 + t]; X.B[t] = g_pb[i0 + t]; }
    if (t == 0)
        for (int s = 0; s < TNST; s++) mbar_init(smem_u32(&X.bar[s]), 1);
    __syncthreads();
    float ai = 0.f, bi = 0.f;
    if (MODE) { ai = X.A[pr]; bi = X.B[pr]; }

    if (t == 0) {
#pragma unroll
        for (int s = 0; s < 3; s++) {
            u32 bar = smem_u32(&X.bar[s]);
            mbar_expect(bar, STAGE_B);
            u32 st = tiles_u + s * STAGE_B;
            tma2d(st,        &mAdj, s * 128, i0, bar);
            tma2d(st + 8192, &mH,   s * 128, co, bar);
        }
    }

    int iacc[4][4];
    int dacc[4];
#pragma unroll
    for (int b = 0; b < 4; b++) {
        dacc[b] = 0;
#pragma unroll
        for (int c = 0; c < 4; c++) iacc[b][c] = 0;
    }
    // constant ones-column B fragment (col 0 = 1, cols 1-7 = 0)
    const u32 bones = (lane < 4) ? 0x01010101u : 0u;
    u32 bh1[2] = { bones, bones };

    for (int kt = 0; kt < NT; kt++) {
        const int cur = kt & 3, k0 = kt * BK;
        const u32 stg = tiles_u + cur * STAGE_B;
        mbar_wait(smem_u32(&X.bar[cur]), (kt >> 2) & 1);

        if (MODE) {
            const char* adjp = tiles_p + cur * STAGE_B;
            u32 off = (u32)pr * 128 + (u32)pc;
            uint4 av0 = *(const uint4*)(adjp + swz(off));
            uint4 av1 = *(const uint4*)(adjp + swz(off + 16));
            u8 ab[32];
            *(uint4*)ab = av0; *(uint4*)(ab + 16) = av1;
            char pq[32];
            const float2* egq = g_egq + k0 + pc;
#pragma unroll
            for (int c = 0; c < 32; c++) {
                float2 e = egq[c];
                float p = fmaxf(ai * e.x, bi * e.y);
                p = ab[c] ? p : 0.f;
                pq[c] = (char)__float2int_rn(p);
            }
            *(uint4*)&X.Phi[pr][pc]      = *(uint4*)pq;
            *(uint4*)&X.Phi[pr][pc + 16] = *(uint4*)(pq + 16);
            __syncthreads();
        }

#pragma unroll
        for (int kk = 0; kk < 4; kk++) {    // 4 x k32 = 128 K per chunk
            u32 ah[4];
            {
                int rr = wm * 16 + (lane & 15);
                u32 boff = (u32)kk * 32 + ((u32)(lane >> 4)) * 16;
                u32 a = MODE ? smem_u32(&X.Phi[rr][0]) + boff
                             : stg + swz((u32)rr * 128 + boff);
                ldm_x4(a, ah);
            }
            u32 bh[4][2];
#pragma unroll
            for (int fp2 = 0; fp2 < 2; fp2++) {
                int nb = wn * 32 + fp2 * 16;
                u32 rowN = (u32)nb + (u32)(lane & 7) + (((u32)lane >> 4) << 3);
                u32 a = stg + 8192
                      + swz(rowN * 128 + (u32)kk * 32 + (((u32)lane >> 3) & 1) * 16);
                u32 r4[4];
                ldm_x4(a, r4);
                bh[2*fp2][0] = r4[0]; bh[2*fp2][1] = r4[1];
                bh[2*fp2+1][0] = r4[2]; bh[2*fp2+1][1] = r4[3];
            }
#pragma unroll
            for (int fn = 0; fn < 4; fn++)
                mma_s8(iacc[fn], ah, bh[fn]);
            if (MODE && wn == 0)
                mma_s8(dacc, ah, bh1);
        }
        __syncthreads();

        if (t == 0 && kt + 3 < NT) {
            const int s = (kt + 3) & 3;
            u32 bar = smem_u32(&X.bar[s]);
            mbar_expect(bar, STAGE_B);
            u32 st = tiles_u + s * STAGE_B;
            tma2d(st,        &mAdj, (kt + 3) * 128, i0, bar);
            tma2d(st + 8192, &mH,   (kt + 3) * 128, co, bar);
        }
    }

    if (MODE && wn == 0 && (lane & 3) == 0) {
        X.D[wm * 16 + (lane >> 2)]     = (float)dacc[0];
        X.D[wm * 16 + (lane >> 2) + 8] = (float)dacc[2];
    }
    __syncthreads();

#pragma unroll
    for (int h = 0; h < 2; h++) {
        int rl = wm * 16 + (lane >> 2) + h * 8;
        int row = i0 + rl;
#pragma unroll
        for (int fn = 0; fn < 4; fn++) {
            int col = co + wn * 32 + fn * 8 + (lane & 3) * 2;
            float* op = Out + (size_t)row * ldo + col;
            if (MODE == 0) {
                float v0 = (float)iacc[fn][2 * h]     * g_hsc[col];
                float v1 = (float)iacc[fn][2 * h + 1] * g_hsc[col + 1];
                float2 rr = *(const float2*)(resid + (size_t)row * ldo + col);
                float2 o; o.x = v0 + rr.x; o.y = v1 + rr.y;
                *(float2*)op = o;
            } else {
                float dd = X.D[rl];
                float v0, v1;
                if (dd > 0.f) {
                    float inv = 1.0f / dd;
                    v0 = (float)iacc[fn][2 * h]     * g_hsc[col]     * inv;
                    v1 = (float)iacc[fn][2 * h + 1] * g_hsc[col + 1] * inv;
                } else { v0 = g_cm[col]; v1 = g_cm[col + 1]; }
                v0 = (v0 > 0.f) ? v0 : fexp(v0) - 1.0f;
                v1 = (v1 > 0.f) ? v1 : fexp(v1) - 1.0f;
                if (accum) {
                    float2 zz = *(const float2*)op;
                    v0 += zz.x; v1 += zz.y;
                }
                float2 o; o.x = v0; o.y = v1;
                *(float2*)op = o;
            }
        }
    }
    __syncthreads();
    if (t == 0)
        for (int s = 0; s < TNST; s++) mbar_inval(smem_u32(&X.bar[s]));
}

// ---------------- dense GEMM: 64x64 per CTA + fused column abs-max ------------
__global__ void __launch_bounds__(256) k_gemm(
        const float* __restrict__ A,
        const float* __restrict__ B, int ldb,
        const float* __restrict__ bias,
        float* __restrict__ C, int ldc,
        float scale, int relu, int rst)
{
    extern __shared__ float sm[];
    float (*As)[65] = (float(*)[65])sm;                  // [128][65]
    float (*Bs)[64] = (float(*)[64])(sm + 128 * 65);     // [128][64]
    const int t = threadIdx.x;
    const int row0 = blockIdx.x * 64, co = blockIdx.y * 64;

    if (rst && blockIdx.x == 0 && blockIdx.y == 0 && t == 0) g_s2maxu = 0u;

#pragma unroll
    for (int l = 0; l < 32; l++) {
        int idx = t + l * 256;
        int m = idx >> 7, k = idx & 127;
        As[k][m] = A[(size_t)(row0 + m) * DIM + k];
    }
#pragma unroll
    for (int l = 0; l < 32; l++) {
        int idx = t + l * 256;
        int k = idx >> 6, c = idx & 63;
        Bs[k][c] = B[(size_t)k * ldb + co + c];
    }
    __syncthreads();

    const int tx = t & 15, ty = t >> 4;
    u64 acc[4][2];
#pragma unroll
    for (int i = 0; i < 4; i++) { acc[i][0] = 0ULL; acc[i][1] = 0ULL; }

#pragma unroll 4
    for (int k = 0; k < 128; k++) {
        float a0 = As[k][ty * 4 + 0];
        float a1 = As[k][ty * 4 + 1];
        float a2 = As[k][ty * 4 + 2];
        float a3 = As[k][ty * 4 + 3];
        u64 b0 = *(const u64*)&Bs[k][tx * 4];
        u64 b1 = *(const u64*)&Bs[k][tx * 4 + 2];
        fma2(acc[0][0], pk2(a0, a0), b0); fma2(acc[0][1], pk2(a0, a0), b1);
        fma2(acc[1][0], pk2(a1, a1), b0); fma2(acc[1][1], pk2(a1, a1), b1);
        fma2(acc[2][0], pk2(a2, a2), b0); fma2(acc[2][1], pk2(a2, a2), b1);
        fma2(acc[3][0], pk2(a3, a3), b0); fma2(acc[3][1], pk2(a3, a3), b1);
    }
    float tmax[4] = {0.f, 0.f, 0.f, 0.f};
#pragma unroll
    for (int i = 0; i < 4; i++) {
        int m = row0 + ty * 4 + i;
#pragma unroll
        for (int j = 0; j < 2; j++) {
            int c = co + tx * 4 + 2 * j;
            float lo, hi; upk2(acc[i][j], lo, hi);
            float v0 = scale * lo, v1 = scale * hi;
            if (bias)  { v0 += bias[c]; v1 += bias[c + 1]; }
            if (relu)  { v0 = fmaxf(v0, 0.f); v1 = fmaxf(v1, 0.f); }
            tmax[2 * j]     = fmaxf(tmax[2 * j],     fabsf(v0));
            tmax[2 * j + 1] = fmaxf(tmax[2 * j + 1], fabsf(v1));
            float2 o; o.x = v0; o.y = v1;
            *(float2*)&C[(size_t)m * ldc + c] = o;
        }
    }
    // fused column abs-max: smem reduce over the 16 thread-rows, then atomicMax
    __syncthreads();
    float* red = sm;   // 16 x 64 overlay on As
#pragma unroll
    for (int q = 0; q < 4; q++) red[ty * 64 + tx * 4 + q] = tmax[q];
    __syncthreads();
    if (t < 64) {
        float m = 0.f;
#pragma unroll
        for (int k = 0; k < 16; k++) m = fmaxf(m, red[k * 64 + t]);
        atomicMax(&g_cmxu[co + t], __float_as_uint(m));
    }
}

// ---------------- row softmax over first 56 of 64 cols ------------------------
__global__ void k_smax56(float* __restrict__ X) {
    int w = threadIdx.x >> 5, lane = threadIdx.x & 31;
    int row = blockIdx.x * 8 + w;
    float* r = X + (size_t)row * ODP;
    float v0 = (lane < OD)      ? r[lane]      : -3e38f;
    float v1 = (lane + 32 < OD) ? r[lane + 32] : -3e38f;
    float m = fmaxf(v0, v1);
#pragma unroll
    for (int o = 16; o > 0; o >>= 1) m = fmaxf(m, __shfl_xor_sync(0xffffffffu, m, o));
    float e0 = (lane < OD)      ? fexp(v0 - m) : 0.f;
    float e1 = (lane + 32 < OD) ? fexp(v1 - m) : 0.f;
    float s = e0 + e1;
#pragma unroll
    for (int o = 16; o > 0; o >>= 1) s += __shfl_xor_sync(0xffffffffu, s, o);
    float inv = 1.0f / s;
    if (lane < OD)      r[lane]      = e0 * inv;
    if (lane + 32 < OD) r[lane + 32] = e1 * inv;
}

// ---------------- segment-sum readout + MLP head ------------------------------
__global__ void k_head(const int* __restrict__ seg,
                       const float* __restrict__ Wout, const float* __restrict__ bout,
                       const float* __restrict__ Wprop, const float* __restrict__ bprop,
                       float* __restrict__ out)
{
    __shared__ float v[OD];
    __shared__ float o[OD];
    __shared__ int bnd[2];
    const int m = blockIdx.x, t = threadIdx.x;
    if (t < 2) {
        int target = m + t;
        int lo = 0, hi = NN;
        while (lo < hi) { int mid = (lo + hi) >> 1; if (seg[mid] < target) lo = mid + 1; else hi = mid; }
        bnd[t] = lo;
    }
    __syncthreads();
    int lo = bnd[0], hi = bnd[1];
    if (t < OD) {
        float s = 0.f;
        for (int i = lo; i < hi; i++) s += g_a56[(size_t)i * ODP + t];
        v[t] = s;
    }
    __syncthreads();
    for (int l = 0; l < 2; l++) {
        if (t < OD) {
            float s = bout[l * OD + t];
            const float* W = Wout + l * OD * OD;
            for (int k = 0; k < OD; k++) s = fmaf(v[k], W[k * OD + t], s);
            o[t] = fmaxf(s, 0.f);
        }
        __syncthreads();
        if (t < OD) v[t] = o[t];
        __syncthreads();
    }
    if (t < 2) {
        float s = bprop[t];
        for (int k = 0; k < OD; k++) s = fmaf(v[k], Wprop[k * 2 + t], s);
        float r;
        if (s >= 0.f) r = 1.0f / (1.0f + fexp(-s));
        else { float e = fexp(s); r = e / (1.0f + e); }
        out[m * 2 + t] = r;
    }
}

// ---------------- orchestration ----------------------------------------------
typedef CUresult (*tmap_fn_t)(CUtensorMap*, CUtensorMapDataType, cuuint32_t, void*,
                              const cuuint64_t*, const cuuint64_t*, const cuuint32_t*,
                              const cuuint32_t*, CUtensorMapInterleave, CUtensorMapSwizzle,
                              CUtensorMapL2promotion, CUtensorMapFloatOOBfill);

static void make_tmap8(tmap_fn_t fn, CUtensorMap* m, void* base,
                       unsigned long long d0, unsigned long long d1) {
    cuuint64_t dims[2] = { d0, d1 };
    cuuint64_t strides[1] = { d0 };
    cuuint32_t box[2] = { 128, 64 };
    cuuint32_t es[2] = { 1, 1 };
    fn(m, CU_TENSOR_MAP_DATA_TYPE_UINT8, 2, base, dims, strides, box, es,
       CU_TENSOR_MAP_INTERLEAVE_NONE, CU_TENSOR_MAP_SWIZZLE_128B,
       CU_TENSOR_MAP_L2_PROMOTION_L2_128B, CU_TENSOR_MAP_FLOAT_OOB_FILL_NONE);
}

extern "C" void kernel_launch(void* const* d_in, const int* in_sizes, int n_in,
                              void* d_out, int out_size) {
    const int*   fp   = (const int*)  d_in[0];
    const float* adj  = (const float*)d_in[1];
    const int*   seg  = (const int*)  d_in[2];
    const float* emb  = (const float*)d_in[3];
    const float* Wfp  = (const float*)d_in[4];
    const float* bfp  = (const float*)d_in[5];
    const float* Wh   = (const float*)d_in[6];
    const float* ah   = (const float*)d_in[7];
    const float* Woa  = (const float*)d_in[8];
    const float* aoa  = (const float*)d_in[9];
    const float* Wout = (const float*)d_in[10];
    const float* bout = (const float*)d_in[11];
    const float* Wpr  = (const float*)d_in[12];
    const float* bpr  = (const float*)d_in[13];
    float* out = (float*)d_out;

    float *x, *h, *tb, *z, *ho, *a56, *wpad;
    void *adj8_p, *h8T_p;
    cudaGetSymbolAddress((void**)&x,    g_x);
    cudaGetSymbolAddress((void**)&h,    g_h);
    cudaGetSymbolAddress((void**)&tb,   g_t);
    cudaGetSymbolAddress((void**)&z,    g_z);
    cudaGetSymbolAddress((void**)&ho,   g_ho);
    cudaGetSymbolAddress((void**)&a56,  g_a56);
    cudaGetSymbolAddress((void**)&wpad, g_wpad);
    cudaGetSymbolAddress(&adj8_p, g_adj8);
    cudaGetSymbolAddress(&h8T_p,  g_h8T);

    tmap_fn_t tmap_fn = nullptr;
    cudaDriverEntryPointQueryResult qr;
    cudaGetDriverEntryPointByVersion("cuTensorMapEncodeTiled", (void**)&tmap_fn,
                                     12000, cudaEnableDefault, &qr);
    static CUtensorMap mapAdj, mapHT, mapHT64;
    make_tmap8(tmap_fn, &mapAdj,  adj8_p, NN, NN);
    make_tmap8(tmap_fn, &mapHT,   h8T_p,  NN, DIM);
    make_tmap8(tmap_fn, &mapHT64, h8T_p,  NN, 64);

    const int SZT = (int)sizeof(TAux) + 1024 + TNST * 2 * 8192;   // ~74 KB
    const int SZG = (128 * 65 + 128 * 64) * 4;                    // ~66 KB
    cudaFuncSetAttribute(k_tmma<0>, cudaFuncAttributeMaxDynamicSharedMemorySize, SZT);
    cudaFuncSetAttribute(k_tmma<1>, cudaFuncAttributeMaxDynamicSharedMemorySize, SZT);
    cudaFuncSetAttribute(k_gemm,    cudaFuncAttributeMaxDynamicSharedMemorySize, SZG);

    k_gather<<<NN * DIM / 256, 256>>>(fp, emb);
    k_adjconv<<<(size_t)NN * NN / 2048, 256>>>(adj);
    k_padw<<<DIM * ODP / 256, 256>>>(Woa);

    // 3 message-passing layers (int8 exact-adj path)
    for (int l = 0; l < 3; l++) {
        k_gemm<<<dim3(NN / 64, 2), 256, SZG>>>(x, Wfp + l * DIM * DIM, DIM,
                                               bfp + l * DIM, h, DIM, 1.f, 1, 0);
        k_qscale<<<1, 128>>>();
        k_transp8i<<<dim3(NN / 64, DIM / 64), 256>>>(h, DIM);
        k_tmma<0><<<dim3(NN / 64, 2), 256, SZT>>>(mapAdj, mapHT, h, tb, DIM, 0);
        k_l2norm<<<NN / 8, 256>>>(tb, x);
    }

    // 2 GAT heads (s8 attention path)
    for (int hd = 0; hd < 2; hd++) {
        k_gemm<<<dim3(NN / 64, 2), 256, SZG>>>(x, Wh + hd * DIM * DIM, DIM,
                                               nullptr, h, DIM, 1.f, 0, 1);
        k_s12<<<NN / 8, 256>>>(h, DIM, DIM, ah + hd * 2 * DIM);
        k_prep<<<NN / 256, 256>>>();
        k_qscale<<<1, 128>>>();
        k_transp8i<<<dim3(NN / 64, DIM / 64), 256>>>(h, DIM);
        k_colmean1<128><<<64, 128>>>(h);
        k_colmean2<<<1, 128>>>(128);
        k_tmma<1><<<dim3(NN / 64, 2), 256, SZT>>>(mapAdj, mapHT, nullptr, z, DIM, hd);
    }

    // out-attention at D=56 (padded to 64); x = z/2 folded into scale
    k_gemm<<<dim3(NN / 64, 1), 256, SZG>>>(z, wpad, ODP, nullptr, ho, ODP, 0.5f, 0, 1);
    k_s12<<<NN / 8, 256>>>(ho, ODP, OD, aoa);
    k_prep<<<NN / 256, 256>>>();
    k_qscale<<<1, 128>>>();
    k_transp8i<<<dim3(NN / 64, 1), 256>>>(ho, ODP);
    k_colmean1<64><<<64, 64>>>(ho);
    k_colmean2<<<1, 128>>>(64);
    k_tmma<1><<<dim3(NN / 64, 1), 256, SZT>>>(mapAdj, mapHT64, nullptr, a56, ODP, 0);

    k_smax56<<<NN / 8, 256>>>(a56);
    k_head<<<NMOL, 64>>>(seg, Wout, bout, Wpr, bpr, out);
}

// round 14
// speedup vs baseline: 6.5991x; 1.0021x over previous
#include <cuda_runtime.h>
#include <cuda.h>
#include <cuda_bf16.h>
#include <cuda_fp16.h>
#include <math.h>

#define NN   8192
#define DIM  128
#define NMOL 256
#define OD   56
#define ODP  64

typedef unsigned long long u64;
typedef unsigned int u32;
typedef unsigned short u16;
typedef unsigned char u8;

// ---------------- f32x2 helpers ----------------------------------------------
__device__ __forceinline__ u64 pk2(float lo, float hi) {
    u64 r; asm("mov.b64 %0, {%1,%2};" : "=l"(r) : "f"(lo), "f"(hi)); return r;
}
__device__ __forceinline__ void upk2(u64 v, float &lo, float &hi) {
    asm("mov.b64 {%0,%1}, %2;" : "=f"(lo), "=f"(hi) : "l"(v));
}
__device__ __forceinline__ void fma2(u64 &d, u64 a, u64 b) {
    asm("fma.rn.f32x2 %0, %1, %2, %0;" : "+l"(d) : "l"(a), "l"(b));
}

// ---------------- FMA-only exp ------------------------------------------------
__device__ __forceinline__ float fexp(float x) {
    x = fmaxf(x, -87.0f);
    float y = x * 1.44269504f;
    float r = rintf(y);
    float f = y - r;
    float p = 1.33335581e-3f;
    p = fmaf(p, f, 9.61812911e-3f);
    p = fmaf(p, f, 5.55041087e-2f);
    p = fmaf(p, f, 2.40226507e-1f);
    p = fmaf(p, f, 6.93147181e-1f);
    p = fmaf(p, f, 1.0f);
    int e = (int)r;
    return p * __int_as_float((e + 127) << 23);
}

__device__ __forceinline__ u32 encf(float s) {
    u32 b = __float_as_uint(s);
    return (b & 0x80000000u) ? ~b : (b | 0x80000000u);
}
__device__ __forceinline__ float decf(u32 u) {
    return __uint_as_float((u & 0x80000000u) ? (u & 0x7fffffffu) : ~u);
}

// ---------------- MMA / ldmatrix helpers --------------------------------------
__device__ __forceinline__ u32 smem_u32(const void* p) {
    return (u32)__cvta_generic_to_shared(p);
}
__device__ __forceinline__ void ldm_x4(u32 a, u32* r) {
    asm volatile("ldmatrix.sync.aligned.m8n8.x4.shared.b16 {%0,%1,%2,%3}, [%4];"
        : "=r"(r[0]), "=r"(r[1]), "=r"(r[2]), "=r"(r[3]) : "r"(a));
}
__device__ __forceinline__ void mma_s8(int* c, const u32* a, const u32* b) {
    asm volatile(
        "mma.sync.aligned.m16n8k32.row.col.s32.s8.s8.s32 "
        "{%0,%1,%2,%3}, {%4,%5,%6,%7}, {%8,%9}, {%0,%1,%2,%3};"
        : "+r"(c[0]), "+r"(c[1]), "+r"(c[2]), "+r"(c[3])
        : "r"(a[0]), "r"(a[1]), "r"(a[2]), "r"(a[3]), "r"(b[0]), "r"(b[1]));
}

// ---------------- TMA / mbarrier ----------------------------------------------
__device__ __forceinline__ void tma2d(u32 dst, const void* map, int x, int y, u32 mbar) {
    asm volatile(
        "cp.async.bulk.tensor.2d.shared::cta.global.tile.mbarrier::complete_tx::bytes "
        "[%0], [%1, {%2, %3}], [%4];"
        :: "r"(dst), "l"(map), "r"(x), "r"(y), "r"(mbar) : "memory");
}
__device__ __forceinline__ void mbar_init(u32 a, u32 cnt) {
    asm volatile("mbarrier.init.shared.b64 [%0], %1;" :: "r"(a), "r"(cnt) : "memory");
}
__device__ __forceinline__ void mbar_expect(u32 a, u32 bytes) {
    asm volatile("mbarrier.arrive.expect_tx.shared.b64 _, [%0], %1;"
                 :: "r"(a), "r"(bytes) : "memory");
}
__device__ __forceinline__ void mbar_wait(u32 a, u32 parity) {
    asm volatile(
        "{\n\t.reg .pred P;\n\t"
        "W_%=:\n\t"
        "mbarrier.try_wait.parity.acquire.cta.shared::cta.b64 P, [%0], %1, 0x989680;\n\t"
        "@P bra.uni D_%=;\n\t"
        "bra.uni W_%=;\n\t"
        "D_%=:\n\t}"
        :: "r"(a), "r"(parity) : "memory");
}
__device__ __forceinline__ void mbar_inval(u32 a) {
    asm volatile("mbarrier.inval.shared.b64 [%0];" :: "r"(a) : "memory");
}
__device__ __forceinline__ u32 swz(u32 o) { return o ^ ((o >> 3) & 0x70); }

// ---------------- scratch -----------------------------------------------------
__device__ u8 g_adj8[(size_t)NN * NN];
__device__ u8 g_h8T[(size_t)DIM * NN];
__device__ float g_x [NN * DIM];
__device__ float g_h [NN * DIM];
__device__ float g_t [NN * DIM];
__device__ float g_z [NN * DIM];
__device__ float g_s1[NN];
__device__ float g_s2[NN];
__device__ u32   g_s2maxu;
__device__ float g_pa[NN], g_pb[NN];
__device__ float2 g_egq[NN];
__device__ float g_ho [NN * ODP];
__device__ float g_a56[NN * ODP];
__device__ float g_wpad[DIM * ODP];
__device__ float g_cm[DIM];
__device__ float g_cmp[64 * DIM];
__device__ u32   g_cmxu[DIM];
__device__ float g_hsc[DIM];
__device__ float g_hsi[DIM];

// ---------------- small utility kernels ---------------------------------------
__global__ void k_gather(const int* __restrict__ fp, const float* __restrict__ emb) {
    int idx = blockIdx.x * 256 + threadIdx.x;
    if (blockIdx.x == 0 && threadIdx.x < DIM) g_cmxu[threadIdx.x] = 0u;
    int i = idx >> 7, c = idx & 127;
    g_x[idx] = emb[fp[i] * DIM + c];
}

__global__ void k_padw(const float* __restrict__ W) {
    int idx = blockIdx.x * 256 + threadIdx.x;
    int k = idx >> 6, c = idx & 63;
    g_wpad[idx] = (c < OD) ? W[k * OD + c] : 0.0f;
}

__global__ void k_adjconv(const float* __restrict__ adj) {
    size_t base = ((size_t)blockIdx.x * 256 + threadIdx.x) * 8;
    float4 a = *(const float4*)(adj + base);
    float4 b = *(const float4*)(adj + base + 4);
    u8 o[8];
    o[0] = a.x != 0.f ? 1 : 0; o[1] = a.y != 0.f ? 1 : 0;
    o[2] = a.z != 0.f ? 1 : 0; o[3] = a.w != 0.f ? 1 : 0;
    o[4] = b.x != 0.f ? 1 : 0; o[5] = b.y != 0.f ? 1 : 0;
    o[6] = b.z != 0.f ? 1 : 0; o[7] = b.w != 0.f ? 1 : 0;
    *(u64*)(g_adj8 + base) = *(u64*)o;
}

__global__ void k_qscale() {
    int t = threadIdx.x;
    float m = __uint_as_float(g_cmxu[t]);
    g_hsc[t] = m * (1.0f / 127.0f);
    g_hsi[t] = (m > 0.f) ? 127.0f / m : 0.f;
}

// H [NN][ldf] fp32 -> H^T s8 per-column quantized; also clears g_cmxu (blk 0,0)
__global__ void __launch_bounds__(256) k_transp8i(const float* __restrict__ H, int ldf) {
    __shared__ float S[64][65];
    if (blockIdx.x == 0 && blockIdx.y == 0 && threadIdx.x < DIM) g_cmxu[threadIdx.x] = 0u;
    const int n0 = blockIdx.x * 64, f0 = blockIdx.y * 64;
    const int t = threadIdx.x, r = t >> 2, cb = t & 3;
#pragma unroll
    for (int q = 0; q < 4; q++) {
        float4 v = *(const float4*)&H[(size_t)(n0 + r) * ldf + f0 + cb * 16 + q * 4];
        S[r][cb * 16 + q * 4 + 0] = v.x; S[r][cb * 16 + q * 4 + 1] = v.y;
        S[r][cb * 16 + q * 4 + 2] = v.z; S[r][cb * 16 + q * 4 + 3] = v.w;
    }
    __syncthreads();
    const int f = t >> 2, nb = t & 3;
    const float si = g_hsi[f0 + f];
    char o[16];
#pragma unroll
    for (int q = 0; q < 16; q++) {
        float v = S[nb * 16 + q][f] * si;
        v = fminf(fmaxf(v, -127.f), 127.f);
        o[q] = (char)__float2int_rn(v);
    }
    *(uint4*)(g_h8T + (size_t)(f0 + f) * NN + n0 + nb * 16) = *(uint4*)o;
}

// ---------------- row L2-normalize --------------------------------------------
__global__ void k_l2norm(const float* __restrict__ in, float* __restrict__ out) {
    int w = threadIdx.x >> 5, lane = threadIdx.x & 31;
    int row = blockIdx.x * 8 + w;
    const float* r = in + (size_t)row * DIM;
    float v[4], ss = 0.f;
#pragma unroll
    for (int q = 0; q < 4; q++) { v[q] = r[lane + q * 32]; ss += v[q] * v[q]; }
#pragma unroll
    for (int o = 16; o > 0; o >>= 1) ss += __shfl_xor_sync(0xffffffffu, ss, o);
    float inv = 1.0f / fmaxf(sqrtf(ss), 1e-12f);
#pragma unroll
    for (int q = 0; q < 4; q++) out[(size_t)row * DIM + lane + q * 32] = v[q] * inv;
}

// ---------------- s1/s2 projections + global s2 max ---------------------------
__global__ void k_s12(const float* __restrict__ H, int ld, int Dr,
                      const float* __restrict__ a) {
    int w = threadIdx.x >> 5, lane = threadIdx.x & 31;
    int row = blockIdx.x * 8 + w;
    const float* r = H + (size_t)row * ld;
    float p1 = 0.f, p2 = 0.f;
    for (int c = lane; c < Dr; c += 32) {
        float v = r[c];
        p1 = fmaf(v, a[c], p1);
        p2 = fmaf(v, a[Dr + c], p2);
    }
#pragma unroll
    for (int o = 16; o > 0; o >>= 1) {
        p1 += __shfl_xor_sync(0xffffffffu, p1, o);
        p2 += __shfl_xor_sync(0xffffffffu, p2, o);
    }
    if (lane == 0) {
        g_s1[row] = p1; g_s2[row] = p2;
        atomicMax(&g_s2maxu, encf(p2));
    }
}

// ---------------- attention precompute (+ fused qscale in block 0) ------------
__global__ void k_prep() {
    if (blockIdx.x == 0 && threadIdx.x < DIM) {
        float mm = __uint_as_float(g_cmxu[threadIdx.x]);
        g_hsc[threadIdx.x] = mm * (1.0f / 127.0f);
        g_hsi[threadIdx.x] = (mm > 0.f) ? 127.0f / mm : 0.f;
    }
    int i = blockIdx.x * 256 + threadIdx.x;
    float gmax = decf(g_s2maxu);
    float s1 = g_s1[i], s2 = g_s2[i];
    float u = s1 + gmax;
    float m = (u > 0.f) ? u : 0.25f * u;
    g_pa[i] = 127.0f * fexp(s1 - m);
    g_pb[i] = 127.0f * fexp(0.25f * s1 - m);
    float2 e; e.x = fexp(s2); e.y = fexp(0.25f * s2);
    g_egq[i] = e;
}

// ---------------- column mean (deterministic 2-stage) -------------------------
template<int BN>
__global__ void k_colmean1(const float* __restrict__ H) {
    int t = threadIdx.x;
    int r0 = blockIdx.x * 128;
    float s = 0.f;
    for (int r = 0; r < 128; r++) s += H[(size_t)(r0 + r) * BN + t];
    g_cmp[blockIdx.x * DIM + t] = s;
}
__global__ void k_colmean2(int BN) {
    int t = threadIdx.x;
    float s = 0.f;
    if (t < BN) for (int b = 0; b < 64; b++) s += g_cmp[b * DIM + t];
    g_cm[t] = s * (1.0f / NN);
}

// ================== TMA-fed s8 mma.sync kernel (64x64 per CTA) ================
#define TNST 4
struct TAux {
    u8 Phi[64][144];
    float A[64], B[64], D0[64], D1[64];
    u64 bar[TNST];
};

template<int MODE>
__global__ void __launch_bounds__(256) k_tmma(
    const __grid_constant__ CUtensorMap mAdj,
    const __grid_constant__ CUtensorMap mH,
    const float* __restrict__ resid,
    float* __restrict__ Out, int ldo, int accum)
{
    constexpr int BK = 128, NT = NN / BK;
    constexpr u32 STAGE_B = 2 * 8192;

    extern __shared__ char raw[];
    TAux& X = *reinterpret_cast<TAux*>(raw);
    const u32 tiles_u = (smem_u32(raw) + (u32)sizeof(TAux) + 1023u) & ~1023u;
    char* tiles_p = raw + (tiles_u - smem_u32(raw));

    const int t = threadIdx.x, lane = t & 31, warp = t >> 5;
    const int i0 = blockIdx.x * 64, co = blockIdx.y * 64;
    const int wm = warp >> 1, wn = warp & 1;
    const int pr = warp * 8 + (lane >> 2);
    const int pc = (lane & 3) * 32;

    if (MODE && t < 64) { X.A[t] = g_pa[i0 + t]; X.B[t] = g_pb[i0 + t]; }
    if (t == 0)
        for (int s = 0; s < TNST; s++) mbar_init(smem_u32(&X.bar[s]), 1);
    __syncthreads();
    float ai = 0.f, bi = 0.f;
    if (MODE) { ai = X.A[pr]; bi = X.B[pr]; }

    if (t == 0) {
#pragma unroll
        for (int s = 0; s < 3; s++) {
            u32 bar = smem_u32(&X.bar[s]);
            mbar_expect(bar, STAGE_B);
            u32 st = tiles_u + s * STAGE_B;
            tma2d(st,        &mAdj, s * 128, i0, bar);
            tma2d(st + 8192, &mH,   s * 128, co, bar);
        }
    }

    int iacc[4][4];
    int dacc[4];
#pragma unroll
    for (int b = 0; b < 4; b++) {
        dacc[b] = 0;
#pragma unroll
        for (int c = 0; c < 4; c++) iacc[b][c] = 0;
    }
    const u32 bones = (lane < 4) ? 0x01010101u : 0u;
    u32 bh1[2] = { bones, bones };

    for (int kt = 0; kt < NT; kt++) {
        const int cur = kt & 3, k0 = kt * BK;
        const u32 stg = tiles_u + cur * STAGE_B;
        mbar_wait(smem_u32(&X.bar[cur]), (kt >> 2) & 1);

        if (MODE) {
            const char* adjp = tiles_p + cur * STAGE_B;
            u32 off = (u32)pr * 128 + (u32)pc;
            uint4 av0 = *(const uint4*)(adjp + swz(off));
            uint4 av1 = *(const uint4*)(adjp + swz(off + 16));
            u8 ab[32];
            *(uint4*)ab = av0; *(uint4*)(ab + 16) = av1;
            char pq[32];
            const float2* egq = g_egq + k0 + pc;
#pragma unroll
            for (int c = 0; c < 32; c++) {
                float2 e = egq[c];
                float p = fmaxf(ai * e.x, bi * e.y);
                p = ab[c] ? p : 0.f;
                pq[c] = (char)__float2int_rn(p);
            }
            *(uint4*)&X.Phi[pr][pc]      = *(uint4*)pq;
            *(uint4*)&X.Phi[pr][pc + 16] = *(uint4*)(pq + 16);
            __syncthreads();
        }

#pragma unroll
        for (int kk = 0; kk < 4; kk++) {
            u32 ah[4];
            {
                int rr = wm * 16 + (lane & 15);
                u32 boff = (u32)kk * 32 + ((u32)(lane >> 4)) * 16;
                u32 a = MODE ? smem_u32(&X.Phi[rr][0]) + boff
                             : stg + swz((u32)rr * 128 + boff);
                ldm_x4(a, ah);
            }
            u32 bh[4][2];
#pragma unroll
            for (int fp2 = 0; fp2 < 2; fp2++) {
                int nb = wn * 32 + fp2 * 16;
                u32 rowN = (u32)nb + (u32)(lane & 7) + (((u32)lane >> 4) << 3);
                u32 a = stg + 8192
                      + swz(rowN * 128 + (u32)kk * 32 + (((u32)lane >> 3) & 1) * 16);
                u32 r4[4];
                ldm_x4(a, r4);
                bh[2*fp2][0] = r4[0]; bh[2*fp2][1] = r4[1];
                bh[2*fp2+1][0] = r4[2]; bh[2*fp2+1][1] = r4[3];
            }
#pragma unroll
            for (int fn = 0; fn < 4; fn++)
                mma_s8(iacc[fn], ah, bh[fn]);
            // balanced d-MMA: wn==0 covers kk 0,1; wn==1 covers kk 2,3
            if (MODE && (kk >> 1) == wn)
                mma_s8(dacc, ah, bh1);
        }
        __syncthreads();

        if (t == 0 && kt + 3 < NT) {
            const int s = (kt + 3) & 3;
            u32 bar = smem_u32(&X.bar[s]);
            mbar_expect(bar, STAGE_B);
            u32 st = tiles_u + s * STAGE_B;
            tma2d(st,        &mAdj, (kt + 3) * 128, i0, bar);
            tma2d(st + 8192, &mH,   (kt + 3) * 128, co, bar);
        }
    }

    if (MODE && (lane & 3) == 0) {
        float* Dp = wn ? X.D1 : X.D0;
        Dp[wm * 16 + (lane >> 2)]     = (float)dacc[0];
        Dp[wm * 16 + (lane >> 2) + 8] = (float)dacc[2];
    }
    __syncthreads();

#pragma unroll
    for (int h = 0; h < 2; h++) {
        int rl = wm * 16 + (lane >> 2) + h * 8;
        int row = i0 + rl;
#pragma unroll
        for (int fn = 0; fn < 4; fn++) {
            int col = co + wn * 32 + fn * 8 + (lane & 3) * 2;
            float* op = Out + (size_t)row * ldo + col;
            if (MODE == 0) {
                float v0 = (float)iacc[fn][2 * h]     * g_hsc[col];
                float v1 = (float)iacc[fn][2 * h + 1] * g_hsc[col + 1];
                float2 rr = *(const float2*)(resid + (size_t)row * ldo + col);
                float2 o; o.x = v0 + rr.x; o.y = v1 + rr.y;
                *(float2*)op = o;
            } else {
                float dd = X.D0[rl] + X.D1[rl];
                float v0, v1;
                if (dd > 0.f) {
                    float inv = 1.0f / dd;
                    v0 = (float)iacc[fn][2 * h]     * g_hsc[col]     * inv;
                    v1 = (float)iacc[fn][2 * h + 1] * g_hsc[col + 1] * inv;
                } else { v0 = g_cm[col]; v1 = g_cm[col + 1]; }
                v0 = (v0 > 0.f) ? v0 : fexp(v0) - 1.0f;
                v1 = (v1 > 0.f) ? v1 : fexp(v1) - 1.0f;
                if (accum) {
                    float2 zz = *(const float2*)op;
                    v0 += zz.x; v1 += zz.y;
                }
                float2 o; o.x = v0; o.y = v1;
                *(float2*)op = o;
            }
        }
    }
    __syncthreads();
    if (t == 0)
        for (int s = 0; s < TNST; s++) mbar_inval(smem_u32(&X.bar[s]));
}

// ---------------- dense GEMM: 64x64 per CTA, vectorized smem ------------------
__global__ void __launch_bounds__(256) k_gemm(
        const float* __restrict__ A,
        const float* __restrict__ B, int ldb,
        const float* __restrict__ bias,
        float* __restrict__ C, int ldc,
        float scale, int relu, int rst)
{
    extern __shared__ float sm[];
    float (*As)[68] = (float(*)[68])sm;                  // [128][68]
    float (*Bs)[68] = (float(*)[68])(sm + 128 * 68);     // [128][68], 64 used
    const int t = threadIdx.x;
    const int row0 = blockIdx.x * 64, co = blockIdx.y * 64;

    if (rst && blockIdx.x == 0 && blockIdx.y == 0 && t == 0) g_s2maxu = 0u;

#pragma unroll
    for (int l = 0; l < 8; l++) {
        int u = t + l * 256;
        int m = u >> 5, kq = (u & 31) * 4;
        float4 v = *(const float4*)&A[(size_t)(row0 + m) * DIM + kq];
        As[kq + 0][m] = v.x; As[kq + 1][m] = v.y;
        As[kq + 2][m] = v.z; As[kq + 3][m] = v.w;
    }
#pragma unroll
    for (int l = 0; l < 8; l++) {
        int u = t + l * 256;
        int k = u >> 4, c = (u & 15) * 4;
        *(float4*)&Bs[k][c] = *(const float4*)&B[(size_t)k * ldb + co + c];
    }
    __syncthreads();

    const int tx = t & 15, ty = t >> 4;
    u64 acc[4][2];
#pragma unroll
    for (int i = 0; i < 4; i++) { acc[i][0] = 0ULL; acc[i][1] = 0ULL; }

#pragma unroll 4
    for (int k = 0; k < 128; k++) {
        float4 a4 = *(const float4*)&As[k][ty * 4];
        u64 b0 = *(const u64*)&Bs[k][tx * 4];
        u64 b1 = *(const u64*)&Bs[k][tx * 4 + 2];
        fma2(acc[0][0], pk2(a4.x, a4.x), b0); fma2(acc[0][1], pk2(a4.x, a4.x), b1);
        fma2(acc[1][0], pk2(a4.y, a4.y), b0); fma2(acc[1][1], pk2(a4.y, a4.y), b1);
        fma2(acc[2][0], pk2(a4.z, a4.z), b0); fma2(acc[2][1], pk2(a4.z, a4.z), b1);
        fma2(acc[3][0], pk2(a4.w, a4.w), b0); fma2(acc[3][1], pk2(a4.w, a4.w), b1);
    }
    float tmax[4] = {0.f, 0.f, 0.f, 0.f};
#pragma unroll
    for (int i = 0; i < 4; i++) {
        int m = row0 + ty * 4 + i;
#pragma unroll
        for (int j = 0; j < 2; j++) {
            int c = co + tx * 4 + 2 * j;
            float lo, hi; upk2(acc[i][j], lo, hi);
            float v0 = scale * lo, v1 = scale * hi;
            if (bias)  { v0 += bias[c]; v1 += bias[c + 1]; }
            if (relu)  { v0 = fmaxf(v0, 0.f); v1 = fmaxf(v1, 0.f); }
            tmax[2 * j]     = fmaxf(tmax[2 * j],     fabsf(v0));
            tmax[2 * j + 1] = fmaxf(tmax[2 * j + 1], fabsf(v1));
            float2 o; o.x = v0; o.y = v1;
            *(float2*)&C[(size_t)m * ldc + c] = o;
        }
    }
    __syncthreads();
    float* red = sm;
#pragma unroll
    for (int q = 0; q < 4; q++) red[ty * 64 + tx * 4 + q] = tmax[q];
    __syncthreads();
    if (t < 64) {
        float m = 0.f;
#pragma unroll
        for (int k = 0; k < 16; k++) m = fmaxf(m, red[k * 64 + t]);
        atomicMax(&g_cmxu[co + t], __float_as_uint(m));
    }
}

// ---------------- row softmax over first 56 of 64 cols ------------------------
__global__ void k_smax56(float* __restrict__ X) {
    int w = threadIdx.x >> 5, lane = threadIdx.x & 31;
    int row = blockIdx.x * 8 + w;
    float* r = X + (size_t)row * ODP;
    float v0 = (lane < OD)      ? r[lane]      : -3e38f;
    float v1 = (lane + 32 < OD) ? r[lane + 32] : -3e38f;
    float m = fmaxf(v0, v1);
#pragma unroll
    for (int o = 16; o > 0; o >>= 1) m = fmaxf(m, __shfl_xor_sync(0xffffffffu, m, o));
    float e0 = (lane < OD)      ? fexp(v0 - m) : 0.f;
    float e1 = (lane + 32 < OD) ? fexp(v1 - m) : 0.f;
    float s = e0 + e1;
#pragma unroll
    for (int o = 16; o > 0; o >>= 1) s += __shfl_xor_sync(0xffffffffu, s, o);
    float inv = 1.0f / s;
    if (lane < OD)      r[lane]      = e0 * inv;
    if (lane + 32 < OD) r[lane + 32] = e1 * inv;
}

// ---------------- segment-sum readout + MLP head ------------------------------
__global__ void k_head(const int* __restrict__ seg,
                       const float* __restrict__ Wout, const float* __restrict__ bout,
                       const float* __restrict__ Wprop, const float* __restrict__ bprop,
                       float* __restrict__ out)
{
    __shared__ float v[OD];
    __shared__ float o[OD];
    __shared__ int bnd[2];
    const int m = blockIdx.x, t = threadIdx.x;
    if (t < 2) {
        int target = m + t;
        int lo = 0, hi = NN;
        while (lo < hi) { int mid = (lo + hi) >> 1; if (seg[mid] < target) lo = mid + 1; else hi = mid; }
        bnd[t] = lo;
    }
    __syncthreads();
    int lo = bnd[0], hi = bnd[1];
    if (t < OD) {
        float s = 0.f;
        for (int i = lo; i < hi; i++) s += g_a56[(size_t)i * ODP + t];
        v[t] = s;
    }
    __syncthreads();
    for (int l = 0; l < 2; l++) {
        if (t < OD) {
            float s = bout[l * OD + t];
            const float* W = Wout + l * OD * OD;
            for (int k = 0; k < OD; k++) s = fmaf(v[k], W[k * OD + t], s);
            o[t] = fmaxf(s, 0.f);
        }
        __syncthreads();
        if (t < OD) v[t] = o[t];
        __syncthreads();
    }
    if (t < 2) {
        float s = bprop[t];
        for (int k = 0; k < OD; k++) s = fmaf(v[k], Wprop[k * 2 + t], s);
        float r;
        if (s >= 0.f) r = 1.0f / (1.0f + fexp(-s));
        else { float e = fexp(s); r = e / (1.0f + e); }
        out[m * 2 + t] = r;
    }
}

// ---------------- orchestration ----------------------------------------------
typedef CUresult (*tmap_fn_t)(CUtensorMap*, CUtensorMapDataType, cuuint32_t, void*,
                              const cuuint64_t*, const cuuint64_t*, const cuuint32_t*,
                              const cuuint32_t*, CUtensorMapInterleave, CUtensorMapSwizzle,
                              CUtensorMapL2promotion, CUtensorMapFloatOOBfill);

static void make_tmap8(tmap_fn_t fn, CUtensorMap* m, void* base,
                       unsigned long long d0, unsigned long long d1) {
    cuuint64_t dims[2] = { d0, d1 };
    cuuint64_t strides[1] = { d0 };
    cuuint32_t box[2] = { 128, 64 };
    cuuint32_t es[2] = { 1, 1 };
    fn(m, CU_TENSOR_MAP_DATA_TYPE_UINT8, 2, base, dims, strides, box, es,
       CU_TENSOR_MAP_INTERLEAVE_NONE, CU_TENSOR_MAP_SWIZZLE_128B,
       CU_TENSOR_MAP_L2_PROMOTION_L2_128B, CU_TENSOR_MAP_FLOAT_OOB_FILL_NONE);
}

extern "C" void kernel_launch(void* const* d_in, const int* in_sizes, int n_in,
                              void* d_out, int out_size) {
    const int*   fp   = (const int*)  d_in[0];
    const float* adj  = (const float*)d_in[1];
    const int*   seg  = (const int*)  d_in[2];
    const float* emb  = (const float*)d_in[3];
    const float* Wfp  = (const float*)d_in[4];
    const float* bfp  = (const float*)d_in[5];
    const float* Wh   = (const float*)d_in[6];
    const float* ah   = (const float*)d_in[7];
    const float* Woa  = (const float*)d_in[8];
    const float* aoa  = (const float*)d_in[9];
    const float* Wout = (const float*)d_in[10];
    const float* bout = (const float*)d_in[11];
    const float* Wpr  = (const float*)d_in[12];
    const float* bpr  = (const float*)d_in[13];
    float* out = (float*)d_out;

    float *x, *h, *tb, *z, *ho, *a56, *wpad;
    void *adj8_p, *h8T_p;
    cudaGetSymbolAddress((void**)&x,    g_x);
    cudaGetSymbolAddress((void**)&h,    g_h);
    cudaGetSymbolAddress((void**)&tb,   g_t);
    cudaGetSymbolAddress((void**)&z,    g_z);
    cudaGetSymbolAddress((void**)&ho,   g_ho);
    cudaGetSymbolAddress((void**)&a56,  g_a56);
    cudaGetSymbolAddress((void**)&wpad, g_wpad);
    cudaGetSymbolAddress(&adj8_p, g_adj8);
    cudaGetSymbolAddress(&h8T_p,  g_h8T);

    tmap_fn_t tmap_fn = nullptr;
    cudaDriverEntryPointQueryResult qr;
    cudaGetDriverEntryPointByVersion("cuTensorMapEncodeTiled", (void**)&tmap_fn,
                                     12000, cudaEnableDefault, &qr);
    static CUtensorMap mapAdj, mapHT, mapHT64;
    make_tmap8(tmap_fn, &mapAdj,  adj8_p, NN, NN);
    make_tmap8(tmap_fn, &mapHT,   h8T_p,  NN, DIM);
    make_tmap8(tmap_fn, &mapHT64, h8T_p,  NN, 64);

    const int SZT = (int)sizeof(TAux) + 1024 + TNST * 2 * 8192;
    const int SZG = 128 * 68 * 2 * 4;
    cudaFuncSetAttribute(k_tmma<0>, cudaFuncAttributeMaxDynamicSharedMemorySize, SZT);
    cudaFuncSetAttribute(k_tmma<1>, cudaFuncAttributeMaxDynamicSharedMemorySize, SZT);
    cudaFuncSetAttribute(k_gemm,    cudaFuncAttributeMaxDynamicSharedMemorySize, SZG);

    k_gather<<<NN * DIM / 256, 256>>>(fp, emb);
    k_adjconv<<<(size_t)NN * NN / 2048, 256>>>(adj);
    k_padw<<<DIM * ODP / 256, 256>>>(Woa);

    // 3 message-passing layers (s8 exact-adj path)
    for (int l = 0; l < 3; l++) {
        k_gemm<<<dim3(NN / 64, 2), 256, SZG>>>(x, Wfp + l * DIM * DIM, DIM,
                                               bfp + l * DIM, h, DIM, 1.f, 1, 0);
        k_qscale<<<1, 128>>>();
        k_transp8i<<<dim3(NN / 64, DIM / 64), 256>>>(h, DIM);
        k_tmma<0><<<dim3(NN / 64, 2), 256, SZT>>>(mapAdj, mapHT, h, tb, DIM, 0);
        k_l2norm<<<NN / 8, 256>>>(tb, x);
    }

    // 2 GAT heads (s8 attention)
    for (int hd = 0; hd < 2; hd++) {
        k_gemm<<<dim3(NN / 64, 2), 256, SZG>>>(x, Wh + hd * DIM * DIM, DIM,
                                               nullptr, h, DIM, 1.f, 0, 1);
        k_s12<<<NN / 8, 256>>>(h, DIM, DIM, ah + hd * 2 * DIM);
        k_prep<<<NN / 256, 256>>>();
        k_transp8i<<<dim3(NN / 64, DIM / 64), 256>>>(h, DIM);
        k_colmean1<128><<<64, 128>>>(h);
        k_colmean2<<<1, 128>>>(128);
        k_tmma<1><<<dim3(NN / 64, 2), 256, SZT>>>(mapAdj, mapHT, nullptr, z, DIM, hd);
    }

    // out-attention at D=56 (padded to 64); x = z/2 folded into scale
    k_gemm<<<dim3(NN / 64, 1), 256, SZG>>>(z, wpad, ODP, nullptr, ho, ODP, 0.5f, 0, 1);
    k_s12<<<NN / 8, 256>>>(ho, ODP, OD, aoa);
    k_prep<<<NN / 256, 256>>>();
    k_transp8i<<<dim3(NN / 64, 1), 256>>>(ho, ODP);
    k_colmean1<64><<<64, 64>>>(ho);
    k_colmean2<<<1, 128>>>(64);
    k_tmma<1><<<dim3(NN / 64, 1), 256, SZT>>>(mapAdj, mapHT64, nullptr, a56, ODP, 0);

    k_smax56<<<NN / 8, 256>>>(a56);
    k_head<<<NMOL, 64>>>(seg, Wout, bout, Wpr, bpr, out);
}

// round 15
// speedup vs baseline: 6.6166x; 1.0026x over previous
#include <cuda_runtime.h>
#include <cuda.h>
#include <cuda_bf16.h>
#include <cuda_fp16.h>
#include <math.h>

#define NN   8192
#define DIM  128
#define NMOL 256
#define OD   56
#define ODP  64

typedef unsigned long long u64;
typedef unsigned int u32;
typedef unsigned short u16;
typedef unsigned char u8;

// ---------------- f32x2 helpers ----------------------------------------------
__device__ __forceinline__ u64 pk2(float lo, float hi) {
    u64 r; asm("mov.b64 %0, {%1,%2};" : "=l"(r) : "f"(lo), "f"(hi)); return r;
}
__device__ __forceinline__ void upk2(u64 v, float &lo, float &hi) {
    asm("mov.b64 {%0,%1}, %2;" : "=f"(lo), "=f"(hi) : "l"(v));
}
__device__ __forceinline__ void fma2(u64 &d, u64 a, u64 b) {
    asm("fma.rn.f32x2 %0, %1, %2, %0;" : "+l"(d) : "l"(a), "l"(b));
}

// ---------------- FMA-only exp ------------------------------------------------
__device__ __forceinline__ float fexp(float x) {
    x = fmaxf(x, -87.0f);
    float y = x * 1.44269504f;
    float r = rintf(y);
    float f = y - r;
    float p = 1.33335581e-3f;
    p = fmaf(p, f, 9.61812911e-3f);
    p = fmaf(p, f, 5.55041087e-2f);
    p = fmaf(p, f, 2.40226507e-1f);
    p = fmaf(p, f, 6.93147181e-1f);
    p = fmaf(p, f, 1.0f);
    int e = (int)r;
    return p * __int_as_float((e + 127) << 23);
}

__device__ __forceinline__ u32 encf(float s) {
    u32 b = __float_as_uint(s);
    return (b & 0x80000000u) ? ~b : (b | 0x80000000u);
}
__device__ __forceinline__ float decf(u32 u) {
    return __uint_as_float((u & 0x80000000u) ? (u & 0x7fffffffu) : ~u);
}

// ---------------- MMA / ldmatrix helpers --------------------------------------
__device__ __forceinline__ u32 smem_u32(const void* p) {
    return (u32)__cvta_generic_to_shared(p);
}
__device__ __forceinline__ void ldm_x4(u32 a, u32* r) {
    asm volatile("ldmatrix.sync.aligned.m8n8.x4.shared.b16 {%0,%1,%2,%3}, [%4];"
        : "=r"(r[0]), "=r"(r[1]), "=r"(r[2]), "=r"(r[3]) : "r"(a));
}
__device__ __forceinline__ void mma_s8(int* c, const u32* a, const u32* b) {
    asm volatile(
        "mma.sync.aligned.m16n8k32.row.col.s32.s8.s8.s32 "
        "{%0,%1,%2,%3}, {%4,%5,%6,%7}, {%8,%9}, {%0,%1,%2,%3};"
        : "+r"(c[0]), "+r"(c[1]), "+r"(c[2]), "+r"(c[3])
        : "r"(a[0]), "r"(a[1]), "r"(a[2]), "r"(a[3]), "r"(b[0]), "r"(b[1]));
}

// ---------------- TMA / mbarrier ----------------------------------------------
__device__ __forceinline__ void tma2d(u32 dst, const void* map, int x, int y, u32 mbar) {
    asm volatile(
        "cp.async.bulk.tensor.2d.shared::cta.global.tile.mbarrier::complete_tx::bytes "
        "[%0], [%1, {%2, %3}], [%4];"
        :: "r"(dst), "l"(map), "r"(x), "r"(y), "r"(mbar) : "memory");
}
__device__ __forceinline__ void mbar_init(u32 a, u32 cnt) {
    asm volatile("mbarrier.init.shared.b64 [%0], %1;" :: "r"(a), "r"(cnt) : "memory");
}
__device__ __forceinline__ void mbar_expect(u32 a, u32 bytes) {
    asm volatile("mbarrier.arrive.expect_tx.shared.b64 _, [%0], %1;"
                 :: "r"(a), "r"(bytes) : "memory");
}
__device__ __forceinline__ void mbar_wait(u32 a, u32 parity) {
    asm volatile(
        "{\n\t.reg .pred P;\n\t"
        "W_%=:\n\t"
        "mbarrier.try_wait.parity.acquire.cta.shared::cta.b64 P, [%0], %1, 0x989680;\n\t"
        "@P bra.uni D_%=;\n\t"
        "bra.uni W_%=;\n\t"
        "D_%=:\n\t}"
        :: "r"(a), "r"(parity) : "memory");
}
__device__ __forceinline__ void mbar_inval(u32 a) {
    asm volatile("mbarrier.inval.shared.b64 [%0];" :: "r"(a) : "memory");
}
__device__ __forceinline__ u32 swz(u32 o) { return o ^ ((o >> 3) & 0x70); }

// ---------------- scratch -----------------------------------------------------
__device__ u8 g_adj8[(size_t)NN * NN];
__device__ u8 g_h8T[(size_t)DIM * NN];
__device__ float g_x [NN * DIM];
__device__ float g_h [NN * DIM];
__device__ float g_t [NN * DIM];
__device__ float g_z [NN * DIM];
__device__ float g_s1[NN];
__device__ float g_s2[NN];
__device__ u32   g_s2maxu;
__device__ float g_pa[NN], g_pb[NN];
__device__ float2 g_egq[NN];
__device__ float g_ho [NN * ODP];
__device__ float g_a56[NN * ODP];
__device__ float g_wpad[DIM * ODP];
__device__ float g_cm[DIM];             // zero-init; d==0 fallback (never taken here)
__device__ u32   g_cmxu[2][DIM];        // double-buffered column abs-max (raw bits)

// ---------------- small utility kernels ---------------------------------------
__global__ void k_gather(const int* __restrict__ fp, const float* __restrict__ emb) {
    int idx = blockIdx.x * 256 + threadIdx.x;
    if (blockIdx.x == 0 && threadIdx.x < DIM) {
        g_cmxu[0][threadIdx.x] = 0u;
        g_cmxu[1][threadIdx.x] = 0u;
    }
    int i = idx >> 7, c = idx & 127;
    g_x[idx] = emb[fp[i] * DIM + c];
}

__global__ void k_padw(const float* __restrict__ W) {
    int idx = blockIdx.x * 256 + threadIdx.x;
    int k = idx >> 6, c = idx & 63;
    g_wpad[idx] = (c < OD) ? W[k * OD + c] : 0.0f;
}

__global__ void k_adjconv(const float* __restrict__ adj) {
    size_t base = ((size_t)blockIdx.x * 256 + threadIdx.x) * 8;
    float4 a = *(const float4*)(adj + base);
    float4 b = *(const float4*)(adj + base + 4);
    u8 o[8];
    o[0] = a.x != 0.f ? 1 : 0; o[1] = a.y != 0.f ? 1 : 0;
    o[2] = a.z != 0.f ? 1 : 0; o[3] = a.w != 0.f ? 1 : 0;
    o[4] = b.x != 0.f ? 1 : 0; o[5] = b.y != 0.f ? 1 : 0;
    o[6] = b.z != 0.f ? 1 : 0; o[7] = b.w != 0.f ? 1 : 0;
    *(u64*)(g_adj8 + base) = *(u64*)o;
}

// H [NN][ldf] fp32 -> H^T s8, per-column quant from raw cmxu[par]
__global__ void __launch_bounds__(256) k_transp8i(const float* __restrict__ H, int ldf,
                                                  int par) {
    __shared__ float S[64][65];
    const int n0 = blockIdx.x * 64, f0 = blockIdx.y * 64;
    const int t = threadIdx.x, r = t >> 2, cb = t & 3;
#pragma unroll
    for (int q = 0; q < 4; q++) {
        float4 v = *(const float4*)&H[(size_t)(n0 + r) * ldf + f0 + cb * 16 + q * 4];
        S[r][cb * 16 + q * 4 + 0] = v.x; S[r][cb * 16 + q * 4 + 1] = v.y;
        S[r][cb * 16 + q * 4 + 2] = v.z; S[r][cb * 16 + q * 4 + 3] = v.w;
    }
    __syncthreads();
    const int f = t >> 2, nb = t & 3;
    float cmx = __uint_as_float(g_cmxu[par][f0 + f]);
    const float si = (cmx > 0.f) ? 127.0f / cmx : 0.f;
    char o[16];
#pragma unroll
    for (int q = 0; q < 16; q++) {
        float v = S[nb * 16 + q][f] * si;
        v = fminf(fmaxf(v, -127.f), 127.f);
        o[q] = (char)__float2int_rn(v);
    }
    *(uint4*)(g_h8T + (size_t)(f0 + f) * NN + n0 + nb * 16) = *(uint4*)o;
}

// ---------------- row L2-normalize --------------------------------------------
__global__ void k_l2norm(const float* __restrict__ in, float* __restrict__ out) {
    int w = threadIdx.x >> 5, lane = threadIdx.x & 31;
    int row = blockIdx.x * 8 + w;
    const float* r = in + (size_t)row * DIM;
    float v[4], ss = 0.f;
#pragma unroll
    for (int q = 0; q < 4; q++) { v[q] = r[lane + q * 32]; ss += v[q] * v[q]; }
#pragma unroll
    for (int o = 16; o > 0; o >>= 1) ss += __shfl_xor_sync(0xffffffffu, ss, o);
    float inv = 1.0f / fmaxf(sqrtf(ss), 1e-12f);
#pragma unroll
    for (int q = 0; q < 4; q++) out[(size_t)row * DIM + lane + q * 32] = v[q] * inv;
}

// ---------------- s1/s2 projections + global s2 max ---------------------------
__global__ void k_s12(const float* __restrict__ H, int ld, int Dr,
                      const float* __restrict__ a) {
    int w = threadIdx.x >> 5, lane = threadIdx.x & 31;
    int row = blockIdx.x * 8 + w;
    const float* r = H + (size_t)row * ld;
    float p1 = 0.f, p2 = 0.f;
    for (int c = lane; c < Dr; c += 32) {
        float v = r[c];
        p1 = fmaf(v, a[c], p1);
        p2 = fmaf(v, a[Dr + c], p2);
    }
#pragma unroll
    for (int o = 16; o > 0; o >>= 1) {
        p1 += __shfl_xor_sync(0xffffffffu, p1, o);
        p2 += __shfl_xor_sync(0xffffffffu, p2, o);
    }
    if (lane == 0) {
        g_s1[row] = p1; g_s2[row] = p2;
        atomicMax(&g_s2maxu, encf(p2));
    }
}

// ---------------- attention precompute ----------------------------------------
__global__ void k_prep() {
    int i = blockIdx.x * 256 + threadIdx.x;
    float gmax = decf(g_s2maxu);
    float s1 = g_s1[i], s2 = g_s2[i];
    float u = s1 + gmax;
    float m = (u > 0.f) ? u : 0.25f * u;
    g_pa[i] = 127.0f * fexp(s1 - m);
    g_pb[i] = 127.0f * fexp(0.25f * s1 - m);
    float2 e; e.x = fexp(s2); e.y = fexp(0.25f * s2);
    g_egq[i] = e;
}

// ================== TMA-fed s8 mma.sync kernel (64x64 per CTA) ================
#define TNST 4
struct TAux {
    u8 Phi[2][64][144];
    float A[64], B[64], D0[64], D1[64];
    u64 bar[TNST];
};

template<int MODE>
__global__ void __launch_bounds__(256) k_tmma(
    const __grid_constant__ CUtensorMap mAdj,
    const __grid_constant__ CUtensorMap mH,
    const float* __restrict__ resid,
    float* __restrict__ Out, int ldo, int accum, int par)
{
    constexpr int BK = 128, NT = NN / BK;
    constexpr u32 STAGE_B = 2 * 8192;

    extern __shared__ char raw[];
    TAux& X = *reinterpret_cast<TAux*>(raw);
    const u32 tiles_u = (smem_u32(raw) + (u32)sizeof(TAux) + 1023u) & ~1023u;
    char* tiles_p = raw + (tiles_u - smem_u32(raw));

    const int t = threadIdx.x, lane = t & 31, warp = t >> 5;
    const int i0 = blockIdx.x * 64, co = blockIdx.y * 64;
    const int wm = warp >> 1, wn = warp & 1;
    const int pr = warp * 8 + (lane >> 2);
    const int pc = (lane & 3) * 32;

    if (MODE && t < 64) { X.A[t] = g_pa[i0 + t]; X.B[t] = g_pb[i0 + t]; }
    if (t == 0)
        for (int s = 0; s < TNST; s++) mbar_init(smem_u32(&X.bar[s]), 1);
    __syncthreads();
    float ai = 0.f, bi = 0.f;
    if (MODE) { ai = X.A[pr]; bi = X.B[pr]; }

    if (t == 0) {
#pragma unroll
        for (int s = 0; s < 3; s++) {
            u32 bar = smem_u32(&X.bar[s]);
            mbar_expect(bar, STAGE_B);
            u32 st = tiles_u + s * STAGE_B;
            tma2d(st,        &mAdj, s * 128, i0, bar);
            tma2d(st + 8192, &mH,   s * 128, co, bar);
        }
    }

    int iacc[4][4];
    int dacc[4];
#pragma unroll
    for (int b = 0; b < 4; b++) {
        dacc[b] = 0;
#pragma unroll
        for (int c = 0; c < 4; c++) iacc[b][c] = 0;
    }
    const u32 bones = (lane < 4) ? 0x01010101u : 0u;
    u32 bh1[2] = { bones, bones };

    for (int kt = 0; kt < NT; kt++) {
        const int cur = kt & 3, k0 = kt * BK;
        const u32 stg = tiles_u + cur * STAGE_B;
        mbar_wait(smem_u32(&X.bar[cur]), (kt >> 2) & 1);

        if (MODE) {
            // P-gen into double-buffered Phi; safe: all warps passed sync(kt-1),
            // hence finished MMA(kt-2) which last read Phi[kt&1].
            const int pb = kt & 1;
            const char* adjp = tiles_p + cur * STAGE_B;
            u32 off = (u32)pr * 128 + (u32)pc;
            uint4 av0 = *(const uint4*)(adjp + swz(off));
            uint4 av1 = *(const uint4*)(adjp + swz(off + 16));
            u8 ab[32];
            *(uint4*)ab = av0; *(uint4*)(ab + 16) = av1;
            char pq[32];
            const float2* egq = g_egq + k0 + pc;
#pragma unroll
            for (int c = 0; c < 32; c++) {
                float2 e = egq[c];
                float p = fmaxf(ai * e.x, bi * e.y);
                p = ab[c] ? p : 0.f;
                pq[c] = (char)__float2int_rn(p);
            }
            *(uint4*)&X.Phi[pb][pr][pc]      = *(uint4*)pq;
            *(uint4*)&X.Phi[pb][pr][pc + 16] = *(uint4*)(pq + 16);
        }
        __syncthreads();  // single per-chunk sync: Phi(kt) ready AND MMA(kt-1) done

        // TMA reissue for stage (kt+3)&3 == (kt-1)&3 — safe after the sync above
        if (t == 0 && kt + 3 < NT) {
            const int s = (kt + 3) & 3;
            u32 bar = smem_u32(&X.bar[s]);
            mbar_expect(bar, STAGE_B);
            u32 st = tiles_u + s * STAGE_B;
            tma2d(st,        &mAdj, (kt + 3) * 128, i0, bar);
            tma2d(st + 8192, &mH,   (kt + 3) * 128, co, bar);
        }

#pragma unroll
        for (int kk = 0; kk < 4; kk++) {
            u32 ah[4];
            {
                int rr = wm * 16 + (lane & 15);
                u32 boff = (u32)kk * 32 + ((u32)(lane >> 4)) * 16;
                u32 a = MODE ? smem_u32(&X.Phi[kt & 1][rr][0]) + boff
                             : stg + swz((u32)rr * 128 + boff);
                ldm_x4(a, ah);
            }
            u32 bh[4][2];
#pragma unroll
            for (int fp2 = 0; fp2 < 2; fp2++) {
                int nb = wn * 32 + fp2 * 16;
                u32 rowN = (u32)nb + (u32)(lane & 7) + (((u32)lane >> 4) << 3);
                u32 a = stg + 8192
                      + swz(rowN * 128 + (u32)kk * 32 + (((u32)lane >> 3) & 1) * 16);
                u32 r4[4];
                ldm_x4(a, r4);
                bh[2*fp2][0] = r4[0]; bh[2*fp2][1] = r4[1];
                bh[2*fp2+1][0] = r4[2]; bh[2*fp2+1][1] = r4[3];
            }
#pragma unroll
            for (int fn = 0; fn < 4; fn++)
                mma_s8(iacc[fn], ah, bh[fn]);
            if (MODE && (kk >> 1) == wn)
                mma_s8(dacc, ah, bh1);
        }
        // MODE 0 has no P-gen sync; protect stage reuse with end-of-chunk sync
        if (!MODE) __syncthreads();
    }

    if (MODE && (lane & 3) == 0) {
        float* Dp = wn ? X.D1 : X.D0;
        Dp[wm * 16 + (lane >> 2)]     = (float)dacc[0];
        Dp[wm * 16 + (lane >> 2) + 8] = (float)dacc[2];
    }
    __syncthreads();

#pragma unroll
    for (int h = 0; h < 2; h++) {
        int rl = wm * 16 + (lane >> 2) + h * 8;
        int row = i0 + rl;
#pragma unroll
        for (int fn = 0; fn < 4; fn++) {
            int col = co + wn * 32 + fn * 8 + (lane & 3) * 2;
            float sc0 = __uint_as_float(g_cmxu[par][col])     * (1.0f / 127.0f);
            float sc1 = __uint_as_float(g_cmxu[par][col + 1]) * (1.0f / 127.0f);
            float* op = Out + (size_t)row * ldo + col;
            if (MODE == 0) {
                float v0 = (float)iacc[fn][2 * h]     * sc0;
                float v1 = (float)iacc[fn][2 * h + 1] * sc1;
                float2 rr = *(const float2*)(resid + (size_t)row * ldo + col);
                float2 o; o.x = v0 + rr.x; o.y = v1 + rr.y;
                *(float2*)op = o;
            } else {
                float dd = X.D0[rl] + X.D1[rl];
                float v0, v1;
                if (dd > 0.f) {
                    float inv = 1.0f / dd;
                    v0 = (float)iacc[fn][2 * h]     * sc0 * inv;
                    v1 = (float)iacc[fn][2 * h + 1] * sc1 * inv;
                } else { v0 = g_cm[col]; v1 = g_cm[col + 1]; }
                v0 = (v0 > 0.f) ? v0 : fexp(v0) - 1.0f;
                v1 = (v1 > 0.f) ? v1 : fexp(v1) - 1.0f;
                if (accum) {
                    float2 zz = *(const float2*)op;
                    v0 += zz.x; v1 += zz.y;
                }
                float2 o; o.x = v0; o.y = v1;
                *(float2*)op = o;
            }
        }
    }
    __syncthreads();
    if (t == 0)
        for (int s = 0; s < TNST; s++) mbar_inval(smem_u32(&X.bar[s]));
}

// ---------------- dense GEMM + fused column abs-max (parity-buffered) ---------
__global__ void __launch_bounds__(256) k_gemm(
        const float* __restrict__ A,
        const float* __restrict__ B, int ldb,
        const float* __restrict__ bias,
        float* __restrict__ C, int ldc,
        float scale, int relu, int rst, int par)
{
    extern __shared__ float sm[];
    float (*As)[68] = (float(*)[68])sm;
    float (*Bs)[68] = (float(*)[68])(sm + 128 * 68);
    const int t = threadIdx.x;
    const int row0 = blockIdx.x * 64, co = blockIdx.y * 64;

    if (blockIdx.x == 0 && blockIdx.y == 0) {
        if (rst && t == 0) g_s2maxu = 0u;
        if (t < DIM) g_cmxu[par ^ 1][t] = 0u;   // clear buffer for pass i+1
    }

#pragma unroll
    for (int l = 0; l < 8; l++) {
        int u = t + l * 256;
        int m = u >> 5, kq = (u & 31) * 4;
        float4 v = *(const float4*)&A[(size_t)(row0 + m) * DIM + kq];
        As[kq + 0][m] = v.x; As[kq + 1][m] = v.y;
        As[kq + 2][m] = v.z; As[kq + 3][m] = v.w;
    }
#pragma unroll
    for (int l = 0; l < 8; l++) {
        int u = t + l * 256;
        int k = u >> 4, c = (u & 15) * 4;
        *(float4*)&Bs[k][c] = *(const float4*)&B[(size_t)k * ldb + co + c];
    }
    __syncthreads();

    const int tx = t & 15, ty = t >> 4;
    u64 acc[4][2];
#pragma unroll
    for (int i = 0; i < 4; i++) { acc[i][0] = 0ULL; acc[i][1] = 0ULL; }

#pragma unroll 4
    for (int k = 0; k < 128; k++) {
        float4 a4 = *(const float4*)&As[k][ty * 4];
        u64 b0 = *(const u64*)&Bs[k][tx * 4];
        u64 b1 = *(const u64*)&Bs[k][tx * 4 + 2];
        fma2(acc[0][0], pk2(a4.x, a4.x), b0); fma2(acc[0][1], pk2(a4.x, a4.x), b1);
        fma2(acc[1][0], pk2(a4.y, a4.y), b0); fma2(acc[1][1], pk2(a4.y, a4.y), b1);
        fma2(acc[2][0], pk2(a4.z, a4.z), b0); fma2(acc[2][1], pk2(a4.z, a4.z), b1);
        fma2(acc[3][0], pk2(a4.w, a4.w), b0); fma2(acc[3][1], pk2(a4.w, a4.w), b1);
    }
    float tmax[4] = {0.f, 0.f, 0.f, 0.f};
#pragma unroll
    for (int i = 0; i < 4; i++) {
        int m = row0 + ty * 4 + i;
#pragma unroll
        for (int j = 0; j < 2; j++) {
            int c = co + tx * 4 + 2 * j;
            float lo, hi; upk2(acc[i][j], lo, hi);
            float v0 = scale * lo, v1 = scale * hi;
            if (bias)  { v0 += bias[c]; v1 += bias[c + 1]; }
            if (relu)  { v0 = fmaxf(v0, 0.f); v1 = fmaxf(v1, 0.f); }
            tmax[2 * j]     = fmaxf(tmax[2 * j],     fabsf(v0));
            tmax[2 * j + 1] = fmaxf(tmax[2 * j + 1], fabsf(v1));
            float2 o; o.x = v0; o.y = v1;
            *(float2*)&C[(size_t)m * ldc + c] = o;
        }
    }
    __syncthreads();
    float* red = sm;
#pragma unroll
    for (int q = 0; q < 4; q++) red[ty * 64 + tx * 4 + q] = tmax[q];
    __syncthreads();
    if (t < 64) {
        float m = 0.f;
#pragma unroll
        for (int k = 0; k < 16; k++) m = fmaxf(m, red[k * 64 + t]);
        atomicMax(&g_cmxu[par][co + t], __float_as_uint(m));
    }
}

// ---------------- row softmax over first 56 of 64 cols ------------------------
__global__ void k_smax56(float* __restrict__ X) {
    int w = threadIdx.x >> 5, lane = threadIdx.x & 31;
    int row = blockIdx.x * 8 + w;
    float* r = X + (size_t)row * ODP;
    float v0 = (lane < OD)      ? r[lane]      : -3e38f;
    float v1 = (lane + 32 < OD) ? r[lane + 32] : -3e38f;
    float m = fmaxf(v0, v1);
#pragma unroll
    for (int o = 16; o > 0; o >>= 1) m = fmaxf(m, __shfl_xor_sync(0xffffffffu, m, o));
    float e0 = (lane < OD)      ? fexp(v0 - m) : 0.f;
    float e1 = (lane + 32 < OD) ? fexp(v1 - m) : 0.f;
    float s = e0 + e1;
#pragma unroll
    for (int o = 16; o > 0; o >>= 1) s += __shfl_xor_sync(0xffffffffu, s, o);
    float inv = 1.0f / s;
    if (lane < OD)      r[lane]      = e0 * inv;
    if (lane + 32 < OD) r[lane + 32] = e1 * inv;
}

// ---------------- segment-sum readout + MLP head ------------------------------
__global__ void k_head(const int* __restrict__ seg,
                       const float* __restrict__ Wout, const float* __restrict__ bout,
                       const float* __restrict__ Wprop, const float* __restrict__ bprop,
                       float* __restrict__ out)
{
    __shared__ float v[OD];
    __shared__ float o[OD];
    __shared__ int bnd[2];
    const int m = blockIdx.x, t = threadIdx.x;
    if (t < 2) {
        int target = m + t;
        int lo = 0, hi = NN;
        while (lo < hi) { int mid = (lo + hi) >> 1; if (seg[mid] < target) lo = mid + 1; else hi = mid; }
        bnd[t] = lo;
    }
    __syncthreads();
    int lo = bnd[0], hi = bnd[1];
    if (t < OD) {
        float s = 0.f;
        for (int i = lo; i < hi; i++) s += g_a56[(size_t)i * ODP + t];
        v[t] = s;
    }
    __syncthreads();
    for (int l = 0; l < 2; l++) {
        if (t < OD) {
            float s = bout[l * OD + t];
            const float* W = Wout + l * OD * OD;
            for (int k = 0; k < OD; k++) s = fmaf(v[k], W[k * OD + t], s);
            o[t] = fmaxf(s, 0.f);
        }
        __syncthreads();
        if (t < OD) v[t] = o[t];
        __syncthreads();
    }
    if (t < 2) {
        float s = bprop[t];
        for (int k = 0; k < OD; k++) s = fmaf(v[k], Wprop[k * 2 + t], s);
        float r;
        if (s >= 0.f) r = 1.0f / (1.0f + fexp(-s));
        else { float e = fexp(s); r = e / (1.0f + e); }
        out[m * 2 + t] = r;
    }
}

// ---------------- orchestration ----------------------------------------------
typedef CUresult (*tmap_fn_t)(CUtensorMap*, CUtensorMapDataType, cuuint32_t, void*,
                              const cuuint64_t*, const cuuint64_t*, const cuuint32_t*,
                              const cuuint32_t*, CUtensorMapInterleave, CUtensorMapSwizzle,
                              CUtensorMapL2promotion, CUtensorMapFloatOOBfill);

static void make_tmap8(tmap_fn_t fn, CUtensorMap* m, void* base,
                       unsigned long long d0, unsigned long long d1) {
    cuuint64_t dims[2] = { d0, d1 };
    cuuint64_t strides[1] = { d0 };
    cuuint32_t box[2] = { 128, 64 };
    cuuint32_t es[2] = { 1, 1 };
    fn(m, CU_TENSOR_MAP_DATA_TYPE_UINT8, 2, base, dims, strides, box, es,
       CU_TENSOR_MAP_INTERLEAVE_NONE, CU_TENSOR_MAP_SWIZZLE_128B,
       CU_TENSOR_MAP_L2_PROMOTION_L2_128B, CU_TENSOR_MAP_FLOAT_OOB_FILL_NONE);
}

extern "C" void kernel_launch(void* const* d_in, const int* in_sizes, int n_in,
                              void* d_out, int out_size) {
    const int*   fp   = (const int*)  d_in[0];
    const float* adj  = (const float*)d_in[1];
    const int*   seg  = (const int*)  d_in[2];
    const float* emb  = (const float*)d_in[3];
    const float* Wfp  = (const float*)d_in[4];
    const float* bfp  = (const float*)d_in[5];
    const float* Wh   = (const float*)d_in[6];
    const float* ah   = (const float*)d_in[7];
    const float* Woa  = (const float*)d_in[8];
    const float* aoa  = (const float*)d_in[9];
    const float* Wout = (const float*)d_in[10];
    const float* bout = (const float*)d_in[11];
    const float* Wpr  = (const float*)d_in[12];
    const float* bpr  = (const float*)d_in[13];
    float* out = (float*)d_out;

    float *x, *h, *tb, *z, *ho, *a56, *wpad;
    void *adj8_p, *h8T_p;
    cudaGetSymbolAddress((void**)&x,    g_x);
    cudaGetSymbolAddress((void**)&h,    g_h);
    cudaGetSymbolAddress((void**)&tb,   g_t);
    cudaGetSymbolAddress((void**)&z,    g_z);
    cudaGetSymbolAddress((void**)&ho,   g_ho);
    cudaGetSymbolAddress((void**)&a56,  g_a56);
    cudaGetSymbolAddress((void**)&wpad, g_wpad);
    cudaGetSymbolAddress(&adj8_p, g_adj8);
    cudaGetSymbolAddress(&h8T_p,  g_h8T);

    tmap_fn_t tmap_fn = nullptr;
    cudaDriverEntryPointQueryResult qr;
    cudaGetDriverEntryPointByVersion("cuTensorMapEncodeTiled", (void**)&tmap_fn,
                                     12000, cudaEnableDefault, &qr);
    static CUtensorMap mapAdj, mapHT, mapHT64;
    make_tmap8(tmap_fn, &mapAdj,  adj8_p, NN, NN);
    make_tmap8(tmap_fn, &mapHT,   h8T_p,  NN, DIM);
    make_tmap8(tmap_fn, &mapHT64, h8T_p,  NN, 64);

    const int SZT = (int)sizeof(TAux) + 1024 + TNST * 2 * 8192;
    const int SZG = 128 * 68 * 2 * 4;
    cudaFuncSetAttribute(k_tmma<0>, cudaFuncAttributeMaxDynamicSharedMemorySize, SZT);
    cudaFuncSetAttribute(k_tmma<1>, cudaFuncAttributeMaxDynamicSharedMemorySize, SZT);
    cudaFuncSetAttribute(k_gemm,    cudaFuncAttributeMaxDynamicSharedMemorySize, SZG);

    k_gather<<<NN * DIM / 256, 256>>>(fp, emb);
    k_adjconv<<<(size_t)NN * NN / 2048, 256>>>(adj);
    k_padw<<<DIM * ODP / 256, 256>>>(Woa);

    int par = 0;
    // 3 message-passing layers
    for (int l = 0; l < 3; l++) {
        k_gemm<<<dim3(NN / 64, 2), 256, SZG>>>(x, Wfp + l * DIM * DIM, DIM,
                                               bfp + l * DIM, h, DIM, 1.f, 1, 0, par);
        k_transp8i<<<dim3(NN / 64, DIM / 64), 256>>>(h, DIM, par);
        k_tmma<0><<<dim3(NN / 64, 2), 256, SZT>>>(mapAdj, mapHT, h, tb, DIM, 0, par);
        k_l2norm<<<NN / 8, 256>>>(tb, x);
        par ^= 1;
    }

    // 2 GAT heads
    for (int hd = 0; hd < 2; hd++) {
        k_gemm<<<dim3(NN / 64, 2), 256, SZG>>>(x, Wh + hd * DIM * DIM, DIM,
                                               nullptr, h, DIM, 1.f, 0, 1, par);
        k_s12<<<NN / 8, 256>>>(h, DIM, DIM, ah + hd * 2 * DIM);
        k_prep<<<NN / 256, 256>>>();
        k_transp8i<<<dim3(NN / 64, DIM / 64), 256>>>(h, DIM, par);
        k_tmma<1><<<dim3(NN / 64, 2), 256, SZT>>>(mapAdj, mapHT, nullptr, z, DIM, hd, par);
        par ^= 1;
    }

    // out-attention at D=56 (padded to 64); x = z/2 folded into scale
    k_gemm<<<dim3(NN / 64, 1), 256, SZG>>>(z, wpad, ODP, nullptr, ho, ODP, 0.5f, 0, 1, par);
    k_s12<<<NN / 8, 256>>>(ho, ODP, OD, aoa);
    k_prep<<<NN / 256, 256>>>();
    k_transp8i<<<dim3(NN / 64, 1), 256>>>(ho, ODP, par);
    k_tmma<1><<<dim3(NN / 64, 1), 256, SZT>>>(mapAdj, mapHT64, nullptr, a56, ODP, 0, par);

    k_smax56<<<NN / 8, 256>>>(a56);
    k_head<<<NMOL, 64>>>(seg, Wout, bout, Wpr, bpr, out);
}